// round 7
// baseline (speedup 1.0000x reference)
#include <cuda_runtime.h>
#include <cuda_bf16.h>
#include <cstdint>

#define N_NODES 50000
#define N_EDGES 400000
#define F_IN    256
#define HID     1024
#define F_MID   512
#define N_OUT   10
#define EPS_BN  1e-5f

// ---------------- scratch (device globals) ----------------
__device__ float g_tmp[(size_t)N_NODES * HID];
__device__ float g_h  [(size_t)N_NODES * HID];
__device__ __nv_bfloat16 g_Ah[(size_t)N_NODES * HID];
__device__ __nv_bfloat16 g_Al[(size_t)N_NODES * HID];
__device__ __nv_bfloat16 g_Bh[(size_t)N_NODES * HID];
__device__ __nv_bfloat16 g_Bl[(size_t)N_NODES * HID];
#define OFF_W1L 0
#define OFF_W1R 262144
#define OFF_W2L 524288
#define OFF_W2R 1572864
#define OFF_WF  2621440
__device__ __nv_bfloat16 g_Wh[3145728];
__device__ __nv_bfloat16 g_Wl[3145728];

__device__ int   g_deg[N_NODES];
__device__ int   g_off[N_NODES];
__device__ int   g_cur[N_NODES];
__device__ int   g_csr[N_EDGES];
__device__ float g_sum[HID];
__device__ float g_sumsq[HID];
__device__ float g_a[HID];
__device__ float g_c[HID];
__device__ int   g_is64;

// ---------------- dtype detection ----------------
__global__ void k_detect(const unsigned int* e) {
    if (threadIdx.x == 0) {
        int is64 = 1;
        for (int i = 0; i < 64; i++)
            if (e[2 * i + 1] != 0u) { is64 = 0; break; }
        g_is64 = is64;
    }
}
__device__ __forceinline__ int load_edge(const void* edges, int idx) {
    if (g_is64) return (int)((const long long*)edges)[idx];
    return ((const int*)edges)[idx];
}

// ---------------- CSR build ----------------
__global__ void k_hist(const void* edges) {
    int i = blockIdx.x * blockDim.x + threadIdx.x;
    if (i < N_EDGES) atomicAdd(&g_deg[load_edge(edges, N_EDGES + i)], 1);
}
__global__ void k_scan() {
    __shared__ int sh[1024];
    __shared__ int carry;
    int t = threadIdx.x;
    if (t == 0) carry = 0;
    __syncthreads();
    for (int base = 0; base < N_NODES; base += 1024) {
        int v = (base + t < N_NODES) ? g_deg[base + t] : 0;
        sh[t] = v;
        __syncthreads();
        #pragma unroll
        for (int off = 1; off < 1024; off <<= 1) {
            int add = (t >= off) ? sh[t - off] : 0;
            __syncthreads();
            sh[t] += add;
            __syncthreads();
        }
        int excl = sh[t] - v;
        int c0 = carry;
        if (base + t < N_NODES) { g_off[base + t] = c0 + excl; g_cur[base + t] = c0 + excl; }
        __syncthreads();
        if (t == 0) carry = c0 + sh[1023];
        __syncthreads();
    }
}
__global__ void k_scatter(const void* edges) {
    int i = blockIdx.x * blockDim.x + threadIdx.x;
    if (i < N_EDGES) {
        int src = load_edge(edges, i);
        int dst = load_edge(edges, N_EDGES + i);
        g_csr[atomicAdd(&g_cur[dst], 1)] = src;
    }
}

// ---------------- mean aggregation (atomic-free gather) -> bf16 hi/lo ------
template <int F>
__global__ void k_aggregate(const float* __restrict__ X,
                            __nv_bfloat16* __restrict__ OH, __nv_bfloat16* __restrict__ OL) {
    int node = blockIdx.x;
    int t = threadIdx.x;                 // 128
    constexpr int J = F / 128;
    float acc[J];
    #pragma unroll
    for (int j = 0; j < J; j++) acc[j] = 0.0f;
    int start = g_off[node];
    int deg = g_deg[node];
    for (int i = 0; i < deg; i++) {
        const float* row = X + (size_t)g_csr[start + i] * F;
        #pragma unroll
        for (int j = 0; j < J; j++) acc[j] += row[t + j * 128];
    }
    float inv = (deg > 0) ? (1.0f / (float)deg) : 0.0f;
    size_t o = (size_t)node * F + t;
    #pragma unroll
    for (int j = 0; j < J; j++) {
        float v = acc[j] * inv;
        __nv_bfloat16 h = __float2bfloat16(v);
        OH[o + j * 128] = h;
        OL[o + j * 128] = __float2bfloat16(v - __bfloat162float(h));
    }
}

// ---------------- fp32 -> bf16 hi/lo split ----------------
__global__ void k_split(const float* __restrict__ X, __nv_bfloat16* __restrict__ H,
                        __nv_bfloat16* __restrict__ L, size_t n) {
    size_t i = (size_t)blockIdx.x * blockDim.x + threadIdx.x;
    if (i < n) {
        float v = X[i];
        __nv_bfloat16 h = __float2bfloat16(v);
        H[i] = h;
        L[i] = __float2bfloat16(v - __bfloat162float(h));
    }
}

// ---------------- weight transpose + split ----------------
__global__ void k_wt(const float* __restrict__ W, __nv_bfloat16* __restrict__ Th,
                     __nv_bfloat16* __restrict__ Tl, int K, int N) {
    __shared__ float t[32][33];
    int kb = blockIdx.x * 32, nb = blockIdx.y * 32;
    int tx = threadIdx.x, ty = threadIdx.y;  // 32 x 8
    #pragma unroll
    for (int i = 0; i < 32; i += 8)
        t[ty + i][tx] = W[(size_t)(kb + ty + i) * N + nb + tx];
    __syncthreads();
    #pragma unroll
    for (int i = 0; i < 32; i += 8) {
        float v = t[tx][ty + i];
        size_t o = (size_t)(nb + ty + i) * K + kb + tx;
        __nv_bfloat16 h = __float2bfloat16(v);
        Th[o] = h;
        Tl[o] = __float2bfloat16(v - __bfloat162float(h));
    }
}

// ---------------- bf16 mma.sync GEMM ----------------
// C[M,N] = sum_p A_p[M,Kp] @ B_p[N,Kp]^T + bias (+ReLU)
// CTA tile 128x128, warp tile 32x64 (4x2 warps), BK=64, 4-stage cp.async.
// Grid: x = N-tiles (fast-varying) so a wave shares A row-blocks via L2.
struct GemmParams {
    const __nv_bfloat16* A[6];
    const __nv_bfloat16* B[6];
    int Kw[6];
    int chEnd[6];
    int totalChunks;
    const float* bias;
    float* C;
    int M;
    int Ncols;
    int relu;
};

#define STAGES 4
#define STAGE_BYTES 32768              // 16KB A + 16KB B
#define SMEM_REQ (1024 + STAGES * STAGE_BYTES)

__device__ __forceinline__ uint32_t swz(uint32_t o) { return o ^ ((o >> 3) & 0x70); }

__device__ __forceinline__ void cp16(uint32_t dst, const void* src, bool p) {
    int sz = p ? 16 : 0;
    asm volatile("cp.async.cg.shared.global [%0], [%1], 16, %2;\n"
                 :: "r"(dst), "l"(src), "r"(sz));
}

__global__ __launch_bounds__(256, 1) void k_gemm(const __grid_constant__ GemmParams P) {
    extern __shared__ char dsm[];
    uint32_t raw;
    asm("{ .reg .u64 t; cvta.to.shared.u64 t, %1; cvt.u32.u64 %0, t; }" : "=r"(raw) : "l"(dsm));
    uint32_t tiles = (raw + 1023) & ~1023u;
    int tid = threadIdx.x;
    int wid = tid >> 5;
    int lane = tid & 31;
    int mBase = blockIdx.y * 128;      // M-tile on y (slow)
    int nBase = blockIdx.x * 128;      // N-tile on x (fast) -> wave shares A via L2
    int mw = wid >> 1;     // 0..3
    int nw = wid & 1;      // 0..1

    auto load_chunk = [&](int c, int s) {
        int p = 0;
        while (c >= P.chEnd[p]) p++;
        int c0 = (p ? c - P.chEnd[p - 1] : c) * 64;
        const char* Ab = (const char*)P.A[p] + (size_t)c0 * 2;
        const char* Bb = (const char*)P.B[p] + (size_t)c0 * 2;
        size_t rowB = (size_t)P.Kw[p] * 2;
        uint32_t stA = tiles + s * STAGE_BYTES;
        uint32_t stB = stA + 16384;
        #pragma unroll
        for (int i = 0; i < 4; i++) {
            int o = tid + i * 256;
            int row = o >> 3, kb = (o & 7) * 16;
            bool ok = (mBase + row) < P.M;
            cp16(stA + swz(row * 128 + kb), Ab + (size_t)(mBase + row) * rowB + kb, ok);
        }
        #pragma unroll
        for (int i = 0; i < 4; i++) {
            int o = tid + i * 256;
            int row = o >> 3, kb = (o & 7) * 16;
            cp16(stB + swz(row * 128 + kb), Bb + (size_t)(nBase + row) * rowB + kb, true);
        }
        asm volatile("cp.async.commit_group;" ::: "memory");
    };

    const int T = P.totalChunks;

    float acc[2][8][4];
    #pragma unroll
    for (int mi = 0; mi < 2; mi++)
        #pragma unroll
        for (int n8 = 0; n8 < 8; n8++)
            #pragma unroll
            for (int q = 0; q < 4; q++) acc[mi][n8][q] = 0.0f;

    int npre = (T < 3) ? T : 3;
    for (int c = 0; c < npre; c++) load_chunk(c, c);

    for (int c = 0; c < T; c++) {
        int s = c & 3;
        int rem = (T - 1) - c;
        if (rem >= 2)      asm volatile("cp.async.wait_group 2;" ::: "memory");
        else if (rem == 1) asm volatile("cp.async.wait_group 1;" ::: "memory");
        else               asm volatile("cp.async.wait_group 0;" ::: "memory");
        __syncthreads();

        uint32_t stA = tiles + s * STAGE_BYTES;
        uint32_t stB = stA + 16384;
        #pragma unroll
        for (int ks = 0; ks < 4; ks++) {
            uint32_t a[2][4];
            uint32_t arow = mw * 32 + ((lane >> 3) & 1) * 8 + (lane & 7);
            uint32_t akb  = ks * 32 + (lane >> 4) * 16;
            #pragma unroll
            for (int mi = 0; mi < 2; mi++) {
                uint32_t ad = stA + swz((arow + mi * 16) * 128 + akb);
                asm volatile("ldmatrix.sync.aligned.m8n8.x4.shared.b16 {%0,%1,%2,%3}, [%4];"
                             : "=r"(a[mi][0]), "=r"(a[mi][1]), "=r"(a[mi][2]), "=r"(a[mi][3])
                             : "r"(ad));
            }
            uint32_t b[4][4];
            uint32_t brow = nw * 64 + ((lane >> 4) & 1) * 8 + (lane & 7);
            uint32_t bkb  = ks * 32 + ((lane >> 3) & 1) * 16;
            #pragma unroll
            for (int ni = 0; ni < 4; ni++) {
                uint32_t bd = stB + swz((brow + ni * 16) * 128 + bkb);
                asm volatile("ldmatrix.sync.aligned.m8n8.x4.shared.b16 {%0,%1,%2,%3}, [%4];"
                             : "=r"(b[ni][0]), "=r"(b[ni][1]), "=r"(b[ni][2]), "=r"(b[ni][3])
                             : "r"(bd));
            }
            #pragma unroll
            for (int mi = 0; mi < 2; mi++)
                #pragma unroll
                for (int n8 = 0; n8 < 8; n8++) {
                    uint32_t b0 = b[n8 >> 1][(n8 & 1) * 2 + 0];
                    uint32_t b1 = b[n8 >> 1][(n8 & 1) * 2 + 1];
                    asm volatile(
                        "mma.sync.aligned.m16n8k16.row.col.f32.bf16.bf16.f32 "
                        "{%0,%1,%2,%3}, {%4,%5,%6,%7}, {%8,%9}, {%0,%1,%2,%3};"
                        : "+f"(acc[mi][n8][0]), "+f"(acc[mi][n8][1]),
                          "+f"(acc[mi][n8][2]), "+f"(acc[mi][n8][3])
                        : "r"(a[mi][0]), "r"(a[mi][1]), "r"(a[mi][2]), "r"(a[mi][3]),
                          "r"(b0), "r"(b1));
                }
        }
        if (c + 3 < T) load_chunk(c + 3, (c + 3) & 3);
    }

    // epilogue: bias (+ReLU) store
    {
        int g = lane >> 2, t4 = lane & 3;
        #pragma unroll
        for (int mi = 0; mi < 2; mi++) {
            #pragma unroll
            for (int n8 = 0; n8 < 8; n8++) {
                int col = nBase + nw * 64 + n8 * 8 + t4 * 2;
                float bx = P.bias[col], by = P.bias[col + 1];
                int r0 = mBase + mw * 32 + mi * 16 + g;
                if (r0 < P.M) {
                    float2 v;
                    v.x = acc[mi][n8][0] + bx;
                    v.y = acc[mi][n8][1] + by;
                    if (P.relu) { v.x = fmaxf(v.x, 0.f); v.y = fmaxf(v.y, 0.f); }
                    *(float2*)(P.C + (size_t)r0 * P.Ncols + col) = v;
                }
                int r1 = r0 + 8;
                if (r1 < P.M) {
                    float2 v;
                    v.x = acc[mi][n8][2] + bx;
                    v.y = acc[mi][n8][3] + by;
                    if (P.relu) { v.x = fmaxf(v.x, 0.f); v.y = fmaxf(v.y, 0.f); }
                    *(float2*)(P.C + (size_t)r1 * P.Ncols + col) = v;
                }
            }
        }
    }
}

// ---------------- BN column stats ----------------
__global__ void k_colstats(const float* __restrict__ X) {
    int t = threadIdx.x;  // 256
    int rows_per = (N_NODES + gridDim.x - 1) / gridDim.x;
    int r0 = blockIdx.x * rows_per;
    int r1 = min(N_NODES, r0 + rows_per);
    float s[4] = {0, 0, 0, 0}, q[4] = {0, 0, 0, 0};
    for (int r = r0; r < r1; r++) {
        const float* row = X + (size_t)r * HID;
        #pragma unroll
        for (int j = 0; j < 4; j++) {
            float v = row[t + j * 256];
            s[j] += v; q[j] += v * v;
        }
    }
    #pragma unroll
    for (int j = 0; j < 4; j++) {
        atomicAdd(&g_sum[t + j * 256], s[j]);
        atomicAdd(&g_sumsq[t + j * 256], q[j]);
    }
}
__global__ void k_bnparams(const float* __restrict__ g, const float* __restrict__ be) {
    int c = blockIdx.x * blockDim.x + threadIdx.x;
    if (c < HID) {
        float m = g_sum[c] * (1.0f / N_NODES);
        float var = g_sumsq[c] * (1.0f / N_NODES) - m * m;
        float a = g[c] * rsqrtf(var + EPS_BN);
        g_a[c] = a;
        g_c[c] = be[c] - m * a;
    }
}
__global__ void k_bnrelu(const float* __restrict__ X, float* __restrict__ Y,
                         __nv_bfloat16* __restrict__ YH, __nv_bfloat16* __restrict__ YL) {
    size_t i = (size_t)blockIdx.x * blockDim.x + threadIdx.x;
    const size_t total = (size_t)N_NODES * HID / 4;
    if (i < total) {
        int c = (int)((i * 4) % HID);
        float4 v = ((const float4*)X)[i];
        v.x = fmaxf(0.f, v.x * g_a[c + 0] + g_c[c + 0]);
        v.y = fmaxf(0.f, v.y * g_a[c + 1] + g_c[c + 1]);
        v.z = fmaxf(0.f, v.z * g_a[c + 2] + g_c[c + 2]);
        v.w = fmaxf(0.f, v.w * g_a[c + 3] + g_c[c + 3]);
        ((float4*)Y)[i] = v;
        __nv_bfloat16 hx = __float2bfloat16(v.x), hy = __float2bfloat16(v.y);
        __nv_bfloat16 hz = __float2bfloat16(v.z), hw = __float2bfloat16(v.w);
        __nv_bfloat162* H2 = (__nv_bfloat162*)YH;
        __nv_bfloat162* L2 = (__nv_bfloat162*)YL;
        H2[i * 2 + 0] = __nv_bfloat162(hx, hy);
        H2[i * 2 + 1] = __nv_bfloat162(hz, hw);
        L2[i * 2 + 0] = __nv_bfloat162(__float2bfloat16(v.x - __bfloat162float(hx)),
                                       __float2bfloat16(v.y - __bfloat162float(hy)));
        L2[i * 2 + 1] = __nv_bfloat162(__float2bfloat16(v.z - __bfloat162float(hz)),
                                       __float2bfloat16(v.w - __bfloat162float(hw)));
    }
}

// ---------------- final head ----------------
__global__ void k_out(const float* __restrict__ H, const float* __restrict__ Wo,
                      const float* __restrict__ bo, float* __restrict__ Out) {
    __shared__ float sw[F_MID * N_OUT];
    for (int i = threadIdx.x; i < F_MID * N_OUT; i += blockDim.x) sw[i] = Wo[i];
    __syncthreads();
    int warp = threadIdx.x / 32, lane = threadIdx.x % 32;
    int row = blockIdx.x * (blockDim.x / 32) + warp;
    if (row >= N_NODES) return;
    float acc[N_OUT];
    #pragma unroll
    for (int o = 0; o < N_OUT; o++) acc[o] = 0.0f;
    const float* h = H + (size_t)row * F_MID;
    for (int k = lane; k < F_MID; k += 32) {
        float hv = h[k];
        #pragma unroll
        for (int o = 0; o < N_OUT; o++) acc[o] += hv * sw[k * N_OUT + o];
    }
    #pragma unroll
    for (int o = 0; o < N_OUT; o++)
        #pragma unroll
        for (int off = 16; off; off >>= 1)
            acc[o] += __shfl_down_sync(0xffffffffu, acc[o], off);
    if (lane == 0)
        #pragma unroll
        for (int o = 0; o < N_OUT; o++)
            Out[(size_t)row * N_OUT + o] = acc[o] + bo[o];
}

// ---------------- host-side GEMM launcher ----------------
struct PassDef { const __nv_bfloat16* A; const __nv_bfloat16* B; int Kw; };
static void run_gemm(const PassDef* passes, int np, const float* bias, float* C,
                     int M, int N, int relu) {
    GemmParams P = {};
    int cum = 0;
    for (int i = 0; i < np; i++) {
        P.A[i] = passes[i].A;
        P.B[i] = passes[i].B;
        P.Kw[i] = passes[i].Kw;
        cum += passes[i].Kw / 64;
        P.chEnd[i] = cum;
    }
    P.totalChunks = cum;
    P.bias = bias; P.C = C; P.M = M; P.Ncols = N; P.relu = relu;
    dim3 g(N / 128, (M + 127) / 128);     // x = N-tile (fast) for L2 A-reuse
    k_gemm<<<g, 256, SMEM_REQ>>>(P);
}

// ---------------- launch ----------------
extern "C" void kernel_launch(void* const* d_in, const int* in_sizes, int n_in,
                              void* d_out, int out_size) {
    const float* x   = (const float*)d_in[0];
    const void*  edges = d_in[1];
    const float* W1l = (const float*)d_in[2];
    const float* b1  = (const float*)d_in[3];
    const float* W1r = (const float*)d_in[4];
    const float* g1  = (const float*)d_in[5];
    const float* be1 = (const float*)d_in[6];
    const float* W2l = (const float*)d_in[7];
    const float* b2  = (const float*)d_in[8];
    const float* W2r = (const float*)d_in[9];
    const float* g2  = (const float*)d_in[10];
    const float* be2 = (const float*)d_in[11];
    const float* Wf  = (const float*)d_in[12];
    const float* bf  = (const float*)d_in[13];
    const float* Wo  = (const float*)d_in[14];
    const float* bo  = (const float*)d_in[15];
    float* out = (float*)d_out;

    cudaFuncSetAttribute(k_gemm, cudaFuncAttributeMaxDynamicSharedMemorySize, SMEM_REQ);

    void *p_deg, *p_sum, *p_sumsq, *p_tmp, *p_h, *p_Ah, *p_Al, *p_Bh, *p_Bl, *p_Wh, *p_Wl;
    cudaGetSymbolAddress(&p_deg, g_deg);
    cudaGetSymbolAddress(&p_sum, g_sum);
    cudaGetSymbolAddress(&p_sumsq, g_sumsq);
    cudaGetSymbolAddress(&p_tmp, g_tmp);
    cudaGetSymbolAddress(&p_h, g_h);
    cudaGetSymbolAddress(&p_Ah, g_Ah);
    cudaGetSymbolAddress(&p_Al, g_Al);
    cudaGetSymbolAddress(&p_Bh, g_Bh);
    cudaGetSymbolAddress(&p_Bl, g_Bl);
    cudaGetSymbolAddress(&p_Wh, g_Wh);
    cudaGetSymbolAddress(&p_Wl, g_Wl);
    float* tmp = (float*)p_tmp;
    float* h   = (float*)p_h;
    __nv_bfloat16* Ah = (__nv_bfloat16*)p_Ah;
    __nv_bfloat16* Al = (__nv_bfloat16*)p_Al;
    __nv_bfloat16* Bh = (__nv_bfloat16*)p_Bh;
    __nv_bfloat16* Bl = (__nv_bfloat16*)p_Bl;
    __nv_bfloat16* Wh = (__nv_bfloat16*)p_Wh;
    __nv_bfloat16* Wl = (__nv_bfloat16*)p_Wl;

    // CSR build
    cudaMemsetAsync(p_deg, 0, N_NODES * sizeof(int));
    k_detect<<<1, 32>>>((const unsigned int*)edges);
    k_hist<<<(N_EDGES + 255) / 256, 256>>>(edges);
    k_scan<<<1, 1024>>>();
    k_scatter<<<(N_EDGES + 255) / 256, 256>>>(edges);

    // weight transpose + split
    dim3 wb(32, 8);
    k_wt<<<dim3(F_IN / 32, HID / 32), wb>>>(W1l, Wh + OFF_W1L, Wl + OFF_W1L, F_IN, HID);
    k_wt<<<dim3(F_IN / 32, HID / 32), wb>>>(W1r, Wh + OFF_W1R, Wl + OFF_W1R, F_IN, HID);
    k_wt<<<dim3(HID / 32, HID / 32), wb>>>(W2l, Wh + OFF_W2L, Wl + OFF_W2L, HID, HID);
    k_wt<<<dim3(HID / 32, HID / 32), wb>>>(W2r, Wh + OFF_W2R, Wl + OFF_W2R, HID, HID);
    k_wt<<<dim3(HID / 32, F_MID / 32), wb>>>(Wf, Wh + OFF_WF, Wl + OFF_WF, HID, F_MID);

    // x split
    {
        size_t n = (size_t)N_NODES * F_IN;
        k_split<<<(unsigned)((n + 255) / 256), 256>>>(x, Bh, Bl, n);
    }

    // ---- layer 1 ----
    k_aggregate<F_IN><<<N_NODES, 128>>>(x, Ah, Al);
    {
        PassDef pl[6] = {
            {Ah, Wh + OFF_W1L, F_IN}, {Ah, Wl + OFF_W1L, F_IN}, {Al, Wh + OFF_W1L, F_IN},
            {Bh, Wh + OFF_W1R, F_IN}, {Bh, Wl + OFF_W1R, F_IN}, {Bl, Wh + OFF_W1R, F_IN},
        };
        run_gemm(pl, 6, b1, tmp, N_NODES, HID, 0);
    }
    cudaMemsetAsync(p_sum, 0, HID * sizeof(float));
    cudaMemsetAsync(p_sumsq, 0, HID * sizeof(float));
    k_colstats<<<128, 256>>>(tmp);
    k_bnparams<<<HID / 256, 256>>>(g1, be1);
    {
        size_t n4 = (size_t)N_NODES * HID / 4;
        k_bnrelu<<<(unsigned)((n4 + 255) / 256), 256>>>(tmp, h, Bh, Bl);
    }

    // ---- layer 2 ----
    k_aggregate<HID><<<N_NODES, 128>>>(h, Ah, Al);
    {
        PassDef pl[6] = {
            {Ah, Wh + OFF_W2L, HID}, {Ah, Wl + OFF_W2L, HID}, {Al, Wh + OFF_W2L, HID},
            {Bh, Wh + OFF_W2R, HID}, {Bh, Wl + OFF_W2R, HID}, {Bl, Wh + OFF_W2R, HID},
        };
        run_gemm(pl, 6, b2, tmp, N_NODES, HID, 0);
    }
    cudaMemsetAsync(p_sum, 0, HID * sizeof(float));
    cudaMemsetAsync(p_sumsq, 0, HID * sizeof(float));
    k_colstats<<<128, 256>>>(tmp);
    k_bnparams<<<HID / 256, 256>>>(g2, be2);
    {
        size_t n4 = (size_t)N_NODES * HID / 4;
        k_bnrelu<<<(unsigned)((n4 + 255) / 256), 256>>>(tmp, h, Bh, Bl);
    }

    // ---- fc + ReLU ----
    {
        PassDef pl[3] = {
            {Bh, Wh + OFF_WF, HID}, {Bh, Wl + OFF_WF, HID}, {Bl, Wh + OFF_WF, HID},
        };
        run_gemm(pl, 3, bf, tmp, N_NODES, F_MID, 1);
    }

    // ---- head ----
    k_out<<<(N_NODES + 7) / 8, 256>>>(tmp, Wo, bo, out);
}

// round 8
// speedup vs baseline: 1.0022x; 1.0022x over previous
#include <cuda_runtime.h>
#include <cuda_bf16.h>
#include <cstdint>

#define N_NODES 50000
#define N_EDGES 400000
#define F_IN    256
#define HID     1024
#define F_MID   512
#define N_OUT   10
#define EPS_BN  1e-5f

// ---------------- scratch (device globals) ----------------
__device__ float g_tmp[(size_t)N_NODES * HID];
__device__ float g_h  [(size_t)N_NODES * HID];
__device__ __nv_bfloat16 g_Ah[(size_t)N_NODES * HID];
__device__ __nv_bfloat16 g_Al[(size_t)N_NODES * HID];
__device__ __nv_bfloat16 g_Bh[(size_t)N_NODES * HID];
__device__ __nv_bfloat16 g_Bl[(size_t)N_NODES * HID];
#define OFF_W1L 0
#define OFF_W1R 262144
#define OFF_W2L 524288
#define OFF_W2R 1572864
#define OFF_WF  2621440
__device__ __nv_bfloat16 g_Wh[3145728];
__device__ __nv_bfloat16 g_Wl[3145728];

__device__ int   g_deg[N_NODES];
__device__ int   g_off[N_NODES];
__device__ int   g_cur[N_NODES];
__device__ int   g_csr[N_EDGES];
__device__ float g_sum[HID];
__device__ float g_sumsq[HID];
__device__ float g_a[HID];
__device__ float g_c[HID];
__device__ int   g_is64;

// ---------------- dtype detection ----------------
__global__ void k_detect(const unsigned int* e) {
    if (threadIdx.x == 0) {
        int is64 = 1;
        for (int i = 0; i < 64; i++)
            if (e[2 * i + 1] != 0u) { is64 = 0; break; }
        g_is64 = is64;
    }
}
__device__ __forceinline__ int load_edge(const void* edges, int idx) {
    if (g_is64) return (int)((const long long*)edges)[idx];
    return ((const int*)edges)[idx];
}

// ---------------- CSR build ----------------
__global__ void k_hist(const void* edges) {
    int i = blockIdx.x * blockDim.x + threadIdx.x;
    if (i < N_EDGES) atomicAdd(&g_deg[load_edge(edges, N_EDGES + i)], 1);
}
__global__ void k_scan() {
    __shared__ int sh[1024];
    __shared__ int carry;
    int t = threadIdx.x;
    if (t == 0) carry = 0;
    __syncthreads();
    for (int base = 0; base < N_NODES; base += 1024) {
        int v = (base + t < N_NODES) ? g_deg[base + t] : 0;
        sh[t] = v;
        __syncthreads();
        #pragma unroll
        for (int off = 1; off < 1024; off <<= 1) {
            int add = (t >= off) ? sh[t - off] : 0;
            __syncthreads();
            sh[t] += add;
            __syncthreads();
        }
        int excl = sh[t] - v;
        int c0 = carry;
        if (base + t < N_NODES) { g_off[base + t] = c0 + excl; g_cur[base + t] = c0 + excl; }
        __syncthreads();
        if (t == 0) carry = c0 + sh[1023];
        __syncthreads();
    }
}
__global__ void k_scatter(const void* edges) {
    int i = blockIdx.x * blockDim.x + threadIdx.x;
    if (i < N_EDGES) {
        int src = load_edge(edges, i);
        int dst = load_edge(edges, N_EDGES + i);
        g_csr[atomicAdd(&g_cur[dst], 1)] = src;
    }
}

// ---------------- mean aggregation (atomic-free gather) -> bf16 hi/lo ------
template <int F>
__global__ void k_aggregate(const float* __restrict__ X,
                            __nv_bfloat16* __restrict__ OH, __nv_bfloat16* __restrict__ OL) {
    int node = blockIdx.x;
    int t = threadIdx.x;                 // 128
    constexpr int J = F / 128;
    float acc[J];
    #pragma unroll
    for (int j = 0; j < J; j++) acc[j] = 0.0f;
    int start = g_off[node];
    int deg = g_deg[node];
    for (int i = 0; i < deg; i++) {
        const float* row = X + (size_t)g_csr[start + i] * F;
        #pragma unroll
        for (int j = 0; j < J; j++) acc[j] += row[t + j * 128];
    }
    float inv = (deg > 0) ? (1.0f / (float)deg) : 0.0f;
    size_t o = (size_t)node * F + t;
    #pragma unroll
    for (int j = 0; j < J; j++) {
        float v = acc[j] * inv;
        __nv_bfloat16 h = __float2bfloat16(v);
        OH[o + j * 128] = h;
        OL[o + j * 128] = __float2bfloat16(v - __bfloat162float(h));
    }
}

// ---------------- fp32 -> bf16 hi/lo split ----------------
__global__ void k_split(const float* __restrict__ X, __nv_bfloat16* __restrict__ H,
                        __nv_bfloat16* __restrict__ L, size_t n) {
    size_t i = (size_t)blockIdx.x * blockDim.x + threadIdx.x;
    if (i < n) {
        float v = X[i];
        __nv_bfloat16 h = __float2bfloat16(v);
        H[i] = h;
        L[i] = __float2bfloat16(v - __bfloat162float(h));
    }
}

// ---------------- weight transpose + split ----------------
__global__ void k_wt(const float* __restrict__ W, __nv_bfloat16* __restrict__ Th,
                     __nv_bfloat16* __restrict__ Tl, int K, int N) {
    __shared__ float t[32][33];
    int kb = blockIdx.x * 32, nb = blockIdx.y * 32;
    int tx = threadIdx.x, ty = threadIdx.y;  // 32 x 8
    #pragma unroll
    for (int i = 0; i < 32; i += 8)
        t[ty + i][tx] = W[(size_t)(kb + ty + i) * N + nb + tx];
    __syncthreads();
    #pragma unroll
    for (int i = 0; i < 32; i += 8) {
        float v = t[tx][ty + i];
        size_t o = (size_t)(nb + ty + i) * K + kb + tx;
        __nv_bfloat16 h = __float2bfloat16(v);
        Th[o] = h;
        Tl[o] = __float2bfloat16(v - __bfloat162float(h));
    }
}

// ---------------- bf16 mma.sync GEMM ----------------
// C[M,N] = sum_p A_p[M,Kp] @ B_p[N,Kp]^T + bias (+ReLU)
// CTA tile 128x128, warp tile 32x64 (4x2 warps), BK=64, 4-stage cp.async.
// Grid: x = M-tiles (fast) — the R3-measured-best rasterization.
struct GemmParams {
    const __nv_bfloat16* A[6];
    const __nv_bfloat16* B[6];
    int Kw[6];
    int chEnd[6];
    int totalChunks;
    const float* bias;
    float* C;
    int M;
    int Ncols;
    int relu;
};

#define STAGES 4
#define STAGE_BYTES 32768              // 16KB A + 16KB B
#define SMEM_REQ (1024 + STAGES * STAGE_BYTES)

__device__ __forceinline__ uint32_t swz(uint32_t o) { return o ^ ((o >> 3) & 0x70); }

__device__ __forceinline__ void cp16(uint32_t dst, const void* src, bool p) {
    int sz = p ? 16 : 0;
    asm volatile("cp.async.cg.shared.global [%0], [%1], 16, %2;\n"
                 :: "r"(dst), "l"(src), "r"(sz));
}

__global__ __launch_bounds__(256, 1) void k_gemm(const __grid_constant__ GemmParams P) {
    extern __shared__ char dsm[];
    uint32_t raw;
    asm("{ .reg .u64 t; cvta.to.shared.u64 t, %1; cvt.u32.u64 %0, t; }" : "=r"(raw) : "l"(dsm));
    uint32_t tiles = (raw + 1023) & ~1023u;
    int tid = threadIdx.x;
    int wid = tid >> 5;
    int lane = tid & 31;
    int mBase = blockIdx.x * 128;      // M-tile on x (fast) — R3 layout
    int nBase = blockIdx.y * 128;      // N-tile on y (slow)
    int mw = wid >> 1;     // 0..3
    int nw = wid & 1;      // 0..1

    auto load_chunk = [&](int c, int s) {
        int p = 0;
        while (c >= P.chEnd[p]) p++;
        int c0 = (p ? c - P.chEnd[p - 1] : c) * 64;
        const char* Ab = (const char*)P.A[p] + (size_t)c0 * 2;
        const char* Bb = (const char*)P.B[p] + (size_t)c0 * 2;
        size_t rowB = (size_t)P.Kw[p] * 2;
        uint32_t stA = tiles + s * STAGE_BYTES;
        uint32_t stB = stA + 16384;
        #pragma unroll
        for (int i = 0; i < 4; i++) {
            int o = tid + i * 256;
            int row = o >> 3, kb = (o & 7) * 16;
            bool ok = (mBase + row) < P.M;
            cp16(stA + swz(row * 128 + kb), Ab + (size_t)(mBase + row) * rowB + kb, ok);
        }
        #pragma unroll
        for (int i = 0; i < 4; i++) {
            int o = tid + i * 256;
            int row = o >> 3, kb = (o & 7) * 16;
            cp16(stB + swz(row * 128 + kb), Bb + (size_t)(nBase + row) * rowB + kb, true);
        }
        asm volatile("cp.async.commit_group;" ::: "memory");
    };

    const int T = P.totalChunks;

    float acc[2][8][4];
    #pragma unroll
    for (int mi = 0; mi < 2; mi++)
        #pragma unroll
        for (int n8 = 0; n8 < 8; n8++)
            #pragma unroll
            for (int q = 0; q < 4; q++) acc[mi][n8][q] = 0.0f;

    int npre = (T < 3) ? T : 3;
    for (int c = 0; c < npre; c++) load_chunk(c, c);

    for (int c = 0; c < T; c++) {
        int s = c & 3;
        int rem = (T - 1) - c;
        if (rem >= 2)      asm volatile("cp.async.wait_group 2;" ::: "memory");
        else if (rem == 1) asm volatile("cp.async.wait_group 1;" ::: "memory");
        else               asm volatile("cp.async.wait_group 0;" ::: "memory");
        __syncthreads();

        uint32_t stA = tiles + s * STAGE_BYTES;
        uint32_t stB = stA + 16384;
        #pragma unroll
        for (int ks = 0; ks < 4; ks++) {
            uint32_t a[2][4];
            uint32_t arow = mw * 32 + ((lane >> 3) & 1) * 8 + (lane & 7);
            uint32_t akb  = ks * 32 + (lane >> 4) * 16;
            #pragma unroll
            for (int mi = 0; mi < 2; mi++) {
                uint32_t ad = stA + swz((arow + mi * 16) * 128 + akb);
                asm volatile("ldmatrix.sync.aligned.m8n8.x4.shared.b16 {%0,%1,%2,%3}, [%4];"
                             : "=r"(a[mi][0]), "=r"(a[mi][1]), "=r"(a[mi][2]), "=r"(a[mi][3])
                             : "r"(ad));
            }
            uint32_t b[4][4];
            uint32_t brow = nw * 64 + ((lane >> 4) & 1) * 8 + (lane & 7);
            uint32_t bkb  = ks * 32 + ((lane >> 3) & 1) * 16;
            #pragma unroll
            for (int ni = 0; ni < 4; ni++) {
                uint32_t bd = stB + swz((brow + ni * 16) * 128 + bkb);
                asm volatile("ldmatrix.sync.aligned.m8n8.x4.shared.b16 {%0,%1,%2,%3}, [%4];"
                             : "=r"(b[ni][0]), "=r"(b[ni][1]), "=r"(b[ni][2]), "=r"(b[ni][3])
                             : "r"(bd));
            }
            #pragma unroll
            for (int mi = 0; mi < 2; mi++)
                #pragma unroll
                for (int n8 = 0; n8 < 8; n8++) {
                    uint32_t b0 = b[n8 >> 1][(n8 & 1) * 2 + 0];
                    uint32_t b1 = b[n8 >> 1][(n8 & 1) * 2 + 1];
                    asm volatile(
                        "mma.sync.aligned.m16n8k16.row.col.f32.bf16.bf16.f32 "
                        "{%0,%1,%2,%3}, {%4,%5,%6,%7}, {%8,%9}, {%0,%1,%2,%3};"
                        : "+f"(acc[mi][n8][0]), "+f"(acc[mi][n8][1]),
                          "+f"(acc[mi][n8][2]), "+f"(acc[mi][n8][3])
                        : "r"(a[mi][0]), "r"(a[mi][1]), "r"(a[mi][2]), "r"(a[mi][3]),
                          "r"(b0), "r"(b1));
                }
        }
        if (c + 3 < T) load_chunk(c + 3, (c + 3) & 3);
    }

    // epilogue: bias (+ReLU) store
    {
        int g = lane >> 2, t4 = lane & 3;
        #pragma unroll
        for (int mi = 0; mi < 2; mi++) {
            #pragma unroll
            for (int n8 = 0; n8 < 8; n8++) {
                int col = nBase + nw * 64 + n8 * 8 + t4 * 2;
                float bx = P.bias[col], by = P.bias[col + 1];
                int r0 = mBase + mw * 32 + mi * 16 + g;
                if (r0 < P.M) {
                    float2 v;
                    v.x = acc[mi][n8][0] + bx;
                    v.y = acc[mi][n8][1] + by;
                    if (P.relu) { v.x = fmaxf(v.x, 0.f); v.y = fmaxf(v.y, 0.f); }
                    *(float2*)(P.C + (size_t)r0 * P.Ncols + col) = v;
                }
                int r1 = r0 + 8;
                if (r1 < P.M) {
                    float2 v;
                    v.x = acc[mi][n8][2] + bx;
                    v.y = acc[mi][n8][3] + by;
                    if (P.relu) { v.x = fmaxf(v.x, 0.f); v.y = fmaxf(v.y, 0.f); }
                    *(float2*)(P.C + (size_t)r1 * P.Ncols + col) = v;
                }
            }
        }
    }
}

// ---------------- BN column stats ----------------
__global__ void k_colstats(const float* __restrict__ X) {
    int t = threadIdx.x;  // 256
    int rows_per = (N_NODES + gridDim.x - 1) / gridDim.x;
    int r0 = blockIdx.x * rows_per;
    int r1 = min(N_NODES, r0 + rows_per);
    float s[4] = {0, 0, 0, 0}, q[4] = {0, 0, 0, 0};
    for (int r = r0; r < r1; r++) {
        const float* row = X + (size_t)r * HID;
        #pragma unroll
        for (int j = 0; j < 4; j++) {
            float v = row[t + j * 256];
            s[j] += v; q[j] += v * v;
        }
    }
    #pragma unroll
    for (int j = 0; j < 4; j++) {
        atomicAdd(&g_sum[t + j * 256], s[j]);
        atomicAdd(&g_sumsq[t + j * 256], q[j]);
    }
}
__global__ void k_bnparams(const float* __restrict__ g, const float* __restrict__ be) {
    int c = blockIdx.x * blockDim.x + threadIdx.x;
    if (c < HID) {
        float m = g_sum[c] * (1.0f / N_NODES);
        float var = g_sumsq[c] * (1.0f / N_NODES) - m * m;
        float a = g[c] * rsqrtf(var + EPS_BN);
        g_a[c] = a;
        g_c[c] = be[c] - m * a;
    }
}
__global__ void k_bnrelu(const float* __restrict__ X, float* __restrict__ Y,
                         __nv_bfloat16* __restrict__ YH, __nv_bfloat16* __restrict__ YL) {
    size_t i = (size_t)blockIdx.x * blockDim.x + threadIdx.x;
    const size_t total = (size_t)N_NODES * HID / 4;
    if (i < total) {
        int c = (int)((i * 4) % HID);
        float4 v = ((const float4*)X)[i];
        v.x = fmaxf(0.f, v.x * g_a[c + 0] + g_c[c + 0]);
        v.y = fmaxf(0.f, v.y * g_a[c + 1] + g_c[c + 1]);
        v.z = fmaxf(0.f, v.z * g_a[c + 2] + g_c[c + 2]);
        v.w = fmaxf(0.f, v.w * g_a[c + 3] + g_c[c + 3]);
        ((float4*)Y)[i] = v;
        __nv_bfloat16 hx = __float2bfloat16(v.x), hy = __float2bfloat16(v.y);
        __nv_bfloat16 hz = __float2bfloat16(v.z), hw = __float2bfloat16(v.w);
        __nv_bfloat162* H2 = (__nv_bfloat162*)YH;
        __nv_bfloat162* L2 = (__nv_bfloat162*)YL;
        H2[i * 2 + 0] = __nv_bfloat162(hx, hy);
        H2[i * 2 + 1] = __nv_bfloat162(hz, hw);
        L2[i * 2 + 0] = __nv_bfloat162(__float2bfloat16(v.x - __bfloat162float(hx)),
                                       __float2bfloat16(v.y - __bfloat162float(hy)));
        L2[i * 2 + 1] = __nv_bfloat162(__float2bfloat16(v.z - __bfloat162float(hz)),
                                       __float2bfloat16(v.w - __bfloat162float(hw)));
    }
}

// ---------------- final head ----------------
__global__ void k_out(const float* __restrict__ H, const float* __restrict__ Wo,
                      const float* __restrict__ bo, float* __restrict__ Out) {
    __shared__ float sw[F_MID * N_OUT];
    for (int i = threadIdx.x; i < F_MID * N_OUT; i += blockDim.x) sw[i] = Wo[i];
    __syncthreads();
    int warp = threadIdx.x / 32, lane = threadIdx.x % 32;
    int row = blockIdx.x * (blockDim.x / 32) + warp;
    if (row >= N_NODES) return;
    float acc[N_OUT];
    #pragma unroll
    for (int o = 0; o < N_OUT; o++) acc[o] = 0.0f;
    const float* h = H + (size_t)row * F_MID;
    for (int k = lane; k < F_MID; k += 32) {
        float hv = h[k];
        #pragma unroll
        for (int o = 0; o < N_OUT; o++) acc[o] += hv * sw[k * N_OUT + o];
    }
    #pragma unroll
    for (int o = 0; o < N_OUT; o++)
        #pragma unroll
        for (int off = 16; off; off >>= 1)
            acc[o] += __shfl_down_sync(0xffffffffu, acc[o], off);
    if (lane == 0)
        #pragma unroll
        for (int o = 0; o < N_OUT; o++)
            Out[(size_t)row * N_OUT + o] = acc[o] + bo[o];
}

// ---------------- host-side GEMM launcher ----------------
struct PassDef { const __nv_bfloat16* A; const __nv_bfloat16* B; int Kw; };
static void run_gemm(const PassDef* passes, int np, const float* bias, float* C,
                     int M, int N, int relu) {
    GemmParams P = {};
    int cum = 0;
    for (int i = 0; i < np; i++) {
        P.A[i] = passes[i].A;
        P.B[i] = passes[i].B;
        P.Kw[i] = passes[i].Kw;
        cum += passes[i].Kw / 64;
        P.chEnd[i] = cum;
    }
    P.totalChunks = cum;
    P.bias = bias; P.C = C; P.M = M; P.Ncols = N; P.relu = relu;
    dim3 g((M + 127) / 128, N / 128);     // x = M-tile fast (R3 measured-best)
    k_gemm<<<g, 256, SMEM_REQ>>>(P);
}

// ---------------- launch ----------------
extern "C" void kernel_launch(void* const* d_in, const int* in_sizes, int n_in,
                              void* d_out, int out_size) {
    const float* x   = (const float*)d_in[0];
    const void*  edges = d_in[1];
    const float* W1l = (const float*)d_in[2];
    const float* b1  = (const float*)d_in[3];
    const float* W1r = (const float*)d_in[4];
    const float* g1  = (const float*)d_in[5];
    const float* be1 = (const float*)d_in[6];
    const float* W2l = (const float*)d_in[7];
    const float* b2  = (const float*)d_in[8];
    const float* W2r = (const float*)d_in[9];
    const float* g2  = (const float*)d_in[10];
    const float* be2 = (const float*)d_in[11];
    const float* Wf  = (const float*)d_in[12];
    const float* bf  = (const float*)d_in[13];
    const float* Wo  = (const float*)d_in[14];
    const float* bo  = (const float*)d_in[15];
    float* out = (float*)d_out;

    cudaFuncSetAttribute(k_gemm, cudaFuncAttributeMaxDynamicSharedMemorySize, SMEM_REQ);

    void *p_deg, *p_sum, *p_sumsq, *p_tmp, *p_h, *p_Ah, *p_Al, *p_Bh, *p_Bl, *p_Wh, *p_Wl;
    cudaGetSymbolAddress(&p_deg, g_deg);
    cudaGetSymbolAddress(&p_sum, g_sum);
    cudaGetSymbolAddress(&p_sumsq, g_sumsq);
    cudaGetSymbolAddress(&p_tmp, g_tmp);
    cudaGetSymbolAddress(&p_h, g_h);
    cudaGetSymbolAddress(&p_Ah, g_Ah);
    cudaGetSymbolAddress(&p_Al, g_Al);
    cudaGetSymbolAddress(&p_Bh, g_Bh);
    cudaGetSymbolAddress(&p_Bl, g_Bl);
    cudaGetSymbolAddress(&p_Wh, g_Wh);
    cudaGetSymbolAddress(&p_Wl, g_Wl);
    float* tmp = (float*)p_tmp;
    float* h   = (float*)p_h;
    __nv_bfloat16* Ah = (__nv_bfloat16*)p_Ah;
    __nv_bfloat16* Al = (__nv_bfloat16*)p_Al;
    __nv_bfloat16* Bh = (__nv_bfloat16*)p_Bh;
    __nv_bfloat16* Bl = (__nv_bfloat16*)p_Bl;
    __nv_bfloat16* Wh = (__nv_bfloat16*)p_Wh;
    __nv_bfloat16* Wl = (__nv_bfloat16*)p_Wl;

    // CSR build
    cudaMemsetAsync(p_deg, 0, N_NODES * sizeof(int));
    k_detect<<<1, 32>>>((const unsigned int*)edges);
    k_hist<<<(N_EDGES + 255) / 256, 256>>>(edges);
    k_scan<<<1, 1024>>>();
    k_scatter<<<(N_EDGES + 255) / 256, 256>>>(edges);

    // weight transpose + split
    dim3 wb(32, 8);
    k_wt<<<dim3(F_IN / 32, HID / 32), wb>>>(W1l, Wh + OFF_W1L, Wl + OFF_W1L, F_IN, HID);
    k_wt<<<dim3(F_IN / 32, HID / 32), wb>>>(W1r, Wh + OFF_W1R, Wl + OFF_W1R, F_IN, HID);
    k_wt<<<dim3(HID / 32, HID / 32), wb>>>(W2l, Wh + OFF_W2L, Wl + OFF_W2L, HID, HID);
    k_wt<<<dim3(HID / 32, HID / 32), wb>>>(W2r, Wh + OFF_W2R, Wl + OFF_W2R, HID, HID);
    k_wt<<<dim3(HID / 32, F_MID / 32), wb>>>(Wf, Wh + OFF_WF, Wl + OFF_WF, HID, F_MID);

    // x split
    {
        size_t n = (size_t)N_NODES * F_IN;
        k_split<<<(unsigned)((n + 255) / 256), 256>>>(x, Bh, Bl, n);
    }

    // ---- layer 1 ----
    k_aggregate<F_IN><<<N_NODES, 128>>>(x, Ah, Al);
    {
        PassDef pl[6] = {
            {Ah, Wh + OFF_W1L, F_IN}, {Ah, Wl + OFF_W1L, F_IN}, {Al, Wh + OFF_W1L, F_IN},
            {Bh, Wh + OFF_W1R, F_IN}, {Bh, Wl + OFF_W1R, F_IN}, {Bl, Wh + OFF_W1R, F_IN},
        };
        run_gemm(pl, 6, b1, tmp, N_NODES, HID, 0);
    }
    cudaMemsetAsync(p_sum, 0, HID * sizeof(float));
    cudaMemsetAsync(p_sumsq, 0, HID * sizeof(float));
    k_colstats<<<128, 256>>>(tmp);
    k_bnparams<<<HID / 256, 256>>>(g1, be1);
    {
        size_t n4 = (size_t)N_NODES * HID / 4;
        k_bnrelu<<<(unsigned)((n4 + 255) / 256), 256>>>(tmp, h, Bh, Bl);
    }

    // ---- layer 2 ----
    k_aggregate<HID><<<N_NODES, 128>>>(h, Ah, Al);
    {
        PassDef pl[6] = {
            {Ah, Wh + OFF_W2L, HID}, {Ah, Wl + OFF_W2L, HID}, {Al, Wh + OFF_W2L, HID},
            {Bh, Wh + OFF_W2R, HID}, {Bh, Wl + OFF_W2R, HID}, {Bl, Wh + OFF_W2R, HID},
        };
        run_gemm(pl, 6, b2, tmp, N_NODES, HID, 0);
    }
    cudaMemsetAsync(p_sum, 0, HID * sizeof(float));
    cudaMemsetAsync(p_sumsq, 0, HID * sizeof(float));
    k_colstats<<<128, 256>>>(tmp);
    k_bnparams<<<HID / 256, 256>>>(g2, be2);
    {
        size_t n4 = (size_t)N_NODES * HID / 4;
        k_bnrelu<<<(unsigned)((n4 + 255) / 256), 256>>>(tmp, h, Bh, Bl);
    }

    // ---- fc + ReLU ----
    {
        PassDef pl[3] = {
            {Bh, Wh + OFF_WF, HID}, {Bh, Wl + OFF_WF, HID}, {Bl, Wh + OFF_WF, HID},
        };
        run_gemm(pl, 3, bf, tmp, N_NODES, F_MID, 1);
    }

    // ---- head ----
    k_out<<<(N_NODES + 7) / 8, 256>>>(tmp, Wo, bo, out);
}

// round 9
// speedup vs baseline: 1.3273x; 1.3244x over previous
#include <cuda_runtime.h>
#include <cuda_bf16.h>
#include <cstdint>

#define N_NODES 50000
#define N_EDGES 400000
#define F_IN    256
#define HID     1024
#define F_MID   512
#define N_OUT   10
#define EPS_BN  1e-5f

// ---------------- scratch (device globals) ----------------
__device__ float g_tmp[(size_t)N_NODES * HID];
__device__ __nv_bfloat16 g_Ah[(size_t)N_NODES * HID];
__device__ __nv_bfloat16 g_Al[(size_t)N_NODES * HID];
__device__ __nv_bfloat16 g_Bh[(size_t)N_NODES * HID];
__device__ __nv_bfloat16 g_Bl[(size_t)N_NODES * HID];
#define OFF_W1L 0
#define OFF_W1R 262144
#define OFF_W2L 524288
#define OFF_W2R 1572864
#define OFF_WF  2621440
__device__ __nv_bfloat16 g_Wh[3145728];
__device__ __nv_bfloat16 g_Wl[3145728];

__device__ int   g_deg[N_NODES];
__device__ int   g_off[N_NODES];
__device__ int   g_cur[N_NODES];
__device__ int   g_csr[N_EDGES];
__device__ float g_sum[HID];
__device__ float g_sumsq[HID];
__device__ float g_a[HID];
__device__ float g_c[HID];
__device__ int   g_is64;

// ---------------- dtype detection ----------------
__global__ void k_detect(const unsigned int* e) {
    if (threadIdx.x == 0) {
        int is64 = 1;
        for (int i = 0; i < 64; i++)
            if (e[2 * i + 1] != 0u) { is64 = 0; break; }
        g_is64 = is64;
    }
}
__device__ __forceinline__ int load_edge(const void* edges, int idx) {
    if (g_is64) return (int)((const long long*)edges)[idx];
    return ((const int*)edges)[idx];
}

// ---------------- CSR build ----------------
__global__ void k_hist(const void* edges) {
    int i = blockIdx.x * blockDim.x + threadIdx.x;
    if (i < N_EDGES) atomicAdd(&g_deg[load_edge(edges, N_EDGES + i)], 1);
}
__global__ void k_scan() {
    __shared__ int sh[1024];
    __shared__ int carry;
    int t = threadIdx.x;
    if (t == 0) carry = 0;
    __syncthreads();
    for (int base = 0; base < N_NODES; base += 1024) {
        int v = (base + t < N_NODES) ? g_deg[base + t] : 0;
        sh[t] = v;
        __syncthreads();
        #pragma unroll
        for (int off = 1; off < 1024; off <<= 1) {
            int add = (t >= off) ? sh[t - off] : 0;
            __syncthreads();
            sh[t] += add;
            __syncthreads();
        }
        int excl = sh[t] - v;
        int c0 = carry;
        if (base + t < N_NODES) { g_off[base + t] = c0 + excl; g_cur[base + t] = c0 + excl; }
        __syncthreads();
        if (t == 0) carry = c0 + sh[1023];
        __syncthreads();
    }
}
__global__ void k_scatter(const void* edges) {
    int i = blockIdx.x * blockDim.x + threadIdx.x;
    if (i < N_EDGES) {
        int src = load_edge(edges, i);
        int dst = load_edge(edges, N_EDGES + i);
        g_csr[atomicAdd(&g_cur[dst], 1)] = src;
    }
}

// ---------------- layer-1 aggregation: fp32 x -> bf16 hi/lo ----------------
__global__ void k_agg1(const float* __restrict__ X,
                       __nv_bfloat16* __restrict__ OH, __nv_bfloat16* __restrict__ OL) {
    int node = blockIdx.x;
    int t = threadIdx.x;                 // 128, 2 floats each
    float a0 = 0.f, a1 = 0.f;
    int start = g_off[node];
    int deg = g_deg[node];
    for (int i = 0; i < deg; i++) {
        const float2 v = *(const float2*)(X + (size_t)g_csr[start + i] * F_IN + t * 2);
        a0 += v.x; a1 += v.y;
    }
    float inv = (deg > 0) ? (1.0f / (float)deg) : 0.0f;
    a0 *= inv; a1 *= inv;
    __nv_bfloat16 h0 = __float2bfloat16(a0), h1 = __float2bfloat16(a1);
    size_t o = (size_t)node * F_IN + t * 2;
    *(__nv_bfloat162*)(OH + o) = __nv_bfloat162(h0, h1);
    *(__nv_bfloat162*)(OL + o) = __nv_bfloat162(
        __float2bfloat16(a0 - __bfloat162float(h0)),
        __float2bfloat16(a1 - __bfloat162float(h1)));
}

// ---------------- layer-2 aggregation: bf16 hi/lo -> bf16 hi/lo ------------
__global__ void k_agg2(const __nv_bfloat16* __restrict__ XH, const __nv_bfloat16* __restrict__ XL,
                       __nv_bfloat16* __restrict__ OH, __nv_bfloat16* __restrict__ OL) {
    int node = blockIdx.x;
    int t = threadIdx.x;                 // 128, 8 elems each
    float acc[8];
    #pragma unroll
    for (int j = 0; j < 8; j++) acc[j] = 0.f;
    int start = g_off[node];
    int deg = g_deg[node];
    for (int i = 0; i < deg; i++) {
        size_t ro = (size_t)g_csr[start + i] * HID + t * 8;
        union { uint4 u; __nv_bfloat16 b[8]; } uh, ul;
        uh.u = *(const uint4*)(XH + ro);
        ul.u = *(const uint4*)(XL + ro);
        #pragma unroll
        for (int j = 0; j < 8; j++)
            acc[j] += __bfloat162float(uh.b[j]) + __bfloat162float(ul.b[j]);
    }
    float inv = (deg > 0) ? (1.0f / (float)deg) : 0.0f;
    union { uint4 u; __nv_bfloat16 b[8]; } oh, ol;
    #pragma unroll
    for (int j = 0; j < 8; j++) {
        float v = acc[j] * inv;
        __nv_bfloat16 h = __float2bfloat16(v);
        oh.b[j] = h;
        ol.b[j] = __float2bfloat16(v - __bfloat162float(h));
    }
    size_t o = (size_t)node * HID + t * 8;
    *(uint4*)(OH + o) = oh.u;
    *(uint4*)(OL + o) = ol.u;
}

// ---------------- fp32 -> bf16 hi/lo split ----------------
__global__ void k_split(const float* __restrict__ X, __nv_bfloat16* __restrict__ H,
                        __nv_bfloat16* __restrict__ L, size_t n) {
    size_t i = (size_t)blockIdx.x * blockDim.x + threadIdx.x;
    if (i < n) {
        float v = X[i];
        __nv_bfloat16 h = __float2bfloat16(v);
        H[i] = h;
        L[i] = __float2bfloat16(v - __bfloat162float(h));
    }
}

// ---------------- weight transpose + split ----------------
__global__ void k_wt(const float* __restrict__ W, __nv_bfloat16* __restrict__ Th,
                     __nv_bfloat16* __restrict__ Tl, int K, int N) {
    __shared__ float t[32][33];
    int kb = blockIdx.x * 32, nb = blockIdx.y * 32;
    int tx = threadIdx.x, ty = threadIdx.y;  // 32 x 8
    #pragma unroll
    for (int i = 0; i < 32; i += 8)
        t[ty + i][tx] = W[(size_t)(kb + ty + i) * N + nb + tx];
    __syncthreads();
    #pragma unroll
    for (int i = 0; i < 32; i += 8) {
        float v = t[tx][ty + i];
        size_t o = (size_t)(nb + ty + i) * K + kb + tx;
        __nv_bfloat16 h = __float2bfloat16(v);
        Th[o] = h;
        Tl[o] = __float2bfloat16(v - __bfloat162float(h));
    }
}

// ---------------- bf16 mma.sync GEMM ----------------
// C[M,N] = sum_p A_p[M,Kp] @ B_p[N,Kp]^T + bias (+ReLU) (+fused column stats)
// CTA tile 128x128, warp tile 32x64 (4x2 warps), BK=64,
// 3-stage cp.async, 2 CTAs/SM (16 warps/SM) — best measured config.
struct GemmParams {
    const __nv_bfloat16* A[6];
    const __nv_bfloat16* B[6];
    int Kw[6];
    int chEnd[6];
    int totalChunks;
    const float* bias;
    float* C;
    int M;
    int Ncols;
    int relu;
    int stats;
};

#define STAGES 3
#define STAGE_BYTES 32768              // 16KB A + 16KB B
#define SMEM_REQ (1024 + STAGES * STAGE_BYTES)

__device__ __forceinline__ uint32_t swz(uint32_t o) { return o ^ ((o >> 3) & 0x70); }

__device__ __forceinline__ void cp16(uint32_t dst, const void* src, bool p) {
    int sz = p ? 16 : 0;
    asm volatile("cp.async.cg.shared.global [%0], [%1], 16, %2;\n"
                 :: "r"(dst), "l"(src), "r"(sz));
}

__global__ __launch_bounds__(256, 2) void k_gemm(const __grid_constant__ GemmParams P) {
    extern __shared__ char dsm[];
    uint32_t raw;
    asm("{ .reg .u64 t; cvta.to.shared.u64 t, %1; cvt.u32.u64 %0, t; }" : "=r"(raw) : "l"(dsm));
    uint32_t tiles = (raw + 1023) & ~1023u;
    int tid = threadIdx.x;
    int wid = tid >> 5;
    int lane = tid & 31;
    int mBase = blockIdx.x * 128;
    int nBase = blockIdx.y * 128;
    int mw = wid >> 1;     // 0..3
    int nw = wid & 1;      // 0..1

    auto load_chunk = [&](int c, int s) {
        int p = 0;
        while (c >= P.chEnd[p]) p++;
        int c0 = (p ? c - P.chEnd[p - 1] : c) * 64;
        const char* Ab = (const char*)P.A[p] + (size_t)c0 * 2;
        const char* Bb = (const char*)P.B[p] + (size_t)c0 * 2;
        size_t rowB = (size_t)P.Kw[p] * 2;
        uint32_t stA = tiles + s * STAGE_BYTES;
        uint32_t stB = stA + 16384;
        #pragma unroll
        for (int i = 0; i < 4; i++) {
            int o = tid + i * 256;
            int row = o >> 3, kb = (o & 7) * 16;
            bool ok = (mBase + row) < P.M;
            cp16(stA + swz(row * 128 + kb), Ab + (size_t)(mBase + row) * rowB + kb, ok);
        }
        #pragma unroll
        for (int i = 0; i < 4; i++) {
            int o = tid + i * 256;
            int row = o >> 3, kb = (o & 7) * 16;
            cp16(stB + swz(row * 128 + kb), Bb + (size_t)(nBase + row) * rowB + kb, true);
        }
        asm volatile("cp.async.commit_group;" ::: "memory");
    };

    const int T = P.totalChunks;

    float acc[2][8][4];
    #pragma unroll
    for (int mi = 0; mi < 2; mi++)
        #pragma unroll
        for (int n8 = 0; n8 < 8; n8++)
            #pragma unroll
            for (int q = 0; q < 4; q++) acc[mi][n8][q] = 0.0f;

    int npre = (T < 2) ? T : 2;
    for (int c = 0; c < npre; c++) load_chunk(c, c);

    for (int c = 0; c < T; c++) {
        int s = c % 3;
        if (c == T - 1) asm volatile("cp.async.wait_group 0;" ::: "memory");
        else            asm volatile("cp.async.wait_group 1;" ::: "memory");
        __syncthreads();

        uint32_t stA = tiles + s * STAGE_BYTES;
        uint32_t stB = stA + 16384;
        #pragma unroll
        for (int ks = 0; ks < 4; ks++) {
            uint32_t a[2][4];
            uint32_t arow = mw * 32 + ((lane >> 3) & 1) * 8 + (lane & 7);
            uint32_t akb  = ks * 32 + (lane >> 4) * 16;
            #pragma unroll
            for (int mi = 0; mi < 2; mi++) {
                uint32_t ad = stA + swz((arow + mi * 16) * 128 + akb);
                asm volatile("ldmatrix.sync.aligned.m8n8.x4.shared.b16 {%0,%1,%2,%3}, [%4];"
                             : "=r"(a[mi][0]), "=r"(a[mi][1]), "=r"(a[mi][2]), "=r"(a[mi][3])
                             : "r"(ad));
            }
            uint32_t b[4][4];
            uint32_t brow = nw * 64 + ((lane >> 4) & 1) * 8 + (lane & 7);
            uint32_t bkb  = ks * 32 + ((lane >> 3) & 1) * 16;
            #pragma unroll
            for (int ni = 0; ni < 4; ni++) {
                uint32_t bd = stB + swz((brow + ni * 16) * 128 + bkb);
                asm volatile("ldmatrix.sync.aligned.m8n8.x4.shared.b16 {%0,%1,%2,%3}, [%4];"
                             : "=r"(b[ni][0]), "=r"(b[ni][1]), "=r"(b[ni][2]), "=r"(b[ni][3])
                             : "r"(bd));
            }
            #pragma unroll
            for (int mi = 0; mi < 2; mi++)
                #pragma unroll
                for (int n8 = 0; n8 < 8; n8++) {
                    uint32_t b0 = b[n8 >> 1][(n8 & 1) * 2 + 0];
                    uint32_t b1 = b[n8 >> 1][(n8 & 1) * 2 + 1];
                    asm volatile(
                        "mma.sync.aligned.m16n8k16.row.col.f32.bf16.bf16.f32 "
                        "{%0,%1,%2,%3}, {%4,%5,%6,%7}, {%8,%9}, {%0,%1,%2,%3};"
                        : "+f"(acc[mi][n8][0]), "+f"(acc[mi][n8][1]),
                          "+f"(acc[mi][n8][2]), "+f"(acc[mi][n8][3])
                        : "r"(a[mi][0]), "r"(a[mi][1]), "r"(a[mi][2]), "r"(a[mi][3]),
                          "r"(b0), "r"(b1));
                }
        }
        if (c + 2 < T) load_chunk(c + 2, (c + 2) % 3);
    }

    // epilogue: bias (+ReLU) store + fused column stats
    {
        int g = lane >> 2, t4 = lane & 3;
        #pragma unroll
        for (int n8 = 0; n8 < 8; n8++) {
            int col = nBase + nw * 64 + n8 * 8 + t4 * 2;
            float bx = P.bias[col], by = P.bias[col + 1];
            float s0 = 0.f, s1 = 0.f, q0 = 0.f, q1 = 0.f;
            #pragma unroll
            for (int mi = 0; mi < 2; mi++) {
                int r0 = mBase + mw * 32 + mi * 16 + g;
                float2 v;
                v.x = acc[mi][n8][0] + bx;
                v.y = acc[mi][n8][1] + by;
                if (P.relu) { v.x = fmaxf(v.x, 0.f); v.y = fmaxf(v.y, 0.f); }
                if (r0 < P.M) {
                    *(float2*)(P.C + (size_t)r0 * P.Ncols + col) = v;
                    s0 += v.x; s1 += v.y; q0 += v.x * v.x; q1 += v.y * v.y;
                }
                int r1 = r0 + 8;
                float2 w;
                w.x = acc[mi][n8][2] + bx;
                w.y = acc[mi][n8][3] + by;
                if (P.relu) { w.x = fmaxf(w.x, 0.f); w.y = fmaxf(w.y, 0.f); }
                if (r1 < P.M) {
                    *(float2*)(P.C + (size_t)r1 * P.Ncols + col) = w;
                    s0 += w.x; s1 += w.y; q0 += w.x * w.x; q1 += w.y * w.y;
                }
            }
            if (P.stats) {
                #pragma unroll
                for (int o = 4; o <= 16; o <<= 1) {
                    s0 += __shfl_xor_sync(0xffffffffu, s0, o);
                    s1 += __shfl_xor_sync(0xffffffffu, s1, o);
                    q0 += __shfl_xor_sync(0xffffffffu, q0, o);
                    q1 += __shfl_xor_sync(0xffffffffu, q1, o);
                }
                if (g == 0) {
                    atomicAdd(&g_sum[col], s0);
                    atomicAdd(&g_sum[col + 1], s1);
                    atomicAdd(&g_sumsq[col], q0);
                    atomicAdd(&g_sumsq[col + 1], q1);
                }
            }
        }
    }
}

// ---------------- BN params / apply ----------------
__global__ void k_bnparams(const float* __restrict__ g, const float* __restrict__ be) {
    int c = blockIdx.x * blockDim.x + threadIdx.x;
    if (c < HID) {
        float m = g_sum[c] * (1.0f / N_NODES);
        float var = g_sumsq[c] * (1.0f / N_NODES) - m * m;
        float a = g[c] * rsqrtf(var + EPS_BN);
        g_a[c] = a;
        g_c[c] = be[c] - m * a;
    }
}
__global__ void k_bnrelu(const float* __restrict__ X,
                         __nv_bfloat16* __restrict__ YH, __nv_bfloat16* __restrict__ YL) {
    size_t i = (size_t)blockIdx.x * blockDim.x + threadIdx.x;  // float4 index
    const size_t total = (size_t)N_NODES * HID / 4;
    if (i < total) {
        int c = (int)((i * 4) % HID);
        float4 v = ((const float4*)X)[i];
        v.x = fmaxf(0.f, v.x * g_a[c + 0] + g_c[c + 0]);
        v.y = fmaxf(0.f, v.y * g_a[c + 1] + g_c[c + 1]);
        v.z = fmaxf(0.f, v.z * g_a[c + 2] + g_c[c + 2]);
        v.w = fmaxf(0.f, v.w * g_a[c + 3] + g_c[c + 3]);
        __nv_bfloat16 hx = __float2bfloat16(v.x), hy = __float2bfloat16(v.y);
        __nv_bfloat16 hz = __float2bfloat16(v.z), hw = __float2bfloat16(v.w);
        __nv_bfloat162* H2 = (__nv_bfloat162*)YH;
        __nv_bfloat162* L2 = (__nv_bfloat162*)YL;
        H2[i * 2 + 0] = __nv_bfloat162(hx, hy);
        H2[i * 2 + 1] = __nv_bfloat162(hz, hw);
        L2[i * 2 + 0] = __nv_bfloat162(__float2bfloat16(v.x - __bfloat162float(hx)),
                                       __float2bfloat16(v.y - __bfloat162float(hy)));
        L2[i * 2 + 1] = __nv_bfloat162(__float2bfloat16(v.z - __bfloat162float(hz)),
                                       __float2bfloat16(v.w - __bfloat162float(hw)));
    }
}

// ---------------- final head ----------------
__global__ void k_out(const float* __restrict__ H, const float* __restrict__ Wo,
                      const float* __restrict__ bo, float* __restrict__ Out) {
    __shared__ float sw[F_MID * N_OUT];
    for (int i = threadIdx.x; i < F_MID * N_OUT; i += blockDim.x) sw[i] = Wo[i];
    __syncthreads();
    int warp = threadIdx.x / 32, lane = threadIdx.x % 32;
    int row = blockIdx.x * (blockDim.x / 32) + warp;
    if (row >= N_NODES) return;
    float acc[N_OUT];
    #pragma unroll
    for (int o = 0; o < N_OUT; o++) acc[o] = 0.0f;
    const float* h = H + (size_t)row * F_MID;
    for (int k = lane; k < F_MID; k += 32) {
        float hv = h[k];
        #pragma unroll
        for (int o = 0; o < N_OUT; o++) acc[o] += hv * sw[k * N_OUT + o];
    }
    #pragma unroll
    for (int o = 0; o < N_OUT; o++)
        #pragma unroll
        for (int off = 16; off; off >>= 1)
            acc[o] += __shfl_down_sync(0xffffffffu, acc[o], off);
    if (lane == 0)
        #pragma unroll
        for (int o = 0; o < N_OUT; o++)
            Out[(size_t)row * N_OUT + o] = acc[o] + bo[o];
}

// ---------------- host-side GEMM launcher ----------------
struct PassDef { const __nv_bfloat16* A; const __nv_bfloat16* B; int Kw; };
static void run_gemm(const PassDef* passes, int np, const float* bias, float* C,
                     int M, int N, int relu, int stats) {
    GemmParams P = {};
    int cum = 0;
    for (int i = 0; i < np; i++) {
        P.A[i] = passes[i].A;
        P.B[i] = passes[i].B;
        P.Kw[i] = passes[i].Kw;
        cum += passes[i].Kw / 64;
        P.chEnd[i] = cum;
    }
    P.totalChunks = cum;
    P.bias = bias; P.C = C; P.M = M; P.Ncols = N; P.relu = relu; P.stats = stats;
    dim3 g((M + 127) / 128, N / 128);
    k_gemm<<<g, 256, SMEM_REQ>>>(P);
}

// ---------------- launch ----------------
extern "C" void kernel_launch(void* const* d_in, const int* in_sizes, int n_in,
                              void* d_out, int out_size) {
    const float* x   = (const float*)d_in[0];
    const void*  edges = d_in[1];
    const float* W1l = (const float*)d_in[2];
    const float* b1  = (const float*)d_in[3];
    const float* W1r = (const float*)d_in[4];
    const float* g1  = (const float*)d_in[5];
    const float* be1 = (const float*)d_in[6];
    const float* W2l = (const float*)d_in[7];
    const float* b2  = (const float*)d_in[8];
    const float* W2r = (const float*)d_in[9];
    const float* g2  = (const float*)d_in[10];
    const float* be2 = (const float*)d_in[11];
    const float* Wf  = (const float*)d_in[12];
    const float* bf  = (const float*)d_in[13];
    const float* Wo  = (const float*)d_in[14];
    const float* bo  = (const float*)d_in[15];
    float* out = (float*)d_out;

    cudaFuncSetAttribute(k_gemm, cudaFuncAttributeMaxDynamicSharedMemorySize, SMEM_REQ);

    void *p_deg, *p_sum, *p_sumsq, *p_tmp, *p_Ah, *p_Al, *p_Bh, *p_Bl, *p_Wh, *p_Wl;
    cudaGetSymbolAddress(&p_deg, g_deg);
    cudaGetSymbolAddress(&p_sum, g_sum);
    cudaGetSymbolAddress(&p_sumsq, g_sumsq);
    cudaGetSymbolAddress(&p_tmp, g_tmp);
    cudaGetSymbolAddress(&p_Ah, g_Ah);
    cudaGetSymbolAddress(&p_Al, g_Al);
    cudaGetSymbolAddress(&p_Bh, g_Bh);
    cudaGetSymbolAddress(&p_Bl, g_Bl);
    cudaGetSymbolAddress(&p_Wh, g_Wh);
    cudaGetSymbolAddress(&p_Wl, g_Wl);
    float* tmp = (float*)p_tmp;
    __nv_bfloat16* Ah = (__nv_bfloat16*)p_Ah;
    __nv_bfloat16* Al = (__nv_bfloat16*)p_Al;
    __nv_bfloat16* Bh = (__nv_bfloat16*)p_Bh;
    __nv_bfloat16* Bl = (__nv_bfloat16*)p_Bl;
    __nv_bfloat16* Wh = (__nv_bfloat16*)p_Wh;
    __nv_bfloat16* Wl = (__nv_bfloat16*)p_Wl;

    // CSR build
    cudaMemsetAsync(p_deg, 0, N_NODES * sizeof(int));
    k_detect<<<1, 32>>>((const unsigned int*)edges);
    k_hist<<<(N_EDGES + 255) / 256, 256>>>(edges);
    k_scan<<<1, 1024>>>();
    k_scatter<<<(N_EDGES + 255) / 256, 256>>>(edges);

    // weight transpose + split
    dim3 wb(32, 8);
    k_wt<<<dim3(F_IN / 32, HID / 32), wb>>>(W1l, Wh + OFF_W1L, Wl + OFF_W1L, F_IN, HID);
    k_wt<<<dim3(F_IN / 32, HID / 32), wb>>>(W1r, Wh + OFF_W1R, Wl + OFF_W1R, F_IN, HID);
    k_wt<<<dim3(HID / 32, HID / 32), wb>>>(W2l, Wh + OFF_W2L, Wl + OFF_W2L, HID, HID);
    k_wt<<<dim3(HID / 32, HID / 32), wb>>>(W2r, Wh + OFF_W2R, Wl + OFF_W2R, HID, HID);
    k_wt<<<dim3(HID / 32, F_MID / 32), wb>>>(Wf, Wh + OFF_WF, Wl + OFF_WF, HID, F_MID);

    // x split
    {
        size_t n = (size_t)N_NODES * F_IN;
        k_split<<<(unsigned)((n + 255) / 256), 256>>>(x, Bh, Bl, n);
    }

    // ---- layer 1 ----
    k_agg1<<<N_NODES, 128>>>(x, Ah, Al);
    cudaMemsetAsync(p_sum, 0, HID * sizeof(float));
    cudaMemsetAsync(p_sumsq, 0, HID * sizeof(float));
    {
        PassDef pl[6] = {
            {Ah, Wh + OFF_W1L, F_IN}, {Ah, Wl + OFF_W1L, F_IN}, {Al, Wh + OFF_W1L, F_IN},
            {Bh, Wh + OFF_W1R, F_IN}, {Bh, Wl + OFF_W1R, F_IN}, {Bl, Wh + OFF_W1R, F_IN},
        };
        run_gemm(pl, 6, b1, tmp, N_NODES, HID, 0, 1);
    }
    k_bnparams<<<HID / 256, 256>>>(g1, be1);
    {
        size_t n4 = (size_t)N_NODES * HID / 4;
        k_bnrelu<<<(unsigned)((n4 + 255) / 256), 256>>>(tmp, Bh, Bl);
    }

    // ---- layer 2 ----
    k_agg2<<<N_NODES, 128>>>(Bh, Bl, Ah, Al);
    cudaMemsetAsync(p_sum, 0, HID * sizeof(float));
    cudaMemsetAsync(p_sumsq, 0, HID * sizeof(float));
    {
        PassDef pl[6] = {
            {Ah, Wh + OFF_W2L, HID}, {Ah, Wl + OFF_W2L, HID}, {Al, Wh + OFF_W2L, HID},
            {Bh, Wh + OFF_W2R, HID}, {Bh, Wl + OFF_W2R, HID}, {Bl, Wh + OFF_W2R, HID},
        };
        run_gemm(pl, 6, b2, tmp, N_NODES, HID, 0, 1);
    }
    k_bnparams<<<HID / 256, 256>>>(g2, be2);
    {
        size_t n4 = (size_t)N_NODES * HID / 4;
        k_bnrelu<<<(unsigned)((n4 + 255) / 256), 256>>>(tmp, Bh, Bl);
    }

    // ---- fc + ReLU ----
    {
        PassDef pl[3] = {
            {Bh, Wh + OFF_WF, HID}, {Bh, Wl + OFF_WF, HID}, {Bl, Wh + OFF_WF, HID},
        };
        run_gemm(pl, 3, bf, tmp, N_NODES, F_MID, 1, 0);
    }

    // ---- head ----
    k_out<<<(N_NODES + 7) / 8, 256>>>(tmp, Wo, bo, out);
}

// round 10
// speedup vs baseline: 1.7700x; 1.3335x over previous
#include <cuda_runtime.h>
#include <cuda_fp16.h>
#include <cstdint>

#define N_NODES 50000
#define N_EDGES 400000
#define F_IN    256
#define HID     1024
#define F_MID   512
#define N_OUT   10
#define EPS_BN  1e-5f

// ---------------- scratch (device globals) ----------------
__device__ float g_tmp[(size_t)N_NODES * HID];
__device__ __half g_Ah[(size_t)N_NODES * HID];   // aggregate hi
__device__ __half g_Al[(size_t)N_NODES * HID];   // aggregate lo
__device__ __half g_Bh[(size_t)N_NODES * HID];   // x / h hi
__device__ __half g_Bl[(size_t)N_NODES * HID];   // x / h lo
#define OFF_W1L 0
#define OFF_W1R 262144
#define OFF_W2L 524288
#define OFF_W2R 1572864
#define OFF_WF  2621440
__device__ __half g_W16[3145728];                // fp16 weights (transposed)

__device__ int   g_deg[N_NODES];
__device__ int   g_off[N_NODES];
__device__ int   g_cur[N_NODES];
__device__ int   g_csr[N_EDGES];
__device__ float g_sum[HID];
__device__ float g_sumsq[HID];
__device__ float g_a[HID];
__device__ float g_c[HID];
__device__ int   g_is64;

// ---------------- dtype detection ----------------
__global__ void k_detect(const unsigned int* e) {
    if (threadIdx.x == 0) {
        int is64 = 1;
        for (int i = 0; i < 64; i++)
            if (e[2 * i + 1] != 0u) { is64 = 0; break; }
        g_is64 = is64;
    }
}
__device__ __forceinline__ int load_edge(const void* edges, int idx) {
    if (g_is64) return (int)((const long long*)edges)[idx];
    return ((const int*)edges)[idx];
}

// ---------------- CSR build ----------------
__global__ void k_hist(const void* edges) {
    int i = blockIdx.x * blockDim.x + threadIdx.x;
    if (i < N_EDGES) atomicAdd(&g_deg[load_edge(edges, N_EDGES + i)], 1);
}
__global__ void k_scan() {
    __shared__ int sh[1024];
    __shared__ int carry;
    int t = threadIdx.x;
    if (t == 0) carry = 0;
    __syncthreads();
    for (int base = 0; base < N_NODES; base += 1024) {
        int v = (base + t < N_NODES) ? g_deg[base + t] : 0;
        sh[t] = v;
        __syncthreads();
        #pragma unroll
        for (int off = 1; off < 1024; off <<= 1) {
            int add = (t >= off) ? sh[t - off] : 0;
            __syncthreads();
            sh[t] += add;
            __syncthreads();
        }
        int excl = sh[t] - v;
        int c0 = carry;
        if (base + t < N_NODES) { g_off[base + t] = c0 + excl; g_cur[base + t] = c0 + excl; }
        __syncthreads();
        if (t == 0) carry = c0 + sh[1023];
        __syncthreads();
    }
}
__global__ void k_scatter(const void* edges) {
    int i = blockIdx.x * blockDim.x + threadIdx.x;
    if (i < N_EDGES) {
        int src = load_edge(edges, i);
        int dst = load_edge(edges, N_EDGES + i);
        g_csr[atomicAdd(&g_cur[dst], 1)] = src;
    }
}

// ---------------- layer-1 aggregation: fp32 x -> fp16 hi/lo ----------------
__global__ void k_agg1(const float* __restrict__ X,
                       __half* __restrict__ OH, __half* __restrict__ OL) {
    int node = blockIdx.x;
    int t = threadIdx.x;                 // 128, 2 floats each
    float a0 = 0.f, a1 = 0.f;
    int start = g_off[node];
    int deg = g_deg[node];
    for (int i = 0; i < deg; i++) {
        const float2 v = *(const float2*)(X + (size_t)g_csr[start + i] * F_IN + t * 2);
        a0 += v.x; a1 += v.y;
    }
    float inv = (deg > 0) ? (1.0f / (float)deg) : 0.0f;
    a0 *= inv; a1 *= inv;
    __half h0 = __float2half_rn(a0), h1 = __float2half_rn(a1);
    size_t o = (size_t)node * F_IN + t * 2;
    *(__half2*)(OH + o) = __halves2half2(h0, h1);
    *(__half2*)(OL + o) = __halves2half2(
        __float2half_rn(a0 - __half2float(h0)),
        __float2half_rn(a1 - __half2float(h1)));
}

// ---------------- layer-2 aggregation: fp16 hi/lo -> fp16 hi/lo ------------
__global__ void k_agg2(const __half* __restrict__ XH, const __half* __restrict__ XL,
                       __half* __restrict__ OH, __half* __restrict__ OL) {
    int node = blockIdx.x;
    int t = threadIdx.x;                 // 128, 8 elems each
    float acc[8];
    #pragma unroll
    for (int j = 0; j < 8; j++) acc[j] = 0.f;
    int start = g_off[node];
    int deg = g_deg[node];
    for (int i = 0; i < deg; i++) {
        size_t ro = (size_t)g_csr[start + i] * HID + t * 8;
        union { uint4 u; __half b[8]; } uh, ul;
        uh.u = *(const uint4*)(XH + ro);
        ul.u = *(const uint4*)(XL + ro);
        #pragma unroll
        for (int j = 0; j < 8; j++)
            acc[j] += __half2float(uh.b[j]) + __half2float(ul.b[j]);
    }
    float inv = (deg > 0) ? (1.0f / (float)deg) : 0.0f;
    union { uint4 u; __half b[8]; } oh, ol;
    #pragma unroll
    for (int j = 0; j < 8; j++) {
        float v = acc[j] * inv;
        __half h = __float2half_rn(v);
        oh.b[j] = h;
        ol.b[j] = __float2half_rn(v - __half2float(h));
    }
    size_t o = (size_t)node * HID + t * 8;
    *(uint4*)(OH + o) = oh.u;
    *(uint4*)(OL + o) = ol.u;
}

// ---------------- fp32 -> fp16 hi/lo split ----------------
__global__ void k_split(const float* __restrict__ X, __half* __restrict__ H,
                        __half* __restrict__ L, size_t n) {
    size_t i = (size_t)blockIdx.x * blockDim.x + threadIdx.x;
    if (i < n) {
        float v = X[i];
        __half h = __float2half_rn(v);
        H[i] = h;
        L[i] = __float2half_rn(v - __half2float(h));
    }
}

// ---------------- weight transpose: W[K,N] -> T[N,K] fp16 ----------------
__global__ void k_wt(const float* __restrict__ W, __half* __restrict__ T, int K, int N) {
    __shared__ float t[32][33];
    int kb = blockIdx.x * 32, nb = blockIdx.y * 32;
    int tx = threadIdx.x, ty = threadIdx.y;  // 32 x 8
    #pragma unroll
    for (int i = 0; i < 32; i += 8)
        t[ty + i][tx] = W[(size_t)(kb + ty + i) * N + nb + tx];
    __syncthreads();
    #pragma unroll
    for (int i = 0; i < 32; i += 8)
        T[(size_t)(nb + ty + i) * K + kb + tx] = __float2half_rn(t[tx][ty + i]);
}

// ---------------- fp16 mma.sync GEMM ----------------
// C[M,N] = sum_p A_p[M,Kp] @ B_p[N,Kp]^T + bias (+ReLU) (+fused column stats)
// CTA tile 128x128, warp tile 32x64 (4x2 warps), BK=64,
// 3-stage cp.async, 2 CTAs/SM — best measured config (R9).
struct GemmParams {
    const __half* A[6];
    const __half* B[6];
    int Kw[6];
    int chEnd[6];
    int totalChunks;
    const float* bias;
    float* C;
    int M;
    int Ncols;
    int relu;
    int stats;
};

#define STAGES 3
#define STAGE_BYTES 32768              // 16KB A + 16KB B
#define SMEM_REQ (1024 + STAGES * STAGE_BYTES)

__device__ __forceinline__ uint32_t swz(uint32_t o) { return o ^ ((o >> 3) & 0x70); }

__device__ __forceinline__ void cp16(uint32_t dst, const void* src, bool p) {
    int sz = p ? 16 : 0;
    asm volatile("cp.async.cg.shared.global [%0], [%1], 16, %2;\n"
                 :: "r"(dst), "l"(src), "r"(sz));
}

__global__ __launch_bounds__(256, 2) void k_gemm(const __grid_constant__ GemmParams P) {
    extern __shared__ char dsm[];
    uint32_t raw;
    asm("{ .reg .u64 t; cvta.to.shared.u64 t, %1; cvt.u32.u64 %0, t; }" : "=r"(raw) : "l"(dsm));
    uint32_t tiles = (raw + 1023) & ~1023u;
    int tid = threadIdx.x;
    int wid = tid >> 5;
    int lane = tid & 31;
    int mBase = blockIdx.x * 128;
    int nBase = blockIdx.y * 128;
    int mw = wid >> 1;     // 0..3
    int nw = wid & 1;      // 0..1

    auto load_chunk = [&](int c, int s) {
        int p = 0;
        while (c >= P.chEnd[p]) p++;
        int c0 = (p ? c - P.chEnd[p - 1] : c) * 64;
        const char* Ab = (const char*)P.A[p] + (size_t)c0 * 2;
        const char* Bb = (const char*)P.B[p] + (size_t)c0 * 2;
        size_t rowB = (size_t)P.Kw[p] * 2;
        uint32_t stA = tiles + s * STAGE_BYTES;
        uint32_t stB = stA + 16384;
        #pragma unroll
        for (int i = 0; i < 4; i++) {
            int o = tid + i * 256;
            int row = o >> 3, kb = (o & 7) * 16;
            bool ok = (mBase + row) < P.M;
            cp16(stA + swz(row * 128 + kb), Ab + (size_t)(mBase + row) * rowB + kb, ok);
        }
        #pragma unroll
        for (int i = 0; i < 4; i++) {
            int o = tid + i * 256;
            int row = o >> 3, kb = (o & 7) * 16;
            cp16(stB + swz(row * 128 + kb), Bb + (size_t)(nBase + row) * rowB + kb, true);
        }
        asm volatile("cp.async.commit_group;" ::: "memory");
    };

    const int T = P.totalChunks;

    float acc[2][8][4];
    #pragma unroll
    for (int mi = 0; mi < 2; mi++)
        #pragma unroll
        for (int n8 = 0; n8 < 8; n8++)
            #pragma unroll
            for (int q = 0; q < 4; q++) acc[mi][n8][q] = 0.0f;

    int npre = (T < 2) ? T : 2;
    for (int c = 0; c < npre; c++) load_chunk(c, c);

    for (int c = 0; c < T; c++) {
        int s = c % 3;
        if (c == T - 1) asm volatile("cp.async.wait_group 0;" ::: "memory");
        else            asm volatile("cp.async.wait_group 1;" ::: "memory");
        __syncthreads();

        uint32_t stA = tiles + s * STAGE_BYTES;
        uint32_t stB = stA + 16384;
        #pragma unroll
        for (int ks = 0; ks < 4; ks++) {
            uint32_t a[2][4];
            uint32_t arow = mw * 32 + ((lane >> 3) & 1) * 8 + (lane & 7);
            uint32_t akb  = ks * 32 + (lane >> 4) * 16;
            #pragma unroll
            for (int mi = 0; mi < 2; mi++) {
                uint32_t ad = stA + swz((arow + mi * 16) * 128 + akb);
                asm volatile("ldmatrix.sync.aligned.m8n8.x4.shared.b16 {%0,%1,%2,%3}, [%4];"
                             : "=r"(a[mi][0]), "=r"(a[mi][1]), "=r"(a[mi][2]), "=r"(a[mi][3])
                             : "r"(ad));
            }
            uint32_t b[4][4];
            uint32_t brow = nw * 64 + ((lane >> 4) & 1) * 8 + (lane & 7);
            uint32_t bkb  = ks * 32 + ((lane >> 3) & 1) * 16;
            #pragma unroll
            for (int ni = 0; ni < 4; ni++) {
                uint32_t bd = stB + swz((brow + ni * 16) * 128 + bkb);
                asm volatile("ldmatrix.sync.aligned.m8n8.x4.shared.b16 {%0,%1,%2,%3}, [%4];"
                             : "=r"(b[ni][0]), "=r"(b[ni][1]), "=r"(b[ni][2]), "=r"(b[ni][3])
                             : "r"(bd));
            }
            #pragma unroll
            for (int mi = 0; mi < 2; mi++)
                #pragma unroll
                for (int n8 = 0; n8 < 8; n8++) {
                    uint32_t b0 = b[n8 >> 1][(n8 & 1) * 2 + 0];
                    uint32_t b1 = b[n8 >> 1][(n8 & 1) * 2 + 1];
                    asm volatile(
                        "mma.sync.aligned.m16n8k16.row.col.f32.f16.f16.f32 "
                        "{%0,%1,%2,%3}, {%4,%5,%6,%7}, {%8,%9}, {%0,%1,%2,%3};"
                        : "+f"(acc[mi][n8][0]), "+f"(acc[mi][n8][1]),
                          "+f"(acc[mi][n8][2]), "+f"(acc[mi][n8][3])
                        : "r"(a[mi][0]), "r"(a[mi][1]), "r"(a[mi][2]), "r"(a[mi][3]),
                          "r"(b0), "r"(b1));
                }
        }
        if (c + 2 < T) load_chunk(c + 2, (c + 2) % 3);
    }

    // epilogue: bias (+ReLU) store + fused column stats
    {
        int g = lane >> 2, t4 = lane & 3;
        #pragma unroll
        for (int n8 = 0; n8 < 8; n8++) {
            int col = nBase + nw * 64 + n8 * 8 + t4 * 2;
            float bx = P.bias[col], by = P.bias[col + 1];
            float s0 = 0.f, s1 = 0.f, q0 = 0.f, q1 = 0.f;
            #pragma unroll
            for (int mi = 0; mi < 2; mi++) {
                int r0 = mBase + mw * 32 + mi * 16 + g;
                float2 v;
                v.x = acc[mi][n8][0] + bx;
                v.y = acc[mi][n8][1] + by;
                if (P.relu) { v.x = fmaxf(v.x, 0.f); v.y = fmaxf(v.y, 0.f); }
                if (r0 < P.M) {
                    *(float2*)(P.C + (size_t)r0 * P.Ncols + col) = v;
                    s0 += v.x; s1 += v.y; q0 += v.x * v.x; q1 += v.y * v.y;
                }
                int r1 = r0 + 8;
                float2 w;
                w.x = acc[mi][n8][2] + bx;
                w.y = acc[mi][n8][3] + by;
                if (P.relu) { w.x = fmaxf(w.x, 0.f); w.y = fmaxf(w.y, 0.f); }
                if (r1 < P.M) {
                    *(float2*)(P.C + (size_t)r1 * P.Ncols + col) = w;
                    s0 += w.x; s1 += w.y; q0 += w.x * w.x; q1 += w.y * w.y;
                }
            }
            if (P.stats) {
                #pragma unroll
                for (int o = 4; o <= 16; o <<= 1) {
                    s0 += __shfl_xor_sync(0xffffffffu, s0, o);
                    s1 += __shfl_xor_sync(0xffffffffu, s1, o);
                    q0 += __shfl_xor_sync(0xffffffffu, q0, o);
                    q1 += __shfl_xor_sync(0xffffffffu, q1, o);
                }
                if (g == 0) {
                    atomicAdd(&g_sum[col], s0);
                    atomicAdd(&g_sum[col + 1], s1);
                    atomicAdd(&g_sumsq[col], q0);
                    atomicAdd(&g_sumsq[col + 1], q1);
                }
            }
        }
    }
}

// ---------------- BN params / apply ----------------
__global__ void k_bnparams(const float* __restrict__ g, const float* __restrict__ be) {
    int c = blockIdx.x * blockDim.x + threadIdx.x;
    if (c < HID) {
        float m = g_sum[c] * (1.0f / N_NODES);
        float var = g_sumsq[c] * (1.0f / N_NODES) - m * m;
        float a = g[c] * rsqrtf(var + EPS_BN);
        g_a[c] = a;
        g_c[c] = be[c] - m * a;
    }
}
__global__ void k_bnrelu(const float* __restrict__ X,
                         __half* __restrict__ YH, __half* __restrict__ YL) {
    size_t i = (size_t)blockIdx.x * blockDim.x + threadIdx.x;  // float4 index
    const size_t total = (size_t)N_NODES * HID / 4;
    if (i < total) {
        int c = (int)((i * 4) % HID);
        float4 v = ((const float4*)X)[i];
        v.x = fmaxf(0.f, v.x * g_a[c + 0] + g_c[c + 0]);
        v.y = fmaxf(0.f, v.y * g_a[c + 1] + g_c[c + 1]);
        v.z = fmaxf(0.f, v.z * g_a[c + 2] + g_c[c + 2]);
        v.w = fmaxf(0.f, v.w * g_a[c + 3] + g_c[c + 3]);
        __half hx = __float2half_rn(v.x), hy = __float2half_rn(v.y);
        __half hz = __float2half_rn(v.z), hw = __float2half_rn(v.w);
        __half2* H2 = (__half2*)YH;
        __half2* L2 = (__half2*)YL;
        H2[i * 2 + 0] = __halves2half2(hx, hy);
        H2[i * 2 + 1] = __halves2half2(hz, hw);
        L2[i * 2 + 0] = __halves2half2(__float2half_rn(v.x - __half2float(hx)),
                                       __float2half_rn(v.y - __half2float(hy)));
        L2[i * 2 + 1] = __halves2half2(__float2half_rn(v.z - __half2float(hz)),
                                       __float2half_rn(v.w - __half2float(hw)));
    }
}

// ---------------- final head ----------------
__global__ void k_out(const float* __restrict__ H, const float* __restrict__ Wo,
                      const float* __restrict__ bo, float* __restrict__ Out) {
    __shared__ float sw[F_MID * N_OUT];
    for (int i = threadIdx.x; i < F_MID * N_OUT; i += blockDim.x) sw[i] = Wo[i];
    __syncthreads();
    int warp = threadIdx.x / 32, lane = threadIdx.x % 32;
    int row = blockIdx.x * (blockDim.x / 32) + warp;
    if (row >= N_NODES) return;
    float acc[N_OUT];
    #pragma unroll
    for (int o = 0; o < N_OUT; o++) acc[o] = 0.0f;
    const float* h = H + (size_t)row * F_MID;
    for (int k = lane; k < F_MID; k += 32) {
        float hv = h[k];
        #pragma unroll
        for (int o = 0; o < N_OUT; o++) acc[o] += hv * sw[k * N_OUT + o];
    }
    #pragma unroll
    for (int o = 0; o < N_OUT; o++)
        #pragma unroll
        for (int off = 16; off; off >>= 1)
            acc[o] += __shfl_down_sync(0xffffffffu, acc[o], off);
    if (lane == 0)
        #pragma unroll
        for (int o = 0; o < N_OUT; o++)
            Out[(size_t)row * N_OUT + o] = acc[o] + bo[o];
}

// ---------------- host-side GEMM launcher ----------------
struct PassDef { const __half* A; const __half* B; int Kw; };
static void run_gemm(const PassDef* passes, int np, const float* bias, float* C,
                     int M, int N, int relu, int stats) {
    GemmParams P = {};
    int cum = 0;
    for (int i = 0; i < np; i++) {
        P.A[i] = passes[i].A;
        P.B[i] = passes[i].B;
        P.Kw[i] = passes[i].Kw;
        cum += passes[i].Kw / 64;
        P.chEnd[i] = cum;
    }
    P.totalChunks = cum;
    P.bias = bias; P.C = C; P.M = M; P.Ncols = N; P.relu = relu; P.stats = stats;
    dim3 g((M + 127) / 128, N / 128);
    k_gemm<<<g, 256, SMEM_REQ>>>(P);
}

// ---------------- launch ----------------
extern "C" void kernel_launch(void* const* d_in, const int* in_sizes, int n_in,
                              void* d_out, int out_size) {
    const float* x   = (const float*)d_in[0];
    const void*  edges = d_in[1];
    const float* W1l = (const float*)d_in[2];
    const float* b1  = (const float*)d_in[3];
    const float* W1r = (const float*)d_in[4];
    const float* g1  = (const float*)d_in[5];
    const float* be1 = (const float*)d_in[6];
    const float* W2l = (const float*)d_in[7];
    const float* b2  = (const float*)d_in[8];
    const float* W2r = (const float*)d_in[9];
    const float* g2  = (const float*)d_in[10];
    const float* be2 = (const float*)d_in[11];
    const float* Wf  = (const float*)d_in[12];
    const float* bf  = (const float*)d_in[13];
    const float* Wo  = (const float*)d_in[14];
    const float* bo  = (const float*)d_in[15];
    float* out = (float*)d_out;

    cudaFuncSetAttribute(k_gemm, cudaFuncAttributeMaxDynamicSharedMemorySize, SMEM_REQ);

    void *p_deg, *p_sum, *p_sumsq, *p_tmp, *p_Ah, *p_Al, *p_Bh, *p_Bl, *p_W;
    cudaGetSymbolAddress(&p_deg, g_deg);
    cudaGetSymbolAddress(&p_sum, g_sum);
    cudaGetSymbolAddress(&p_sumsq, g_sumsq);
    cudaGetSymbolAddress(&p_tmp, g_tmp);
    cudaGetSymbolAddress(&p_Ah, g_Ah);
    cudaGetSymbolAddress(&p_Al, g_Al);
    cudaGetSymbolAddress(&p_Bh, g_Bh);
    cudaGetSymbolAddress(&p_Bl, g_Bl);
    cudaGetSymbolAddress(&p_W, g_W16);
    float* tmp = (float*)p_tmp;
    __half* Ah = (__half*)p_Ah;
    __half* Al = (__half*)p_Al;
    __half* Bh = (__half*)p_Bh;
    __half* Bl = (__half*)p_Bl;
    __half* W16 = (__half*)p_W;

    // CSR build
    cudaMemsetAsync(p_deg, 0, N_NODES * sizeof(int));
    k_detect<<<1, 32>>>((const unsigned int*)edges);
    k_hist<<<(N_EDGES + 255) / 256, 256>>>(edges);
    k_scan<<<1, 1024>>>();
    k_scatter<<<(N_EDGES + 255) / 256, 256>>>(edges);

    // weight transpose (fp16, single array)
    dim3 wb(32, 8);
    k_wt<<<dim3(F_IN / 32, HID / 32), wb>>>(W1l, W16 + OFF_W1L, F_IN, HID);
    k_wt<<<dim3(F_IN / 32, HID / 32), wb>>>(W1r, W16 + OFF_W1R, F_IN, HID);
    k_wt<<<dim3(HID / 32, HID / 32), wb>>>(W2l, W16 + OFF_W2L, HID, HID);
    k_wt<<<dim3(HID / 32, HID / 32), wb>>>(W2r, W16 + OFF_W2R, HID, HID);
    k_wt<<<dim3(HID / 32, F_MID / 32), wb>>>(Wf, W16 + OFF_WF, HID, F_MID);

    // x split
    {
        size_t n = (size_t)N_NODES * F_IN;
        k_split<<<(unsigned)((n + 255) / 256), 256>>>(x, Bh, Bl, n);
    }

    // ---- layer 1 ----
    k_agg1<<<N_NODES, 128>>>(x, Ah, Al);
    cudaMemsetAsync(p_sum, 0, HID * sizeof(float));
    cudaMemsetAsync(p_sumsq, 0, HID * sizeof(float));
    {
        PassDef pl[4] = {
            {Ah, W16 + OFF_W1L, F_IN}, {Al, W16 + OFF_W1L, F_IN},
            {Bh, W16 + OFF_W1R, F_IN}, {Bl, W16 + OFF_W1R, F_IN},
        };
        run_gemm(pl, 4, b1, tmp, N_NODES, HID, 0, 1);
    }
    k_bnparams<<<HID / 256, 256>>>(g1, be1);
    {
        size_t n4 = (size_t)N_NODES * HID / 4;
        k_bnrelu<<<(unsigned)((n4 + 255) / 256), 256>>>(tmp, Bh, Bl);
    }

    // ---- layer 2 ----
    k_agg2<<<N_NODES, 128>>>(Bh, Bl, Ah, Al);
    cudaMemsetAsync(p_sum, 0, HID * sizeof(float));
    cudaMemsetAsync(p_sumsq, 0, HID * sizeof(float));
    {
        PassDef pl[4] = {
            {Ah, W16 + OFF_W2L, HID}, {Al, W16 + OFF_W2L, HID},
            {Bh, W16 + OFF_W2R, HID}, {Bl, W16 + OFF_W2R, HID},
        };
        run_gemm(pl, 4, b2, tmp, N_NODES, HID, 0, 1);
    }
    k_bnparams<<<HID / 256, 256>>>(g2, be2);
    {
        size_t n4 = (size_t)N_NODES * HID / 4;
        k_bnrelu<<<(unsigned)((n4 + 255) / 256), 256>>>(tmp, Bh, Bl);
    }

    // ---- fc + ReLU ----
    {
        PassDef pl[2] = {
            {Bh, W16 + OFF_WF, HID}, {Bl, W16 + OFF_WF, HID},
        };
        run_gemm(pl, 2, bf, tmp, N_NODES, F_MID, 1, 0);
    }

    // ---- head ----
    k_out<<<(N_NODES + 7) / 8, 256>>>(tmp, Wo, bo, out);
}

// round 11
// speedup vs baseline: 2.1008x; 1.1869x over previous
#include <cuda_runtime.h>
#include <cuda_fp16.h>
#include <cstdint>

#define N_NODES 50000
#define N_EDGES 400000
#define F_IN    256
#define HID     1024
#define F_MID   512
#define N_OUT   10
#define EPS_BN  1e-5f

// ---------------- scratch (device globals) ----------------
__device__ float g_tmp[(size_t)N_NODES * HID];
__device__ __half g_Ah[(size_t)N_NODES * HID];   // aggregate hi
__device__ __half g_Al[(size_t)N_NODES * HID];   // aggregate lo (layer 1 only)
__device__ __half g_Bh[(size_t)N_NODES * HID];   // x / h hi
__device__ __half g_Bl[(size_t)N_NODES * HID];   // x / h lo
#define OFF_W1L 0
#define OFF_W1R 262144
#define OFF_W2L 524288
#define OFF_W2R 1572864
#define OFF_WF  2621440
__device__ __half g_W16[3145728];                // fp16 weights (transposed)

__device__ int   g_deg[N_NODES];
__device__ int   g_off[N_NODES];
__device__ int   g_cur[N_NODES];
__device__ int   g_csr[N_EDGES];
__device__ float g_sum[HID];
__device__ float g_sumsq[HID];
__device__ float g_a[HID];
__device__ float g_c[HID];
__device__ int   g_is64;

// ---------------- dtype detection ----------------
__global__ void k_detect(const unsigned int* e) {
    if (threadIdx.x == 0) {
        int is64 = 1;
        for (int i = 0; i < 64; i++)
            if (e[2 * i + 1] != 0u) { is64 = 0; break; }
        g_is64 = is64;
    }
}
__device__ __forceinline__ int load_edge(const void* edges, int idx) {
    if (g_is64) return (int)((const long long*)edges)[idx];
    return ((const int*)edges)[idx];
}

// ---------------- CSR build ----------------
__global__ void k_hist(const void* edges) {
    int i = blockIdx.x * blockDim.x + threadIdx.x;
    if (i < N_EDGES) atomicAdd(&g_deg[load_edge(edges, N_EDGES + i)], 1);
}
__global__ void k_scan() {
    __shared__ int sh[1024];
    __shared__ int carry;
    int t = threadIdx.x;
    if (t == 0) carry = 0;
    __syncthreads();
    for (int base = 0; base < N_NODES; base += 1024) {
        int v = (base + t < N_NODES) ? g_deg[base + t] : 0;
        sh[t] = v;
        __syncthreads();
        #pragma unroll
        for (int off = 1; off < 1024; off <<= 1) {
            int add = (t >= off) ? sh[t - off] : 0;
            __syncthreads();
            sh[t] += add;
            __syncthreads();
        }
        int excl = sh[t] - v;
        int c0 = carry;
        if (base + t < N_NODES) { g_off[base + t] = c0 + excl; g_cur[base + t] = c0 + excl; }
        __syncthreads();
        if (t == 0) carry = c0 + sh[1023];
        __syncthreads();
    }
}
__global__ void k_scatter(const void* edges) {
    int i = blockIdx.x * blockDim.x + threadIdx.x;
    if (i < N_EDGES) {
        int src = load_edge(edges, i);
        int dst = load_edge(edges, N_EDGES + i);
        g_csr[atomicAdd(&g_cur[dst], 1)] = src;
    }
}

// ---------------- layer-1 aggregation: fp32 x -> fp16 hi/lo ----------------
__global__ void k_agg1(const float* __restrict__ X,
                       __half* __restrict__ OH, __half* __restrict__ OL) {
    int node = blockIdx.x;
    int t = threadIdx.x;                 // 128, 2 floats each
    float a0 = 0.f, a1 = 0.f;
    int start = g_off[node];
    int deg = g_deg[node];
    for (int i = 0; i < deg; i++) {
        const float2 v = *(const float2*)(X + (size_t)g_csr[start + i] * F_IN + t * 2);
        a0 += v.x; a1 += v.y;
    }
    float inv = (deg > 0) ? (1.0f / (float)deg) : 0.0f;
    a0 *= inv; a1 *= inv;
    __half h0 = __float2half_rn(a0), h1 = __float2half_rn(a1);
    size_t o = (size_t)node * F_IN + t * 2;
    *(__half2*)(OH + o) = __halves2half2(h0, h1);
    *(__half2*)(OL + o) = __halves2half2(
        __float2half_rn(a0 - __half2float(h0)),
        __float2half_rn(a1 - __half2float(h1)));
}

// ---------------- layer-2 aggregation: fp16 hi -> fp16 hi (pure fp16 path) -
__global__ void k_agg2(const __half* __restrict__ XH, __half* __restrict__ OH) {
    int node = blockIdx.x;
    int t = threadIdx.x;                 // 128, 8 elems each
    float acc[8];
    #pragma unroll
    for (int j = 0; j < 8; j++) acc[j] = 0.f;
    int start = g_off[node];
    int deg = g_deg[node];
    for (int i = 0; i < deg; i++) {
        size_t ro = (size_t)g_csr[start + i] * HID + t * 8;
        union { uint4 u; __half b[8]; } uh;
        uh.u = *(const uint4*)(XH + ro);
        #pragma unroll
        for (int j = 0; j < 8; j++)
            acc[j] += __half2float(uh.b[j]);
    }
    float inv = (deg > 0) ? (1.0f / (float)deg) : 0.0f;
    union { uint4 u; __half b[8]; } oh;
    #pragma unroll
    for (int j = 0; j < 8; j++)
        oh.b[j] = __float2half_rn(acc[j] * inv);
    *(uint4*)(OH + (size_t)node * HID + t * 8) = oh.u;
}

// ---------------- fp32 -> fp16 hi/lo split ----------------
__global__ void k_split(const float* __restrict__ X, __half* __restrict__ H,
                        __half* __restrict__ L, size_t n) {
    size_t i = (size_t)blockIdx.x * blockDim.x + threadIdx.x;
    if (i < n) {
        float v = X[i];
        __half h = __float2half_rn(v);
        H[i] = h;
        L[i] = __float2half_rn(v - __half2float(h));
    }
}

// ---------------- weight transpose: W[K,N] -> T[N,K] fp16 ----------------
__global__ void k_wt(const float* __restrict__ W, __half* __restrict__ T, int K, int N) {
    __shared__ float t[32][33];
    int kb = blockIdx.x * 32, nb = blockIdx.y * 32;
    int tx = threadIdx.x, ty = threadIdx.y;  // 32 x 8
    #pragma unroll
    for (int i = 0; i < 32; i += 8)
        t[ty + i][tx] = W[(size_t)(kb + ty + i) * N + nb + tx];
    __syncthreads();
    #pragma unroll
    for (int i = 0; i < 32; i += 8)
        T[(size_t)(nb + ty + i) * K + kb + tx] = __float2half_rn(t[tx][ty + i]);
}

// ---------------- fp16 mma.sync GEMM ----------------
// C[M,N] = sum_p A_p[M,Kp] @ B_p[N,Kp]^T + bias (+ReLU) (+fused column stats)
// CTA tile 128x128, warp tile 32x64 (4x2 warps), BK=64,
// 3-stage cp.async, 2 CTAs/SM — best measured config.
struct GemmParams {
    const __half* A[6];
    const __half* B[6];
    int Kw[6];
    int chEnd[6];
    int totalChunks;
    const float* bias;
    float* C;
    int M;
    int Ncols;
    int relu;
    int stats;
};

#define STAGES 3
#define STAGE_BYTES 32768              // 16KB A + 16KB B
#define SMEM_REQ (1024 + STAGES * STAGE_BYTES)

__device__ __forceinline__ uint32_t swz(uint32_t o) { return o ^ ((o >> 3) & 0x70); }

__device__ __forceinline__ void cp16(uint32_t dst, const void* src, bool p) {
    int sz = p ? 16 : 0;
    asm volatile("cp.async.cg.shared.global [%0], [%1], 16, %2;\n"
                 :: "r"(dst), "l"(src), "r"(sz));
}

__global__ __launch_bounds__(256, 2) void k_gemm(const __grid_constant__ GemmParams P) {
    extern __shared__ char dsm[];
    uint32_t raw;
    asm("{ .reg .u64 t; cvta.to.shared.u64 t, %1; cvt.u32.u64 %0, t; }" : "=r"(raw) : "l"(dsm));
    uint32_t tiles = (raw + 1023) & ~1023u;
    int tid = threadIdx.x;
    int wid = tid >> 5;
    int lane = tid & 31;
    int mBase = blockIdx.x * 128;
    int nBase = blockIdx.y * 128;
    int mw = wid >> 1;     // 0..3
    int nw = wid & 1;      // 0..1

    auto load_chunk = [&](int c, int s) {
        int p = 0;
        while (c >= P.chEnd[p]) p++;
        int c0 = (p ? c - P.chEnd[p - 1] : c) * 64;
        const char* Ab = (const char*)P.A[p] + (size_t)c0 * 2;
        const char* Bb = (const char*)P.B[p] + (size_t)c0 * 2;
        size_t rowB = (size_t)P.Kw[p] * 2;
        uint32_t stA = tiles + s * STAGE_BYTES;
        uint32_t stB = stA + 16384;
        #pragma unroll
        for (int i = 0; i < 4; i++) {
            int o = tid + i * 256;
            int row = o >> 3, kb = (o & 7) * 16;
            bool ok = (mBase + row) < P.M;
            cp16(stA + swz(row * 128 + kb), Ab + (size_t)(mBase + row) * rowB + kb, ok);
        }
        #pragma unroll
        for (int i = 0; i < 4; i++) {
            int o = tid + i * 256;
            int row = o >> 3, kb = (o & 7) * 16;
            cp16(stB + swz(row * 128 + kb), Bb + (size_t)(nBase + row) * rowB + kb, true);
        }
        asm volatile("cp.async.commit_group;" ::: "memory");
    };

    const int T = P.totalChunks;

    float acc[2][8][4];
    #pragma unroll
    for (int mi = 0; mi < 2; mi++)
        #pragma unroll
        for (int n8 = 0; n8 < 8; n8++)
            #pragma unroll
            for (int q = 0; q < 4; q++) acc[mi][n8][q] = 0.0f;

    int npre = (T < 2) ? T : 2;
    for (int c = 0; c < npre; c++) load_chunk(c, c);

    for (int c = 0; c < T; c++) {
        int s = c % 3;
        if (c == T - 1) asm volatile("cp.async.wait_group 0;" ::: "memory");
        else            asm volatile("cp.async.wait_group 1;" ::: "memory");
        __syncthreads();

        uint32_t stA = tiles + s * STAGE_BYTES;
        uint32_t stB = stA + 16384;
        #pragma unroll
        for (int ks = 0; ks < 4; ks++) {
            uint32_t a[2][4];
            uint32_t arow = mw * 32 + ((lane >> 3) & 1) * 8 + (lane & 7);
            uint32_t akb  = ks * 32 + (lane >> 4) * 16;
            #pragma unroll
            for (int mi = 0; mi < 2; mi++) {
                uint32_t ad = stA + swz((arow + mi * 16) * 128 + akb);
                asm volatile("ldmatrix.sync.aligned.m8n8.x4.shared.b16 {%0,%1,%2,%3}, [%4];"
                             : "=r"(a[mi][0]), "=r"(a[mi][1]), "=r"(a[mi][2]), "=r"(a[mi][3])
                             : "r"(ad));
            }
            uint32_t b[4][4];
            uint32_t brow = nw * 64 + ((lane >> 4) & 1) * 8 + (lane & 7);
            uint32_t bkb  = ks * 32 + ((lane >> 3) & 1) * 16;
            #pragma unroll
            for (int ni = 0; ni < 4; ni++) {
                uint32_t bd = stB + swz((brow + ni * 16) * 128 + bkb);
                asm volatile("ldmatrix.sync.aligned.m8n8.x4.shared.b16 {%0,%1,%2,%3}, [%4];"
                             : "=r"(b[ni][0]), "=r"(b[ni][1]), "=r"(b[ni][2]), "=r"(b[ni][3])
                             : "r"(bd));
            }
            #pragma unroll
            for (int mi = 0; mi < 2; mi++)
                #pragma unroll
                for (int n8 = 0; n8 < 8; n8++) {
                    uint32_t b0 = b[n8 >> 1][(n8 & 1) * 2 + 0];
                    uint32_t b1 = b[n8 >> 1][(n8 & 1) * 2 + 1];
                    asm volatile(
                        "mma.sync.aligned.m16n8k16.row.col.f32.f16.f16.f32 "
                        "{%0,%1,%2,%3}, {%4,%5,%6,%7}, {%8,%9}, {%0,%1,%2,%3};"
                        : "+f"(acc[mi][n8][0]), "+f"(acc[mi][n8][1]),
                          "+f"(acc[mi][n8][2]), "+f"(acc[mi][n8][3])
                        : "r"(a[mi][0]), "r"(a[mi][1]), "r"(a[mi][2]), "r"(a[mi][3]),
                          "r"(b0), "r"(b1));
                }
        }
        if (c + 2 < T) load_chunk(c + 2, (c + 2) % 3);
    }

    // epilogue: bias (+ReLU) store + fused column stats
    {
        int g = lane >> 2, t4 = lane & 3;
        #pragma unroll
        for (int n8 = 0; n8 < 8; n8++) {
            int col = nBase + nw * 64 + n8 * 8 + t4 * 2;
            float bx = P.bias[col], by = P.bias[col + 1];
            float s0 = 0.f, s1 = 0.f, q0 = 0.f, q1 = 0.f;
            #pragma unroll
            for (int mi = 0; mi < 2; mi++) {
                int r0 = mBase + mw * 32 + mi * 16 + g;
                float2 v;
                v.x = acc[mi][n8][0] + bx;
                v.y = acc[mi][n8][1] + by;
                if (P.relu) { v.x = fmaxf(v.x, 0.f); v.y = fmaxf(v.y, 0.f); }
                if (r0 < P.M) {
                    *(float2*)(P.C + (size_t)r0 * P.Ncols + col) = v;
                    s0 += v.x; s1 += v.y; q0 += v.x * v.x; q1 += v.y * v.y;
                }
                int r1 = r0 + 8;
                float2 w;
                w.x = acc[mi][n8][2] + bx;
                w.y = acc[mi][n8][3] + by;
                if (P.relu) { w.x = fmaxf(w.x, 0.f); w.y = fmaxf(w.y, 0.f); }
                if (r1 < P.M) {
                    *(float2*)(P.C + (size_t)r1 * P.Ncols + col) = w;
                    s0 += w.x; s1 += w.y; q0 += w.x * w.x; q1 += w.y * w.y;
                }
            }
            if (P.stats) {
                #pragma unroll
                for (int o = 4; o <= 16; o <<= 1) {
                    s0 += __shfl_xor_sync(0xffffffffu, s0, o);
                    s1 += __shfl_xor_sync(0xffffffffu, s1, o);
                    q0 += __shfl_xor_sync(0xffffffffu, q0, o);
                    q1 += __shfl_xor_sync(0xffffffffu, q1, o);
                }
                if (g == 0) {
                    atomicAdd(&g_sum[col], s0);
                    atomicAdd(&g_sum[col + 1], s1);
                    atomicAdd(&g_sumsq[col], q0);
                    atomicAdd(&g_sumsq[col + 1], q1);
                }
            }
        }
    }
}

// ---------------- BN params / apply ----------------
__global__ void k_bnparams(const float* __restrict__ g, const float* __restrict__ be) {
    int c = blockIdx.x * blockDim.x + threadIdx.x;
    if (c < HID) {
        float m = g_sum[c] * (1.0f / N_NODES);
        float var = g_sumsq[c] * (1.0f / N_NODES) - m * m;
        float a = g[c] * rsqrtf(var + EPS_BN);
        g_a[c] = a;
        g_c[c] = be[c] - m * a;
    }
}
__global__ void k_bnrelu(const float* __restrict__ X,
                         __half* __restrict__ YH, __half* __restrict__ YL) {
    size_t i = (size_t)blockIdx.x * blockDim.x + threadIdx.x;  // float4 index
    const size_t total = (size_t)N_NODES * HID / 4;
    if (i < total) {
        int c = (int)((i * 4) % HID);
        float4 v = ((const float4*)X)[i];
        v.x = fmaxf(0.f, v.x * g_a[c + 0] + g_c[c + 0]);
        v.y = fmaxf(0.f, v.y * g_a[c + 1] + g_c[c + 1]);
        v.z = fmaxf(0.f, v.z * g_a[c + 2] + g_c[c + 2]);
        v.w = fmaxf(0.f, v.w * g_a[c + 3] + g_c[c + 3]);
        __half hx = __float2half_rn(v.x), hy = __float2half_rn(v.y);
        __half hz = __float2half_rn(v.z), hw = __float2half_rn(v.w);
        __half2* H2 = (__half2*)YH;
        __half2* L2 = (__half2*)YL;
        H2[i * 2 + 0] = __halves2half2(hx, hy);
        H2[i * 2 + 1] = __halves2half2(hz, hw);
        L2[i * 2 + 0] = __halves2half2(__float2half_rn(v.x - __half2float(hx)),
                                       __float2half_rn(v.y - __half2float(hy)));
        L2[i * 2 + 1] = __halves2half2(__float2half_rn(v.z - __half2float(hz)),
                                       __float2half_rn(v.w - __half2float(hw)));
    }
}

// ---------------- final head ----------------
__global__ void k_out(const float* __restrict__ H, const float* __restrict__ Wo,
                      const float* __restrict__ bo, float* __restrict__ Out) {
    __shared__ float sw[F_MID * N_OUT];
    for (int i = threadIdx.x; i < F_MID * N_OUT; i += blockDim.x) sw[i] = Wo[i];
    __syncthreads();
    int warp = threadIdx.x / 32, lane = threadIdx.x % 32;
    int row = blockIdx.x * (blockDim.x / 32) + warp;
    if (row >= N_NODES) return;
    float acc[N_OUT];
    #pragma unroll
    for (int o = 0; o < N_OUT; o++) acc[o] = 0.0f;
    const float* h = H + (size_t)row * F_MID;
    for (int k = lane; k < F_MID; k += 32) {
        float hv = h[k];
        #pragma unroll
        for (int o = 0; o < N_OUT; o++) acc[o] += hv * sw[k * N_OUT + o];
    }
    #pragma unroll
    for (int o = 0; o < N_OUT; o++)
        #pragma unroll
        for (int off = 16; off; off >>= 1)
            acc[o] += __shfl_down_sync(0xffffffffu, acc[o], off);
    if (lane == 0)
        #pragma unroll
        for (int o = 0; o < N_OUT; o++)
            Out[(size_t)row * N_OUT + o] = acc[o] + bo[o];
}

// ---------------- host-side GEMM launcher ----------------
struct PassDef { const __half* A; const __half* B; int Kw; };
static void run_gemm(const PassDef* passes, int np, const float* bias, float* C,
                     int M, int N, int relu, int stats) {
    GemmParams P = {};
    int cum = 0;
    for (int i = 0; i < np; i++) {
        P.A[i] = passes[i].A;
        P.B[i] = passes[i].B;
        P.Kw[i] = passes[i].Kw;
        cum += passes[i].Kw / 64;
        P.chEnd[i] = cum;
    }
    P.totalChunks = cum;
    P.bias = bias; P.C = C; P.M = M; P.Ncols = N; P.relu = relu; P.stats = stats;
    dim3 g((M + 127) / 128, N / 128);
    k_gemm<<<g, 256, SMEM_REQ>>>(P);
}

// ---------------- launch ----------------
extern "C" void kernel_launch(void* const* d_in, const int* in_sizes, int n_in,
                              void* d_out, int out_size) {
    const float* x   = (const float*)d_in[0];
    const void*  edges = d_in[1];
    const float* W1l = (const float*)d_in[2];
    const float* b1  = (const float*)d_in[3];
    const float* W1r = (const float*)d_in[4];
    const float* g1  = (const float*)d_in[5];
    const float* be1 = (const float*)d_in[6];
    const float* W2l = (const float*)d_in[7];
    const float* b2  = (const float*)d_in[8];
    const float* W2r = (const float*)d_in[9];
    const float* g2  = (const float*)d_in[10];
    const float* be2 = (const float*)d_in[11];
    const float* Wf  = (const float*)d_in[12];
    const float* bf  = (const float*)d_in[13];
    const float* Wo  = (const float*)d_in[14];
    const float* bo  = (const float*)d_in[15];
    float* out = (float*)d_out;

    cudaFuncSetAttribute(k_gemm, cudaFuncAttributeMaxDynamicSharedMemorySize, SMEM_REQ);

    void *p_deg, *p_sum, *p_sumsq, *p_tmp, *p_Ah, *p_Al, *p_Bh, *p_Bl, *p_W;
    cudaGetSymbolAddress(&p_deg, g_deg);
    cudaGetSymbolAddress(&p_sum, g_sum);
    cudaGetSymbolAddress(&p_sumsq, g_sumsq);
    cudaGetSymbolAddress(&p_tmp, g_tmp);
    cudaGetSymbolAddress(&p_Ah, g_Ah);
    cudaGetSymbolAddress(&p_Al, g_Al);
    cudaGetSymbolAddress(&p_Bh, g_Bh);
    cudaGetSymbolAddress(&p_Bl, g_Bl);
    cudaGetSymbolAddress(&p_W, g_W16);
    float* tmp = (float*)p_tmp;
    __half* Ah = (__half*)p_Ah;
    __half* Al = (__half*)p_Al;
    __half* Bh = (__half*)p_Bh;
    __half* Bl = (__half*)p_Bl;
    __half* W16 = (__half*)p_W;

    // CSR build
    cudaMemsetAsync(p_deg, 0, N_NODES * sizeof(int));
    k_detect<<<1, 32>>>((const unsigned int*)edges);
    k_hist<<<(N_EDGES + 255) / 256, 256>>>(edges);
    k_scan<<<1, 1024>>>();
    k_scatter<<<(N_EDGES + 255) / 256, 256>>>(edges);

    // weight transpose (fp16, single array)
    dim3 wb(32, 8);
    k_wt<<<dim3(F_IN / 32, HID / 32), wb>>>(W1l, W16 + OFF_W1L, F_IN, HID);
    k_wt<<<dim3(F_IN / 32, HID / 32), wb>>>(W1r, W16 + OFF_W1R, F_IN, HID);
    k_wt<<<dim3(HID / 32, HID / 32), wb>>>(W2l, W16 + OFF_W2L, HID, HID);
    k_wt<<<dim3(HID / 32, HID / 32), wb>>>(W2r, W16 + OFF_W2R, HID, HID);
    k_wt<<<dim3(HID / 32, F_MID / 32), wb>>>(Wf, W16 + OFF_WF, HID, F_MID);

    // x split
    {
        size_t n = (size_t)N_NODES * F_IN;
        k_split<<<(unsigned)((n + 255) / 256), 256>>>(x, Bh, Bl, n);
    }

    // ---- layer 1 ----
    k_agg1<<<N_NODES, 128>>>(x, Ah, Al);
    cudaMemsetAsync(p_sum, 0, HID * sizeof(float));
    cudaMemsetAsync(p_sumsq, 0, HID * sizeof(float));
    {
        PassDef pl[4] = {
            {Ah, W16 + OFF_W1L, F_IN}, {Al, W16 + OFF_W1L, F_IN},
            {Bh, W16 + OFF_W1R, F_IN}, {Bl, W16 + OFF_W1R, F_IN},
        };
        run_gemm(pl, 4, b1, tmp, N_NODES, HID, 0, 1);
    }
    k_bnparams<<<HID / 256, 256>>>(g1, be1);
    {
        size_t n4 = (size_t)N_NODES * HID / 4;
        k_bnrelu<<<(unsigned)((n4 + 255) / 256), 256>>>(tmp, Bh, Bl);
    }

    // ---- layer 2 (aggregate path pure fp16: hi-only gather, no Al pass) ----
    k_agg2<<<N_NODES, 128>>>(Bh, Ah);
    cudaMemsetAsync(p_sum, 0, HID * sizeof(float));
    cudaMemsetAsync(p_sumsq, 0, HID * sizeof(float));
    {
        PassDef pl[3] = {
            {Ah, W16 + OFF_W2L, HID},
            {Bh, W16 + OFF_W2R, HID}, {Bl, W16 + OFF_W2R, HID},
        };
        run_gemm(pl, 3, b2, tmp, N_NODES, HID, 0, 1);
    }
    k_bnparams<<<HID / 256, 256>>>(g2, be2);
    {
        size_t n4 = (size_t)N_NODES * HID / 4;
        k_bnrelu<<<(unsigned)((n4 + 255) / 256), 256>>>(tmp, Bh, Bl);
    }

    // ---- fc + ReLU ----
    {
        PassDef pl[2] = {
            {Bh, W16 + OFF_WF, HID}, {Bl, W16 + OFF_WF, HID},
        };
        run_gemm(pl, 2, bf, tmp, N_NODES, F_MID, 1, 0);
    }

    // ---- head ----
    k_out<<<(N_NODES + 7) / 8, 256>>>(tmp, Wo, bo, out);
}

// round 12
// speedup vs baseline: 2.6480x; 1.2605x over previous
#include <cuda_runtime.h>
#include <cuda_fp16.h>
#include <cstdint>

#define N_NODES 50000
#define N_EDGES 400000
#define F_IN    256
#define HID     1024
#define F_MID   512
#define N_OUT   10
#define EPS_BN  1e-5f

// ---------------- scratch (device globals) ----------------
__device__ float g_tmp[(size_t)N_NODES * HID];
__device__ __half g_Ah[(size_t)N_NODES * HID];   // aggregate hi
__device__ __half g_Al[(size_t)N_NODES * HID];   // aggregate lo (layer 1 only)
__device__ __half g_Bh[(size_t)N_NODES * HID];   // x / h hi
__device__ __half g_Bl[(size_t)N_NODES * HID];   // x lo (layer 1 only)
#define OFF_W1L 0
#define OFF_W1R 262144
#define OFF_W2L 524288
#define OFF_W2R 1572864
#define OFF_WF  2621440
__device__ __half g_W16[3145728];                // fp16 weights (transposed)

__device__ int   g_deg[N_NODES];
__device__ int   g_off[N_NODES];
__device__ int   g_cur[N_NODES];
__device__ int   g_csr[N_EDGES];
__device__ float g_sum[HID];
__device__ float g_sumsq[HID];
__device__ float g_a[HID];
__device__ float g_c[HID];
__device__ int   g_is64;

// ---------------- dtype detection ----------------
__global__ void k_detect(const unsigned int* e) {
    if (threadIdx.x == 0) {
        int is64 = 1;
        for (int i = 0; i < 64; i++)
            if (e[2 * i + 1] != 0u) { is64 = 0; break; }
        g_is64 = is64;
    }
}
__device__ __forceinline__ int load_edge(const void* edges, int idx) {
    if (g_is64) return (int)((const long long*)edges)[idx];
    return ((const int*)edges)[idx];
}

// ---------------- CSR build ----------------
__global__ void k_hist(const void* edges) {
    int i = blockIdx.x * blockDim.x + threadIdx.x;
    if (i < N_EDGES) atomicAdd(&g_deg[load_edge(edges, N_EDGES + i)], 1);
}
__global__ void k_scan() {
    __shared__ int sh[1024];
    __shared__ int carry;
    int t = threadIdx.x;
    if (t == 0) carry = 0;
    __syncthreads();
    for (int base = 0; base < N_NODES; base += 1024) {
        int v = (base + t < N_NODES) ? g_deg[base + t] : 0;
        sh[t] = v;
        __syncthreads();
        #pragma unroll
        for (int off = 1; off < 1024; off <<= 1) {
            int add = (t >= off) ? sh[t - off] : 0;
            __syncthreads();
            sh[t] += add;
            __syncthreads();
        }
        int excl = sh[t] - v;
        int c0 = carry;
        if (base + t < N_NODES) { g_off[base + t] = c0 + excl; g_cur[base + t] = c0 + excl; }
        __syncthreads();
        if (t == 0) carry = c0 + sh[1023];
        __syncthreads();
    }
}
__global__ void k_scatter(const void* edges) {
    int i = blockIdx.x * blockDim.x + threadIdx.x;
    if (i < N_EDGES) {
        int src = load_edge(edges, i);
        int dst = load_edge(edges, N_EDGES + i);
        g_csr[atomicAdd(&g_cur[dst], 1)] = src;
    }
}

// ---------------- layer-1 aggregation: fp32 x -> fp16 hi/lo ----------------
__global__ void k_agg1(const float* __restrict__ X,
                       __half* __restrict__ OH, __half* __restrict__ OL) {
    int node = blockIdx.x;
    int t = threadIdx.x;                 // 128, 2 floats each
    float a0 = 0.f, a1 = 0.f;
    int start = g_off[node];
    int deg = g_deg[node];
    for (int i = 0; i < deg; i++) {
        const float2 v = *(const float2*)(X + (size_t)g_csr[start + i] * F_IN + t * 2);
        a0 += v.x; a1 += v.y;
    }
    float inv = (deg > 0) ? (1.0f / (float)deg) : 0.0f;
    a0 *= inv; a1 *= inv;
    __half h0 = __float2half_rn(a0), h1 = __float2half_rn(a1);
    size_t o = (size_t)node * F_IN + t * 2;
    *(__half2*)(OH + o) = __halves2half2(h0, h1);
    *(__half2*)(OL + o) = __halves2half2(
        __float2half_rn(a0 - __half2float(h0)),
        __float2half_rn(a1 - __half2float(h1)));
}

// ---------------- layer-2 aggregation: fp16 hi -> fp16 hi ----------------
__global__ void k_agg2(const __half* __restrict__ XH, __half* __restrict__ OH) {
    int node = blockIdx.x;
    int t = threadIdx.x;                 // 128, 8 elems each
    float acc[8];
    #pragma unroll
    for (int j = 0; j < 8; j++) acc[j] = 0.f;
    int start = g_off[node];
    int deg = g_deg[node];
    for (int i = 0; i < deg; i++) {
        size_t ro = (size_t)g_csr[start + i] * HID + t * 8;
        union { uint4 u; __half b[8]; } uh;
        uh.u = *(const uint4*)(XH + ro);
        #pragma unroll
        for (int j = 0; j < 8; j++)
            acc[j] += __half2float(uh.b[j]);
    }
    float inv = (deg > 0) ? (1.0f / (float)deg) : 0.0f;
    union { uint4 u; __half b[8]; } oh;
    #pragma unroll
    for (int j = 0; j < 8; j++)
        oh.b[j] = __float2half_rn(acc[j] * inv);
    *(uint4*)(OH + (size_t)node * HID + t * 8) = oh.u;
}

// ---------------- fp32 -> fp16 hi/lo split ----------------
__global__ void k_split(const float* __restrict__ X, __half* __restrict__ H,
                        __half* __restrict__ L, size_t n) {
    size_t i = (size_t)blockIdx.x * blockDim.x + threadIdx.x;
    if (i < n) {
        float v = X[i];
        __half h = __float2half_rn(v);
        H[i] = h;
        L[i] = __float2half_rn(v - __half2float(h));
    }
}

// ---------------- weight transpose: W[K,N] -> T[N,K] fp16 ----------------
__global__ void k_wt(const float* __restrict__ W, __half* __restrict__ T, int K, int N) {
    __shared__ float t[32][33];
    int kb = blockIdx.x * 32, nb = blockIdx.y * 32;
    int tx = threadIdx.x, ty = threadIdx.y;  // 32 x 8
    #pragma unroll
    for (int i = 0; i < 32; i += 8)
        t[ty + i][tx] = W[(size_t)(kb + ty + i) * N + nb + tx];
    __syncthreads();
    #pragma unroll
    for (int i = 0; i < 32; i += 8)
        T[(size_t)(nb + ty + i) * K + kb + tx] = __float2half_rn(t[tx][ty + i]);
}

// ---------------- fp16 mma.sync GEMM ----------------
// C[M,N] = sum_p A_p[M,Kp] @ B_p[N,Kp]^T + bias (+ReLU) (+fused column stats)
// CTA tile 128x128, warp tile 32x64 (4x2 warps), BK=64,
// 3-stage cp.async, 2 CTAs/SM — best measured config.
struct GemmParams {
    const __half* A[6];
    const __half* B[6];
    int Kw[6];
    int chEnd[6];
    int totalChunks;
    const float* bias;
    float* C;
    int M;
    int Ncols;
    int relu;
    int stats;
};

#define STAGES 3
#define STAGE_BYTES 32768              // 16KB A + 16KB B
#define SMEM_REQ (1024 + STAGES * STAGE_BYTES)

__device__ __forceinline__ uint32_t swz(uint32_t o) { return o ^ ((o >> 3) & 0x70); }

__device__ __forceinline__ void cp16(uint32_t dst, const void* src, bool p) {
    int sz = p ? 16 : 0;
    asm volatile("cp.async.cg.shared.global [%0], [%1], 16, %2;\n"
                 :: "r"(dst), "l"(src), "r"(sz));
}

__global__ __launch_bounds__(256, 2) void k_gemm(const __grid_constant__ GemmParams P) {
    extern __shared__ char dsm[];
    uint32_t raw;
    asm("{ .reg .u64 t; cvta.to.shared.u64 t, %1; cvt.u32.u64 %0, t; }" : "=r"(raw) : "l"(dsm));
    uint32_t tiles = (raw + 1023) & ~1023u;
    int tid = threadIdx.x;
    int wid = tid >> 5;
    int lane = tid & 31;
    int mBase = blockIdx.x * 128;
    int nBase = blockIdx.y * 128;
    int mw = wid >> 1;     // 0..3
    int nw = wid & 1;      // 0..1

    auto load_chunk = [&](int c, int s) {
        int p = 0;
        while (c >= P.chEnd[p]) p++;
        int c0 = (p ? c - P.chEnd[p - 1] : c) * 64;
        const char* Ab = (const char*)P.A[p] + (size_t)c0 * 2;
        const char* Bb = (const char*)P.B[p] + (size_t)c0 * 2;
        size_t rowB = (size_t)P.Kw[p] * 2;
        uint32_t stA = tiles + s * STAGE_BYTES;
        uint32_t stB = stA + 16384;
        #pragma unroll
        for (int i = 0; i < 4; i++) {
            int o = tid + i * 256;
            int row = o >> 3, kb = (o & 7) * 16;
            bool ok = (mBase + row) < P.M;
            cp16(stA + swz(row * 128 + kb), Ab + (size_t)(mBase + row) * rowB + kb, ok);
        }
        #pragma unroll
        for (int i = 0; i < 4; i++) {
            int o = tid + i * 256;
            int row = o >> 3, kb = (o & 7) * 16;
            cp16(stB + swz(row * 128 + kb), Bb + (size_t)(nBase + row) * rowB + kb, true);
        }
        asm volatile("cp.async.commit_group;" ::: "memory");
    };

    const int T = P.totalChunks;

    float acc[2][8][4];
    #pragma unroll
    for (int mi = 0; mi < 2; mi++)
        #pragma unroll
        for (int n8 = 0; n8 < 8; n8++)
            #pragma unroll
            for (int q = 0; q < 4; q++) acc[mi][n8][q] = 0.0f;

    int npre = (T < 2) ? T : 2;
    for (int c = 0; c < npre; c++) load_chunk(c, c);

    for (int c = 0; c < T; c++) {
        int s = c % 3;
        if (c == T - 1) asm volatile("cp.async.wait_group 0;" ::: "memory");
        else            asm volatile("cp.async.wait_group 1;" ::: "memory");
        __syncthreads();

        uint32_t stA = tiles + s * STAGE_BYTES;
        uint32_t stB = stA + 16384;
        #pragma unroll
        for (int ks = 0; ks < 4; ks++) {
            uint32_t a[2][4];
            uint32_t arow = mw * 32 + ((lane >> 3) & 1) * 8 + (lane & 7);
            uint32_t akb  = ks * 32 + (lane >> 4) * 16;
            #pragma unroll
            for (int mi = 0; mi < 2; mi++) {
                uint32_t ad = stA + swz((arow + mi * 16) * 128 + akb);
                asm volatile("ldmatrix.sync.aligned.m8n8.x4.shared.b16 {%0,%1,%2,%3}, [%4];"
                             : "=r"(a[mi][0]), "=r"(a[mi][1]), "=r"(a[mi][2]), "=r"(a[mi][3])
                             : "r"(ad));
            }
            uint32_t b[4][4];
            uint32_t brow = nw * 64 + ((lane >> 4) & 1) * 8 + (lane & 7);
            uint32_t bkb  = ks * 32 + ((lane >> 3) & 1) * 16;
            #pragma unroll
            for (int ni = 0; ni < 4; ni++) {
                uint32_t bd = stB + swz((brow + ni * 16) * 128 + bkb);
                asm volatile("ldmatrix.sync.aligned.m8n8.x4.shared.b16 {%0,%1,%2,%3}, [%4];"
                             : "=r"(b[ni][0]), "=r"(b[ni][1]), "=r"(b[ni][2]), "=r"(b[ni][3])
                             : "r"(bd));
            }
            #pragma unroll
            for (int mi = 0; mi < 2; mi++)
                #pragma unroll
                for (int n8 = 0; n8 < 8; n8++) {
                    uint32_t b0 = b[n8 >> 1][(n8 & 1) * 2 + 0];
                    uint32_t b1 = b[n8 >> 1][(n8 & 1) * 2 + 1];
                    asm volatile(
                        "mma.sync.aligned.m16n8k16.row.col.f32.f16.f16.f32 "
                        "{%0,%1,%2,%3}, {%4,%5,%6,%7}, {%8,%9}, {%0,%1,%2,%3};"
                        : "+f"(acc[mi][n8][0]), "+f"(acc[mi][n8][1]),
                          "+f"(acc[mi][n8][2]), "+f"(acc[mi][n8][3])
                        : "r"(a[mi][0]), "r"(a[mi][1]), "r"(a[mi][2]), "r"(a[mi][3]),
                          "r"(b0), "r"(b1));
                }
        }
        if (c + 2 < T) load_chunk(c + 2, (c + 2) % 3);
    }

    // epilogue: bias (+ReLU) store + fused column stats
    {
        int g = lane >> 2, t4 = lane & 3;
        #pragma unroll
        for (int n8 = 0; n8 < 8; n8++) {
            int col = nBase + nw * 64 + n8 * 8 + t4 * 2;
            float bx = P.bias[col], by = P.bias[col + 1];
            float s0 = 0.f, s1 = 0.f, q0 = 0.f, q1 = 0.f;
            #pragma unroll
            for (int mi = 0; mi < 2; mi++) {
                int r0 = mBase + mw * 32 + mi * 16 + g;
                float2 v;
                v.x = acc[mi][n8][0] + bx;
                v.y = acc[mi][n8][1] + by;
                if (P.relu) { v.x = fmaxf(v.x, 0.f); v.y = fmaxf(v.y, 0.f); }
                if (r0 < P.M) {
                    *(float2*)(P.C + (size_t)r0 * P.Ncols + col) = v;
                    s0 += v.x; s1 += v.y; q0 += v.x * v.x; q1 += v.y * v.y;
                }
                int r1 = r0 + 8;
                float2 w;
                w.x = acc[mi][n8][2] + bx;
                w.y = acc[mi][n8][3] + by;
                if (P.relu) { w.x = fmaxf(w.x, 0.f); w.y = fmaxf(w.y, 0.f); }
                if (r1 < P.M) {
                    *(float2*)(P.C + (size_t)r1 * P.Ncols + col) = w;
                    s0 += w.x; s1 += w.y; q0 += w.x * w.x; q1 += w.y * w.y;
                }
            }
            if (P.stats) {
                #pragma unroll
                for (int o = 4; o <= 16; o <<= 1) {
                    s0 += __shfl_xor_sync(0xffffffffu, s0, o);
                    s1 += __shfl_xor_sync(0xffffffffu, s1, o);
                    q0 += __shfl_xor_sync(0xffffffffu, q0, o);
                    q1 += __shfl_xor_sync(0xffffffffu, q1, o);
                }
                if (g == 0) {
                    atomicAdd(&g_sum[col], s0);
                    atomicAdd(&g_sum[col + 1], s1);
                    atomicAdd(&g_sumsq[col], q0);
                    atomicAdd(&g_sumsq[col + 1], q1);
                }
            }
        }
    }
}

// ---------------- BN params / apply ----------------
__global__ void k_bnparams(const float* __restrict__ g, const float* __restrict__ be) {
    int c = blockIdx.x * blockDim.x + threadIdx.x;
    if (c < HID) {
        float m = g_sum[c] * (1.0f / N_NODES);
        float var = g_sumsq[c] * (1.0f / N_NODES) - m * m;
        float a = g[c] * rsqrtf(var + EPS_BN);
        g_a[c] = a;
        g_c[c] = be[c] - m * a;
    }
}
// BN+ReLU -> fp16 hi only (no correction consumers downstream)
__global__ void k_bnrelu(const float* __restrict__ X, __half* __restrict__ YH) {
    size_t i = (size_t)blockIdx.x * blockDim.x + threadIdx.x;  // float4 index
    const size_t total = (size_t)N_NODES * HID / 4;
    if (i < total) {
        int c = (int)((i * 4) % HID);
        float4 v = ((const float4*)X)[i];
        v.x = fmaxf(0.f, v.x * g_a[c + 0] + g_c[c + 0]);
        v.y = fmaxf(0.f, v.y * g_a[c + 1] + g_c[c + 1]);
        v.z = fmaxf(0.f, v.z * g_a[c + 2] + g_c[c + 2]);
        v.w = fmaxf(0.f, v.w * g_a[c + 3] + g_c[c + 3]);
        __half2* H2 = (__half2*)YH;
        H2[i * 2 + 0] = __halves2half2(__float2half_rn(v.x), __float2half_rn(v.y));
        H2[i * 2 + 1] = __halves2half2(__float2half_rn(v.z), __float2half_rn(v.w));
    }
}

// ---------------- final head ----------------
__global__ void k_out(const float* __restrict__ H, const float* __restrict__ Wo,
                      const float* __restrict__ bo, float* __restrict__ Out) {
    __shared__ float sw[F_MID * N_OUT];
    for (int i = threadIdx.x; i < F_MID * N_OUT; i += blockDim.x) sw[i] = Wo[i];
    __syncthreads();
    int warp = threadIdx.x / 32, lane = threadIdx.x % 32;
    int row = blockIdx.x * (blockDim.x / 32) + warp;
    if (row >= N_NODES) return;
    float acc[N_OUT];
    #pragma unroll
    for (int o = 0; o < N_OUT; o++) acc[o] = 0.0f;
    const float* h = H + (size_t)row * F_MID;
    for (int k = lane; k < F_MID; k += 32) {
        float hv = h[k];
        #pragma unroll
        for (int o = 0; o < N_OUT; o++) acc[o] += hv * sw[k * N_OUT + o];
    }
    #pragma unroll
    for (int o = 0; o < N_OUT; o++)
        #pragma unroll
        for (int off = 16; off; off >>= 1)
            acc[o] += __shfl_down_sync(0xffffffffu, acc[o], off);
    if (lane == 0)
        #pragma unroll
        for (int o = 0; o < N_OUT; o++)
            Out[(size_t)row * N_OUT + o] = acc[o] + bo[o];
}

// ---------------- host-side GEMM launcher ----------------
struct PassDef { const __half* A; const __half* B; int Kw; };
static void run_gemm(const PassDef* passes, int np, const float* bias, float* C,
                     int M, int N, int relu, int stats) {
    GemmParams P = {};
    int cum = 0;
    for (int i = 0; i < np; i++) {
        P.A[i] = passes[i].A;
        P.B[i] = passes[i].B;
        P.Kw[i] = passes[i].Kw;
        cum += passes[i].Kw / 64;
        P.chEnd[i] = cum;
    }
    P.totalChunks = cum;
    P.bias = bias; P.C = C; P.M = M; P.Ncols = N; P.relu = relu; P.stats = stats;
    dim3 g((M + 127) / 128, N / 128);
    k_gemm<<<g, 256, SMEM_REQ>>>(P);
}

// ---------------- launch ----------------
extern "C" void kernel_launch(void* const* d_in, const int* in_sizes, int n_in,
                              void* d_out, int out_size) {
    const float* x   = (const float*)d_in[0];
    const void*  edges = d_in[1];
    const float* W1l = (const float*)d_in[2];
    const float* b1  = (const float*)d_in[3];
    const float* W1r = (const float*)d_in[4];
    const float* g1  = (const float*)d_in[5];
    const float* be1 = (const float*)d_in[6];
    const float* W2l = (const float*)d_in[7];
    const float* b2  = (const float*)d_in[8];
    const float* W2r = (const float*)d_in[9];
    const float* g2  = (const float*)d_in[10];
    const float* be2 = (const float*)d_in[11];
    const float* Wf  = (const float*)d_in[12];
    const float* bf  = (const float*)d_in[13];
    const float* Wo  = (const float*)d_in[14];
    const float* bo  = (const float*)d_in[15];
    float* out = (float*)d_out;

    cudaFuncSetAttribute(k_gemm, cudaFuncAttributeMaxDynamicSharedMemorySize, SMEM_REQ);

    void *p_deg, *p_sum, *p_sumsq, *p_tmp, *p_Ah, *p_Al, *p_Bh, *p_Bl, *p_W;
    cudaGetSymbolAddress(&p_deg, g_deg);
    cudaGetSymbolAddress(&p_sum, g_sum);
    cudaGetSymbolAddress(&p_sumsq, g_sumsq);
    cudaGetSymbolAddress(&p_tmp, g_tmp);
    cudaGetSymbolAddress(&p_Ah, g_Ah);
    cudaGetSymbolAddress(&p_Al, g_Al);
    cudaGetSymbolAddress(&p_Bh, g_Bh);
    cudaGetSymbolAddress(&p_Bl, g_Bl);
    cudaGetSymbolAddress(&p_W, g_W16);
    float* tmp = (float*)p_tmp;
    __half* Ah = (__half*)p_Ah;
    __half* Al = (__half*)p_Al;
    __half* Bh = (__half*)p_Bh;
    __half* Bl = (__half*)p_Bl;
    __half* W16 = (__half*)p_W;

    // CSR build
    cudaMemsetAsync(p_deg, 0, N_NODES * sizeof(int));
    k_detect<<<1, 32>>>((const unsigned int*)edges);
    k_hist<<<(N_EDGES + 255) / 256, 256>>>(edges);
    k_scan<<<1, 1024>>>();
    k_scatter<<<(N_EDGES + 255) / 256, 256>>>(edges);

    // weight transpose (fp16)
    dim3 wb(32, 8);
    k_wt<<<dim3(F_IN / 32, HID / 32), wb>>>(W1l, W16 + OFF_W1L, F_IN, HID);
    k_wt<<<dim3(F_IN / 32, HID / 32), wb>>>(W1r, W16 + OFF_W1R, F_IN, HID);
    k_wt<<<dim3(HID / 32, HID / 32), wb>>>(W2l, W16 + OFF_W2L, HID, HID);
    k_wt<<<dim3(HID / 32, HID / 32), wb>>>(W2r, W16 + OFF_W2R, HID, HID);
    k_wt<<<dim3(HID / 32, F_MID / 32), wb>>>(Wf, W16 + OFF_WF, HID, F_MID);

    // x split (layer-1 right operand, full hi/lo)
    {
        size_t n = (size_t)N_NODES * F_IN;
        k_split<<<(unsigned)((n + 255) / 256), 256>>>(x, Bh, Bl, n);
    }

    // ---- layer 1 (fully corrected: Ah+Al, Bh+Bl) ----
    k_agg1<<<N_NODES, 128>>>(x, Ah, Al);
    cudaMemsetAsync(p_sum, 0, HID * sizeof(float));
    cudaMemsetAsync(p_sumsq, 0, HID * sizeof(float));
    {
        PassDef pl[4] = {
            {Ah, W16 + OFF_W1L, F_IN}, {Al, W16 + OFF_W1L, F_IN},
            {Bh, W16 + OFF_W1R, F_IN}, {Bl, W16 + OFF_W1R, F_IN},
        };
        run_gemm(pl, 4, b1, tmp, N_NODES, HID, 0, 1);
    }
    k_bnparams<<<HID / 256, 256>>>(g1, be1);
    {
        size_t n4 = (size_t)N_NODES * HID / 4;
        k_bnrelu<<<(unsigned)((n4 + 255) / 256), 256>>>(tmp, Bh);
    }

    // ---- layer 2 (pure fp16: hi-only everywhere) ----
    k_agg2<<<N_NODES, 128>>>(Bh, Ah);
    cudaMemsetAsync(p_sum, 0, HID * sizeof(float));
    cudaMemsetAsync(p_sumsq, 0, HID * sizeof(float));
    {
        PassDef pl[2] = {
            {Ah, W16 + OFF_W2L, HID},
            {Bh, W16 + OFF_W2R, HID},
        };
        run_gemm(pl, 2, b2, tmp, N_NODES, HID, 0, 1);
    }
    k_bnparams<<<HID / 256, 256>>>(g2, be2);
    {
        size_t n4 = (size_t)N_NODES * HID / 4;
        k_bnrelu<<<(unsigned)((n4 + 255) / 256), 256>>>(tmp, Bh);
    }

    // ---- fc + ReLU (pure fp16) ----
    {
        PassDef pl[1] = {
            {Bh, W16 + OFF_WF, HID},
        };
        run_gemm(pl, 1, bf, tmp, N_NODES, F_MID, 1, 0);
    }

    // ---- head ----
    k_out<<<(N_NODES + 7) / 8, 256>>>(tmp, Wo, bo, out);
}

// round 13
// speedup vs baseline: 2.9133x; 1.1002x over previous
#include <cuda_runtime.h>
#include <cuda_fp16.h>
#include <cstdint>

#define N_NODES 50000
#define N_EDGES 400000
#define F_IN    256
#define HID     1024
#define F_MID   512
#define N_OUT   10
#define EPS_BN  1e-5f

// ---------------- scratch (device globals) ----------------
__device__ float g_tmp[(size_t)N_NODES * HID];
__device__ __half g_Ah[(size_t)N_NODES * HID];   // aggregate (fp16)
__device__ __half g_Bh[(size_t)N_NODES * HID];   // x / h (fp16)
#define OFF_W1L 0
#define OFF_W1R 262144
#define OFF_W2L 524288
#define OFF_W2R 1572864
#define OFF_WF  2621440
__device__ __half g_W16[3145728];                // fp16 weights (transposed)

__device__ int   g_deg[N_NODES];
__device__ int   g_off[N_NODES];
__device__ int   g_cur[N_NODES];
__device__ int   g_csr[N_EDGES];
__device__ float g_sum[HID];
__device__ float g_sumsq[HID];
__device__ float g_a[HID];
__device__ float g_c[HID];
__device__ int   g_is64;

// ---------------- dtype detection ----------------
__global__ void k_detect(const unsigned int* e) {
    if (threadIdx.x == 0) {
        int is64 = 1;
        for (int i = 0; i < 64; i++)
            if (e[2 * i + 1] != 0u) { is64 = 0; break; }
        g_is64 = is64;
    }
}
__device__ __forceinline__ int load_edge(const void* edges, int idx) {
    if (g_is64) return (int)((const long long*)edges)[idx];
    return ((const int*)edges)[idx];
}

// ---------------- CSR build ----------------
__global__ void k_hist(const void* edges) {
    int i = blockIdx.x * blockDim.x + threadIdx.x;
    if (i < N_EDGES) atomicAdd(&g_deg[load_edge(edges, N_EDGES + i)], 1);
}
__global__ void k_scan() {
    __shared__ int sh[1024];
    __shared__ int carry;
    int t = threadIdx.x;
    if (t == 0) carry = 0;
    __syncthreads();
    for (int base = 0; base < N_NODES; base += 1024) {
        int v = (base + t < N_NODES) ? g_deg[base + t] : 0;
        sh[t] = v;
        __syncthreads();
        #pragma unroll
        for (int off = 1; off < 1024; off <<= 1) {
            int add = (t >= off) ? sh[t - off] : 0;
            __syncthreads();
            sh[t] += add;
            __syncthreads();
        }
        int excl = sh[t] - v;
        int c0 = carry;
        if (base + t < N_NODES) { g_off[base + t] = c0 + excl; g_cur[base + t] = c0 + excl; }
        __syncthreads();
        if (t == 0) carry = c0 + sh[1023];
        __syncthreads();
    }
}
__global__ void k_scatter(const void* edges) {
    int i = blockIdx.x * blockDim.x + threadIdx.x;
    if (i < N_EDGES) {
        int src = load_edge(edges, i);
        int dst = load_edge(edges, N_EDGES + i);
        g_csr[atomicAdd(&g_cur[dst], 1)] = src;
    }
}

// ---------------- layer-1 aggregation + own-row split (pure fp16) ---------
// Writes agg mean -> OH, and the node's own x row -> XHO (replaces k_split).
__global__ void k_agg1(const float* __restrict__ X,
                       __half* __restrict__ OH, __half* __restrict__ XHO) {
    int node = blockIdx.x;
    int t = threadIdx.x;                 // 128, 2 floats each
    float a0 = 0.f, a1 = 0.f;
    int start = g_off[node];
    int deg = g_deg[node];
    for (int i = 0; i < deg; i++) {
        const float2 v = *(const float2*)(X + (size_t)g_csr[start + i] * F_IN + t * 2);
        a0 += v.x; a1 += v.y;
    }
    float inv = (deg > 0) ? (1.0f / (float)deg) : 0.0f;
    a0 *= inv; a1 *= inv;
    size_t o = (size_t)node * F_IN + t * 2;
    *(__half2*)(OH + o) = __halves2half2(__float2half_rn(a0), __float2half_rn(a1));
    // own row -> fp16 (for the W1r path)
    const float2 xv = *(const float2*)(X + o);
    *(__half2*)(XHO + o) = __halves2half2(__float2half_rn(xv.x), __float2half_rn(xv.y));
}

// ---------------- layer-2 aggregation: fp16 -> fp16 ----------------
__global__ void k_agg2(const __half* __restrict__ XH, __half* __restrict__ OH) {
    int node = blockIdx.x;
    int t = threadIdx.x;                 // 128, 8 elems each
    float acc[8];
    #pragma unroll
    for (int j = 0; j < 8; j++) acc[j] = 0.f;
    int start = g_off[node];
    int deg = g_deg[node];
    for (int i = 0; i < deg; i++) {
        size_t ro = (size_t)g_csr[start + i] * HID + t * 8;
        union { uint4 u; __half b[8]; } uh;
        uh.u = *(const uint4*)(XH + ro);
        #pragma unroll
        for (int j = 0; j < 8; j++)
            acc[j] += __half2float(uh.b[j]);
    }
    float inv = (deg > 0) ? (1.0f / (float)deg) : 0.0f;
    union { uint4 u; __half b[8]; } oh;
    #pragma unroll
    for (int j = 0; j < 8; j++)
        oh.b[j] = __float2half_rn(acc[j] * inv);
    *(uint4*)(OH + (size_t)node * HID + t * 8) = oh.u;
}

// ---------------- weight transpose: W[K,N] -> T[N,K] fp16 ----------------
__global__ void k_wt(const float* __restrict__ W, __half* __restrict__ T, int K, int N) {
    __shared__ float t[32][33];
    int kb = blockIdx.x * 32, nb = blockIdx.y * 32;
    int tx = threadIdx.x, ty = threadIdx.y;  // 32 x 8
    #pragma unroll
    for (int i = 0; i < 32; i += 8)
        t[ty + i][tx] = W[(size_t)(kb + ty + i) * N + nb + tx];
    __syncthreads();
    #pragma unroll
    for (int i = 0; i < 32; i += 8)
        T[(size_t)(nb + ty + i) * K + kb + tx] = __float2half_rn(t[tx][ty + i]);
}

// ---------------- fp16 mma.sync GEMM ----------------
// C[M,N] = sum_p A_p[M,Kp] @ B_p[N,Kp]^T + bias (+ReLU) (+fused column stats)
// CTA tile 128x128, warp tile 32x64 (4x2 warps), BK=64,
// 3-stage cp.async, 2 CTAs/SM — best measured config.
struct GemmParams {
    const __half* A[4];
    const __half* B[4];
    int Kw[4];
    int chEnd[4];
    int totalChunks;
    const float* bias;
    float* C;
    int M;
    int Ncols;
    int relu;
    int stats;
};

#define STAGES 3
#define STAGE_BYTES 32768              // 16KB A + 16KB B
#define SMEM_REQ (1024 + STAGES * STAGE_BYTES)

__device__ __forceinline__ uint32_t swz(uint32_t o) { return o ^ ((o >> 3) & 0x70); }

__device__ __forceinline__ void cp16(uint32_t dst, const void* src, bool p) {
    int sz = p ? 16 : 0;
    asm volatile("cp.async.cg.shared.global [%0], [%1], 16, %2;\n"
                 :: "r"(dst), "l"(src), "r"(sz));
}

__global__ __launch_bounds__(256, 2) void k_gemm(const __grid_constant__ GemmParams P) {
    extern __shared__ char dsm[];
    uint32_t raw;
    asm("{ .reg .u64 t; cvta.to.shared.u64 t, %1; cvt.u32.u64 %0, t; }" : "=r"(raw) : "l"(dsm));
    uint32_t tiles = (raw + 1023) & ~1023u;
    int tid = threadIdx.x;
    int wid = tid >> 5;
    int lane = tid & 31;
    int mBase = blockIdx.x * 128;
    int nBase = blockIdx.y * 128;
    int mw = wid >> 1;     // 0..3
    int nw = wid & 1;      // 0..1

    auto load_chunk = [&](int c, int s) {
        int p = 0;
        while (c >= P.chEnd[p]) p++;
        int c0 = (p ? c - P.chEnd[p - 1] : c) * 64;
        const char* Ab = (const char*)P.A[p] + (size_t)c0 * 2;
        const char* Bb = (const char*)P.B[p] + (size_t)c0 * 2;
        size_t rowB = (size_t)P.Kw[p] * 2;
        uint32_t stA = tiles + s * STAGE_BYTES;
        uint32_t stB = stA + 16384;
        #pragma unroll
        for (int i = 0; i < 4; i++) {
            int o = tid + i * 256;
            int row = o >> 3, kb = (o & 7) * 16;
            bool ok = (mBase + row) < P.M;
            cp16(stA + swz(row * 128 + kb), Ab + (size_t)(mBase + row) * rowB + kb, ok);
        }
        #pragma unroll
        for (int i = 0; i < 4; i++) {
            int o = tid + i * 256;
            int row = o >> 3, kb = (o & 7) * 16;
            cp16(stB + swz(row * 128 + kb), Bb + (size_t)(nBase + row) * rowB + kb, true);
        }
        asm volatile("cp.async.commit_group;" ::: "memory");
    };

    const int T = P.totalChunks;

    float acc[2][8][4];
    #pragma unroll
    for (int mi = 0; mi < 2; mi++)
        #pragma unroll
        for (int n8 = 0; n8 < 8; n8++)
            #pragma unroll
            for (int q = 0; q < 4; q++) acc[mi][n8][q] = 0.0f;

    int npre = (T < 2) ? T : 2;
    for (int c = 0; c < npre; c++) load_chunk(c, c);

    for (int c = 0; c < T; c++) {
        int s = c % 3;
        if (c == T - 1) asm volatile("cp.async.wait_group 0;" ::: "memory");
        else            asm volatile("cp.async.wait_group 1;" ::: "memory");
        __syncthreads();

        uint32_t stA = tiles + s * STAGE_BYTES;
        uint32_t stB = stA + 16384;
        #pragma unroll
        for (int ks = 0; ks < 4; ks++) {
            uint32_t a[2][4];
            uint32_t arow = mw * 32 + ((lane >> 3) & 1) * 8 + (lane & 7);
            uint32_t akb  = ks * 32 + (lane >> 4) * 16;
            #pragma unroll
            for (int mi = 0; mi < 2; mi++) {
                uint32_t ad = stA + swz((arow + mi * 16) * 128 + akb);
                asm volatile("ldmatrix.sync.aligned.m8n8.x4.shared.b16 {%0,%1,%2,%3}, [%4];"
                             : "=r"(a[mi][0]), "=r"(a[mi][1]), "=r"(a[mi][2]), "=r"(a[mi][3])
                             : "r"(ad));
            }
            uint32_t b[4][4];
            uint32_t brow = nw * 64 + ((lane >> 4) & 1) * 8 + (lane & 7);
            uint32_t bkb  = ks * 32 + ((lane >> 3) & 1) * 16;
            #pragma unroll
            for (int ni = 0; ni < 4; ni++) {
                uint32_t bd = stB + swz((brow + ni * 16) * 128 + bkb);
                asm volatile("ldmatrix.sync.aligned.m8n8.x4.shared.b16 {%0,%1,%2,%3}, [%4];"
                             : "=r"(b[ni][0]), "=r"(b[ni][1]), "=r"(b[ni][2]), "=r"(b[ni][3])
                             : "r"(bd));
            }
            #pragma unroll
            for (int mi = 0; mi < 2; mi++)
                #pragma unroll
                for (int n8 = 0; n8 < 8; n8++) {
                    uint32_t b0 = b[n8 >> 1][(n8 & 1) * 2 + 0];
                    uint32_t b1 = b[n8 >> 1][(n8 & 1) * 2 + 1];
                    asm volatile(
                        "mma.sync.aligned.m16n8k16.row.col.f32.f16.f16.f32 "
                        "{%0,%1,%2,%3}, {%4,%5,%6,%7}, {%8,%9}, {%0,%1,%2,%3};"
                        : "+f"(acc[mi][n8][0]), "+f"(acc[mi][n8][1]),
                          "+f"(acc[mi][n8][2]), "+f"(acc[mi][n8][3])
                        : "r"(a[mi][0]), "r"(a[mi][1]), "r"(a[mi][2]), "r"(a[mi][3]),
                          "r"(b0), "r"(b1));
                }
        }
        if (c + 2 < T) load_chunk(c + 2, (c + 2) % 3);
    }

    // epilogue: bias (+ReLU) store + fused column stats
    {
        int g = lane >> 2, t4 = lane & 3;
        #pragma unroll
        for (int n8 = 0; n8 < 8; n8++) {
            int col = nBase + nw * 64 + n8 * 8 + t4 * 2;
            float bx = P.bias[col], by = P.bias[col + 1];
            float s0 = 0.f, s1 = 0.f, q0 = 0.f, q1 = 0.f;
            #pragma unroll
            for (int mi = 0; mi < 2; mi++) {
                int r0 = mBase + mw * 32 + mi * 16 + g;
                float2 v;
                v.x = acc[mi][n8][0] + bx;
                v.y = acc[mi][n8][1] + by;
                if (P.relu) { v.x = fmaxf(v.x, 0.f); v.y = fmaxf(v.y, 0.f); }
                if (r0 < P.M) {
                    *(float2*)(P.C + (size_t)r0 * P.Ncols + col) = v;
                    s0 += v.x; s1 += v.y; q0 += v.x * v.x; q1 += v.y * v.y;
                }
                int r1 = r0 + 8;
                float2 w;
                w.x = acc[mi][n8][2] + bx;
                w.y = acc[mi][n8][3] + by;
                if (P.relu) { w.x = fmaxf(w.x, 0.f); w.y = fmaxf(w.y, 0.f); }
                if (r1 < P.M) {
                    *(float2*)(P.C + (size_t)r1 * P.Ncols + col) = w;
                    s0 += w.x; s1 += w.y; q0 += w.x * w.x; q1 += w.y * w.y;
                }
            }
            if (P.stats) {
                #pragma unroll
                for (int o = 4; o <= 16; o <<= 1) {
                    s0 += __shfl_xor_sync(0xffffffffu, s0, o);
                    s1 += __shfl_xor_sync(0xffffffffu, s1, o);
                    q0 += __shfl_xor_sync(0xffffffffu, q0, o);
                    q1 += __shfl_xor_sync(0xffffffffu, q1, o);
                }
                if (g == 0) {
                    atomicAdd(&g_sum[col], s0);
                    atomicAdd(&g_sum[col + 1], s1);
                    atomicAdd(&g_sumsq[col], q0);
                    atomicAdd(&g_sumsq[col + 1], q1);
                }
            }
        }
    }
}

// ---------------- BN params / apply ----------------
__global__ void k_bnparams(const float* __restrict__ g, const float* __restrict__ be) {
    int c = blockIdx.x * blockDim.x + threadIdx.x;
    if (c < HID) {
        float m = g_sum[c] * (1.0f / N_NODES);
        float var = g_sumsq[c] * (1.0f / N_NODES) - m * m;
        float a = g[c] * rsqrtf(var + EPS_BN);
        g_a[c] = a;
        g_c[c] = be[c] - m * a;
    }
}
// BN+ReLU -> fp16
__global__ void k_bnrelu(const float* __restrict__ X, __half* __restrict__ YH) {
    size_t i = (size_t)blockIdx.x * blockDim.x + threadIdx.x;  // float4 index
    const size_t total = (size_t)N_NODES * HID / 4;
    if (i < total) {
        int c = (int)((i * 4) % HID);
        float4 v = ((const float4*)X)[i];
        v.x = fmaxf(0.f, v.x * g_a[c + 0] + g_c[c + 0]);
        v.y = fmaxf(0.f, v.y * g_a[c + 1] + g_c[c + 1]);
        v.z = fmaxf(0.f, v.z * g_a[c + 2] + g_c[c + 2]);
        v.w = fmaxf(0.f, v.w * g_a[c + 3] + g_c[c + 3]);
        __half2* H2 = (__half2*)YH;
        H2[i * 2 + 0] = __halves2half2(__float2half_rn(v.x), __float2half_rn(v.y));
        H2[i * 2 + 1] = __halves2half2(__float2half_rn(v.z), __float2half_rn(v.w));
    }
}

// ---------------- final head ----------------
__global__ void k_out(const float* __restrict__ H, const float* __restrict__ Wo,
                      const float* __restrict__ bo, float* __restrict__ Out) {
    __shared__ float sw[F_MID * N_OUT];
    for (int i = threadIdx.x; i < F_MID * N_OUT; i += blockDim.x) sw[i] = Wo[i];
    __syncthreads();
    int warp = threadIdx.x / 32, lane = threadIdx.x % 32;
    int row = blockIdx.x * (blockDim.x / 32) + warp;
    if (row >= N_NODES) return;
    float acc[N_OUT];
    #pragma unroll
    for (int o = 0; o < N_OUT; o++) acc[o] = 0.0f;
    const float* h = H + (size_t)row * F_MID;
    for (int k = lane; k < F_MID; k += 32) {
        float hv = h[k];
        #pragma unroll
        for (int o = 0; o < N_OUT; o++) acc[o] += hv * sw[k * N_OUT + o];
    }
    #pragma unroll
    for (int o = 0; o < N_OUT; o++)
        #pragma unroll
        for (int off = 16; off; off >>= 1)
            acc[o] += __shfl_down_sync(0xffffffffu, acc[o], off);
    if (lane == 0)
        #pragma unroll
        for (int o = 0; o < N_OUT; o++)
            Out[(size_t)row * N_OUT + o] = acc[o] + bo[o];
}

// ---------------- host-side GEMM launcher ----------------
struct PassDef { const __half* A; const __half* B; int Kw; };
static void run_gemm(const PassDef* passes, int np, const float* bias, float* C,
                     int M, int N, int relu, int stats) {
    GemmParams P = {};
    int cum = 0;
    for (int i = 0; i < np; i++) {
        P.A[i] = passes[i].A;
        P.B[i] = passes[i].B;
        P.Kw[i] = passes[i].Kw;
        cum += passes[i].Kw / 64;
        P.chEnd[i] = cum;
    }
    P.totalChunks = cum;
    P.bias = bias; P.C = C; P.M = M; P.Ncols = N; P.relu = relu; P.stats = stats;
    dim3 g((M + 127) / 128, N / 128);
    k_gemm<<<g, 256, SMEM_REQ>>>(P);
}

// ---------------- launch ----------------
extern "C" void kernel_launch(void* const* d_in, const int* in_sizes, int n_in,
                              void* d_out, int out_size) {
    const float* x   = (const float*)d_in[0];
    const void*  edges = d_in[1];
    const float* W1l = (const float*)d_in[2];
    const float* b1  = (const float*)d_in[3];
    const float* W1r = (const float*)d_in[4];
    const float* g1  = (const float*)d_in[5];
    const float* be1 = (const float*)d_in[6];
    const float* W2l = (const float*)d_in[7];
    const float* b2  = (const float*)d_in[8];
    const float* W2r = (const float*)d_in[9];
    const float* g2  = (const float*)d_in[10];
    const float* be2 = (const float*)d_in[11];
    const float* Wf  = (const float*)d_in[12];
    const float* bf  = (const float*)d_in[13];
    const float* Wo  = (const float*)d_in[14];
    const float* bo  = (const float*)d_in[15];
    float* out = (float*)d_out;

    cudaFuncSetAttribute(k_gemm, cudaFuncAttributeMaxDynamicSharedMemorySize, SMEM_REQ);

    void *p_deg, *p_sum, *p_sumsq, *p_tmp, *p_Ah, *p_Bh, *p_W;
    cudaGetSymbolAddress(&p_deg, g_deg);
    cudaGetSymbolAddress(&p_sum, g_sum);
    cudaGetSymbolAddress(&p_sumsq, g_sumsq);
    cudaGetSymbolAddress(&p_tmp, g_tmp);
    cudaGetSymbolAddress(&p_Ah, g_Ah);
    cudaGetSymbolAddress(&p_Bh, g_Bh);
    cudaGetSymbolAddress(&p_W, g_W16);
    float* tmp = (float*)p_tmp;
    __half* Ah = (__half*)p_Ah;
    __half* Bh = (__half*)p_Bh;
    __half* W16 = (__half*)p_W;

    // CSR build
    cudaMemsetAsync(p_deg, 0, N_NODES * sizeof(int));
    k_detect<<<1, 32>>>((const unsigned int*)edges);
    k_hist<<<(N_EDGES + 255) / 256, 256>>>(edges);
    k_scan<<<1, 1024>>>();
    k_scatter<<<(N_EDGES + 255) / 256, 256>>>(edges);

    // weight transpose (fp16)
    dim3 wb(32, 8);
    k_wt<<<dim3(F_IN / 32, HID / 32), wb>>>(W1l, W16 + OFF_W1L, F_IN, HID);
    k_wt<<<dim3(F_IN / 32, HID / 32), wb>>>(W1r, W16 + OFF_W1R, F_IN, HID);
    k_wt<<<dim3(HID / 32, HID / 32), wb>>>(W2l, W16 + OFF_W2L, HID, HID);
    k_wt<<<dim3(HID / 32, HID / 32), wb>>>(W2r, W16 + OFF_W2R, HID, HID);
    k_wt<<<dim3(HID / 32, F_MID / 32), wb>>>(Wf, W16 + OFF_WF, HID, F_MID);

    // ---- layer 1 (pure fp16; agg1 also emits x in fp16) ----
    k_agg1<<<N_NODES, 128>>>(x, Ah, Bh);
    cudaMemsetAsync(p_sum, 0, HID * sizeof(float));
    cudaMemsetAsync(p_sumsq, 0, HID * sizeof(float));
    {
        PassDef pl[2] = {
            {Ah, W16 + OFF_W1L, F_IN},
            {Bh, W16 + OFF_W1R, F_IN},
        };
        run_gemm(pl, 2, b1, tmp, N_NODES, HID, 0, 1);
    }
    k_bnparams<<<HID / 256, 256>>>(g1, be1);
    {
        size_t n4 = (size_t)N_NODES * HID / 4;
        k_bnrelu<<<(unsigned)((n4 + 255) / 256), 256>>>(tmp, Bh);
    }

    // ---- layer 2 (pure fp16) ----
    k_agg2<<<N_NODES, 128>>>(Bh, Ah);
    cudaMemsetAsync(p_sum, 0, HID * sizeof(float));
    cudaMemsetAsync(p_sumsq, 0, HID * sizeof(float));
    {
        PassDef pl[2] = {
            {Ah, W16 + OFF_W2L, HID},
            {Bh, W16 + OFF_W2R, HID},
        };
        run_gemm(pl, 2, b2, tmp, N_NODES, HID, 0, 1);
    }
    k_bnparams<<<HID / 256, 256>>>(g2, be2);
    {
        size_t n4 = (size_t)N_NODES * HID / 4;
        k_bnrelu<<<(unsigned)((n4 + 255) / 256), 256>>>(tmp, Bh);
    }

    // ---- fc + ReLU (pure fp16) ----
    {
        PassDef pl[1] = {
            {Bh, W16 + OFF_WF, HID},
        };
        run_gemm(pl, 1, bf, tmp, N_NODES, F_MID, 1, 0);
    }

    // ---- head ----
    k_out<<<(N_NODES + 7) / 8, 256>>>(tmp, Wo, bo, out);
}

// round 14
// speedup vs baseline: 2.9490x; 1.0123x over previous
#include <cuda_runtime.h>
#include <cuda_fp16.h>
#include <cstdint>

#define N_NODES 50000
#define N_EDGES 400000
#define F_IN    256
#define HID     1024
#define F_MID   512
#define N_OUT   10
#define EPS_BN  1e-5f

// ---------------- scratch (device globals) ----------------
__device__ __half g_tmp16[(size_t)N_NODES * HID];  // pre-BN / fc output (fp16)
__device__ __half g_Ah[(size_t)N_NODES * HID];     // aggregate (fp16)
__device__ __half g_Bh[(size_t)N_NODES * HID];     // x / h (fp16)
#define OFF_W1L 0
#define OFF_W1R 262144
#define OFF_W2L 524288
#define OFF_W2R 1572864
#define OFF_WF  2621440
__device__ __half g_W16[3145728];                  // fp16 weights (transposed)

__device__ int   g_deg[N_NODES];
__device__ int   g_off[N_NODES];
__device__ int   g_cur[N_NODES];
__device__ int   g_csr[N_EDGES];
__device__ float g_sum[HID];
__device__ float g_sumsq[HID];
__device__ float g_a[HID];
__device__ float g_c[HID];
__device__ int   g_is64;

// ---------------- dtype detection ----------------
__global__ void k_detect(const unsigned int* e) {
    if (threadIdx.x == 0) {
        int is64 = 1;
        for (int i = 0; i < 64; i++)
            if (e[2 * i + 1] != 0u) { is64 = 0; break; }
        g_is64 = is64;
    }
}
__device__ __forceinline__ int load_edge(const void* edges, int idx) {
    if (g_is64) return (int)((const long long*)edges)[idx];
    return ((const int*)edges)[idx];
}

// ---------------- CSR build ----------------
__global__ void k_hist(const void* edges) {
    int i = blockIdx.x * blockDim.x + threadIdx.x;
    if (i < N_EDGES) atomicAdd(&g_deg[load_edge(edges, N_EDGES + i)], 1);
}
__global__ void k_scan() {
    __shared__ int sh[1024];
    __shared__ int carry;
    int t = threadIdx.x;
    if (t == 0) carry = 0;
    __syncthreads();
    for (int base = 0; base < N_NODES; base += 1024) {
        int v = (base + t < N_NODES) ? g_deg[base + t] : 0;
        sh[t] = v;
        __syncthreads();
        #pragma unroll
        for (int off = 1; off < 1024; off <<= 1) {
            int add = (t >= off) ? sh[t - off] : 0;
            __syncthreads();
            sh[t] += add;
            __syncthreads();
        }
        int excl = sh[t] - v;
        int c0 = carry;
        if (base + t < N_NODES) { g_off[base + t] = c0 + excl; g_cur[base + t] = c0 + excl; }
        __syncthreads();
        if (t == 0) carry = c0 + sh[1023];
        __syncthreads();
    }
}
__global__ void k_scatter(const void* edges) {
    int i = blockIdx.x * blockDim.x + threadIdx.x;
    if (i < N_EDGES) {
        int src = load_edge(edges, i);
        int dst = load_edge(edges, N_EDGES + i);
        g_csr[atomicAdd(&g_cur[dst], 1)] = src;
    }
}

// ---------------- layer-1 aggregation + own-row split (pure fp16) ---------
__global__ void k_agg1(const float* __restrict__ X,
                       __half* __restrict__ OH, __half* __restrict__ XHO) {
    int node = blockIdx.x;
    int t = threadIdx.x;                 // 128, 2 floats each
    float a0 = 0.f, a1 = 0.f;
    int start = g_off[node];
    int deg = g_deg[node];
    for (int i = 0; i < deg; i++) {
        const float2 v = *(const float2*)(X + (size_t)g_csr[start + i] * F_IN + t * 2);
        a0 += v.x; a1 += v.y;
    }
    float inv = (deg > 0) ? (1.0f / (float)deg) : 0.0f;
    a0 *= inv; a1 *= inv;
    size_t o = (size_t)node * F_IN + t * 2;
    *(__half2*)(OH + o) = __halves2half2(__float2half_rn(a0), __float2half_rn(a1));
    const float2 xv = *(const float2*)(X + o);
    *(__half2*)(XHO + o) = __halves2half2(__float2half_rn(xv.x), __float2half_rn(xv.y));
}

// ---------------- layer-2 aggregation: fp16 -> fp16 ----------------
__global__ void k_agg2(const __half* __restrict__ XH, __half* __restrict__ OH) {
    int node = blockIdx.x;
    int t = threadIdx.x;                 // 128, 8 elems each
    float acc[8];
    #pragma unroll
    for (int j = 0; j < 8; j++) acc[j] = 0.f;
    int start = g_off[node];
    int deg = g_deg[node];
    for (int i = 0; i < deg; i++) {
        size_t ro = (size_t)g_csr[start + i] * HID + t * 8;
        union { uint4 u; __half b[8]; } uh;
        uh.u = *(const uint4*)(XH + ro);
        #pragma unroll
        for (int j = 0; j < 8; j++)
            acc[j] += __half2float(uh.b[j]);
    }
    float inv = (deg > 0) ? (1.0f / (float)deg) : 0.0f;
    union { uint4 u; __half b[8]; } oh;
    #pragma unroll
    for (int j = 0; j < 8; j++)
        oh.b[j] = __float2half_rn(acc[j] * inv);
    *(uint4*)(OH + (size_t)node * HID + t * 8) = oh.u;
}

// ---------------- weight transpose: W[K,N] -> T[N,K] fp16 ----------------
__global__ void k_wt(const float* __restrict__ W, __half* __restrict__ T, int K, int N) {
    __shared__ float t[32][33];
    int kb = blockIdx.x * 32, nb = blockIdx.y * 32;
    int tx = threadIdx.x, ty = threadIdx.y;  // 32 x 8
    #pragma unroll
    for (int i = 0; i < 32; i += 8)
        t[ty + i][tx] = W[(size_t)(kb + ty + i) * N + nb + tx];
    __syncthreads();
    #pragma unroll
    for (int i = 0; i < 32; i += 8)
        T[(size_t)(nb + ty + i) * K + kb + tx] = __float2half_rn(t[tx][ty + i]);
}

// ---------------- fp16 mma.sync GEMM, fp16 output ----------------
// C16[M,N] = sum_p A_p[M,Kp] @ B_p[N,Kp]^T + bias (+ReLU) (+fused column stats)
// CTA tile 128x128, warp tile 32x64 (4x2 warps), BK=64,
// 3-stage cp.async, 2 CTAs/SM — best measured config.
struct GemmParams {
    const __half* A[4];
    const __half* B[4];
    int Kw[4];
    int chEnd[4];
    int totalChunks;
    const float* bias;
    __half* C16;
    int M;
    int Ncols;
    int relu;
    int stats;
};

#define STAGES 3
#define STAGE_BYTES 32768              // 16KB A + 16KB B
#define SMEM_REQ (1024 + STAGES * STAGE_BYTES)

__device__ __forceinline__ uint32_t swz(uint32_t o) { return o ^ ((o >> 3) & 0x70); }

__device__ __forceinline__ void cp16(uint32_t dst, const void* src, bool p) {
    int sz = p ? 16 : 0;
    asm volatile("cp.async.cg.shared.global [%0], [%1], 16, %2;\n"
                 :: "r"(dst), "l"(src), "r"(sz));
}

__global__ __launch_bounds__(256, 2) void k_gemm(const __grid_constant__ GemmParams P) {
    extern __shared__ char dsm[];
    uint32_t raw;
    asm("{ .reg .u64 t; cvta.to.shared.u64 t, %1; cvt.u32.u64 %0, t; }" : "=r"(raw) : "l"(dsm));
    uint32_t tiles = (raw + 1023) & ~1023u;
    int tid = threadIdx.x;
    int wid = tid >> 5;
    int lane = tid & 31;
    int mBase = blockIdx.x * 128;
    int nBase = blockIdx.y * 128;
    int mw = wid >> 1;     // 0..3
    int nw = wid & 1;      // 0..1

    auto load_chunk = [&](int c, int s) {
        int p = 0;
        while (c >= P.chEnd[p]) p++;
        int c0 = (p ? c - P.chEnd[p - 1] : c) * 64;
        const char* Ab = (const char*)P.A[p] + (size_t)c0 * 2;
        const char* Bb = (const char*)P.B[p] + (size_t)c0 * 2;
        size_t rowB = (size_t)P.Kw[p] * 2;
        uint32_t stA = tiles + s * STAGE_BYTES;
        uint32_t stB = stA + 16384;
        #pragma unroll
        for (int i = 0; i < 4; i++) {
            int o = tid + i * 256;
            int row = o >> 3, kb = (o & 7) * 16;
            bool ok = (mBase + row) < P.M;
            cp16(stA + swz(row * 128 + kb), Ab + (size_t)(mBase + row) * rowB + kb, ok);
        }
        #pragma unroll
        for (int i = 0; i < 4; i++) {
            int o = tid + i * 256;
            int row = o >> 3, kb = (o & 7) * 16;
            cp16(stB + swz(row * 128 + kb), Bb + (size_t)(nBase + row) * rowB + kb, true);
        }
        asm volatile("cp.async.commit_group;" ::: "memory");
    };

    const int T = P.totalChunks;

    float acc[2][8][4];
    #pragma unroll
    for (int mi = 0; mi < 2; mi++)
        #pragma unroll
        for (int n8 = 0; n8 < 8; n8++)
            #pragma unroll
            for (int q = 0; q < 4; q++) acc[mi][n8][q] = 0.0f;

    int npre = (T < 2) ? T : 2;
    for (int c = 0; c < npre; c++) load_chunk(c, c);

    for (int c = 0; c < T; c++) {
        int s = c % 3;
        if (c == T - 1) asm volatile("cp.async.wait_group 0;" ::: "memory");
        else            asm volatile("cp.async.wait_group 1;" ::: "memory");
        __syncthreads();

        uint32_t stA = tiles + s * STAGE_BYTES;
        uint32_t stB = stA + 16384;
        #pragma unroll
        for (int ks = 0; ks < 4; ks++) {
            uint32_t a[2][4];
            uint32_t arow = mw * 32 + ((lane >> 3) & 1) * 8 + (lane & 7);
            uint32_t akb  = ks * 32 + (lane >> 4) * 16;
            #pragma unroll
            for (int mi = 0; mi < 2; mi++) {
                uint32_t ad = stA + swz((arow + mi * 16) * 128 + akb);
                asm volatile("ldmatrix.sync.aligned.m8n8.x4.shared.b16 {%0,%1,%2,%3}, [%4];"
                             : "=r"(a[mi][0]), "=r"(a[mi][1]), "=r"(a[mi][2]), "=r"(a[mi][3])
                             : "r"(ad));
            }
            uint32_t b[4][4];
            uint32_t brow = nw * 64 + ((lane >> 4) & 1) * 8 + (lane & 7);
            uint32_t bkb  = ks * 32 + ((lane >> 3) & 1) * 16;
            #pragma unroll
            for (int ni = 0; ni < 4; ni++) {
                uint32_t bd = stB + swz((brow + ni * 16) * 128 + bkb);
                asm volatile("ldmatrix.sync.aligned.m8n8.x4.shared.b16 {%0,%1,%2,%3}, [%4];"
                             : "=r"(b[ni][0]), "=r"(b[ni][1]), "=r"(b[ni][2]), "=r"(b[ni][3])
                             : "r"(bd));
            }
            #pragma unroll
            for (int mi = 0; mi < 2; mi++)
                #pragma unroll
                for (int n8 = 0; n8 < 8; n8++) {
                    uint32_t b0 = b[n8 >> 1][(n8 & 1) * 2 + 0];
                    uint32_t b1 = b[n8 >> 1][(n8 & 1) * 2 + 1];
                    asm volatile(
                        "mma.sync.aligned.m16n8k16.row.col.f32.f16.f16.f32 "
                        "{%0,%1,%2,%3}, {%4,%5,%6,%7}, {%8,%9}, {%0,%1,%2,%3};"
                        : "+f"(acc[mi][n8][0]), "+f"(acc[mi][n8][1]),
                          "+f"(acc[mi][n8][2]), "+f"(acc[mi][n8][3])
                        : "r"(a[mi][0]), "r"(a[mi][1]), "r"(a[mi][2]), "r"(a[mi][3]),
                          "r"(b0), "r"(b1));
                }
        }
        if (c + 2 < T) load_chunk(c + 2, (c + 2) % 3);
    }

    // epilogue: bias (+ReLU), fp16 store + fused column stats (fp32)
    {
        int g = lane >> 2, t4 = lane & 3;
        #pragma unroll
        for (int n8 = 0; n8 < 8; n8++) {
            int col = nBase + nw * 64 + n8 * 8 + t4 * 2;
            float bx = P.bias[col], by = P.bias[col + 1];
            float s0 = 0.f, s1 = 0.f, q0 = 0.f, q1 = 0.f;
            #pragma unroll
            for (int mi = 0; mi < 2; mi++) {
                int r0 = mBase + mw * 32 + mi * 16 + g;
                float vx = acc[mi][n8][0] + bx;
                float vy = acc[mi][n8][1] + by;
                if (P.relu) { vx = fmaxf(vx, 0.f); vy = fmaxf(vy, 0.f); }
                if (r0 < P.M) {
                    *(__half2*)(P.C16 + (size_t)r0 * P.Ncols + col) =
                        __halves2half2(__float2half_rn(vx), __float2half_rn(vy));
                    s0 += vx; s1 += vy; q0 += vx * vx; q1 += vy * vy;
                }
                int r1 = r0 + 8;
                float wx = acc[mi][n8][2] + bx;
                float wy = acc[mi][n8][3] + by;
                if (P.relu) { wx = fmaxf(wx, 0.f); wy = fmaxf(wy, 0.f); }
                if (r1 < P.M) {
                    *(__half2*)(P.C16 + (size_t)r1 * P.Ncols + col) =
                        __halves2half2(__float2half_rn(wx), __float2half_rn(wy));
                    s0 += wx; s1 += wy; q0 += wx * wx; q1 += wy * wy;
                }
            }
            if (P.stats) {
                #pragma unroll
                for (int o = 4; o <= 16; o <<= 1) {
                    s0 += __shfl_xor_sync(0xffffffffu, s0, o);
                    s1 += __shfl_xor_sync(0xffffffffu, s1, o);
                    q0 += __shfl_xor_sync(0xffffffffu, q0, o);
                    q1 += __shfl_xor_sync(0xffffffffu, q1, o);
                }
                if (g == 0) {
                    atomicAdd(&g_sum[col], s0);
                    atomicAdd(&g_sum[col + 1], s1);
                    atomicAdd(&g_sumsq[col], q0);
                    atomicAdd(&g_sumsq[col + 1], q1);
                }
            }
        }
    }
}

// ---------------- BN params / apply ----------------
__global__ void k_bnparams(const float* __restrict__ g, const float* __restrict__ be) {
    int c = blockIdx.x * blockDim.x + threadIdx.x;
    if (c < HID) {
        float m = g_sum[c] * (1.0f / N_NODES);
        float var = g_sumsq[c] * (1.0f / N_NODES) - m * m;
        float a = g[c] * rsqrtf(var + EPS_BN);
        g_a[c] = a;
        g_c[c] = be[c] - m * a;
    }
}
// BN+ReLU: fp16 in -> fp16 out
__global__ void k_bnrelu(const __half* __restrict__ X16, __half* __restrict__ YH) {
    size_t i = (size_t)blockIdx.x * blockDim.x + threadIdx.x;  // group of 4 halves
    const size_t total = (size_t)N_NODES * HID / 4;
    if (i < total) {
        int c = (int)((i * 4) % HID);
        union { uint2 u; __half b[4]; } in;
        in.u = ((const uint2*)X16)[i];
        float v0 = fmaxf(0.f, __half2float(in.b[0]) * g_a[c + 0] + g_c[c + 0]);
        float v1 = fmaxf(0.f, __half2float(in.b[1]) * g_a[c + 1] + g_c[c + 1]);
        float v2 = fmaxf(0.f, __half2float(in.b[2]) * g_a[c + 2] + g_c[c + 2]);
        float v3 = fmaxf(0.f, __half2float(in.b[3]) * g_a[c + 3] + g_c[c + 3]);
        union { uint2 u; __half b[4]; } o;
        o.b[0] = __float2half_rn(v0);
        o.b[1] = __float2half_rn(v1);
        o.b[2] = __float2half_rn(v2);
        o.b[3] = __float2half_rn(v3);
        ((uint2*)YH)[i] = o.u;
    }
}

// ---------------- final head (fp16 input) ----------------
__global__ void k_out(const __half* __restrict__ H, const float* __restrict__ Wo,
                      const float* __restrict__ bo, float* __restrict__ Out) {
    __shared__ float sw[F_MID * N_OUT];
    for (int i = threadIdx.x; i < F_MID * N_OUT; i += blockDim.x) sw[i] = Wo[i];
    __syncthreads();
    int warp = threadIdx.x / 32, lane = threadIdx.x % 32;
    int row = blockIdx.x * (blockDim.x / 32) + warp;
    if (row >= N_NODES) return;
    float acc[N_OUT];
    #pragma unroll
    for (int o = 0; o < N_OUT; o++) acc[o] = 0.0f;
    const __half* h = H + (size_t)row * F_MID;
    for (int k = lane; k < F_MID; k += 32) {
        float hv = __half2float(h[k]);
        #pragma unroll
        for (int o = 0; o < N_OUT; o++) acc[o] += hv * sw[k * N_OUT + o];
    }
    #pragma unroll
    for (int o = 0; o < N_OUT; o++)
        #pragma unroll
        for (int off = 16; off; off >>= 1)
            acc[o] += __shfl_down_sync(0xffffffffu, acc[o], off);
    if (lane == 0)
        #pragma unroll
        for (int o = 0; o < N_OUT; o++)
            Out[(size_t)row * N_OUT + o] = acc[o] + bo[o];
}

// ---------------- host-side GEMM launcher ----------------
struct PassDef { const __half* A; const __half* B; int Kw; };
static void run_gemm(const PassDef* passes, int np, const float* bias, __half* C16,
                     int M, int N, int relu, int stats) {
    GemmParams P = {};
    int cum = 0;
    for (int i = 0; i < np; i++) {
        P.A[i] = passes[i].A;
        P.B[i] = passes[i].B;
        P.Kw[i] = passes[i].Kw;
        cum += passes[i].Kw / 64;
        P.chEnd[i] = cum;
    }
    P.totalChunks = cum;
    P.bias = bias; P.C16 = C16; P.M = M; P.Ncols = N; P.relu = relu; P.stats = stats;
    dim3 g((M + 127) / 128, N / 128);
    k_gemm<<<g, 256, SMEM_REQ>>>(P);
}

// ---------------- launch ----------------
extern "C" void kernel_launch(void* const* d_in, const int* in_sizes, int n_in,
                              void* d_out, int out_size) {
    const float* x   = (const float*)d_in[0];
    const void*  edges = d_in[1];
    const float* W1l = (const float*)d_in[2];
    const float* b1  = (const float*)d_in[3];
    const float* W1r = (const float*)d_in[4];
    const float* g1  = (const float*)d_in[5];
    const float* be1 = (const float*)d_in[6];
    const float* W2l = (const float*)d_in[7];
    const float* b2  = (const float*)d_in[8];
    const float* W2r = (const float*)d_in[9];
    const float* g2  = (const float*)d_in[10];
    const float* be2 = (const float*)d_in[11];
    const float* Wf  = (const float*)d_in[12];
    const float* bf  = (const float*)d_in[13];
    const float* Wo  = (const float*)d_in[14];
    const float* bo  = (const float*)d_in[15];
    float* out = (float*)d_out;

    cudaFuncSetAttribute(k_gemm, cudaFuncAttributeMaxDynamicSharedMemorySize, SMEM_REQ);

    void *p_deg, *p_sum, *p_sumsq, *p_tmp, *p_Ah, *p_Bh, *p_W;
    cudaGetSymbolAddress(&p_deg, g_deg);
    cudaGetSymbolAddress(&p_sum, g_sum);
    cudaGetSymbolAddress(&p_sumsq, g_sumsq);
    cudaGetSymbolAddress(&p_tmp, g_tmp16);
    cudaGetSymbolAddress(&p_Ah, g_Ah);
    cudaGetSymbolAddress(&p_Bh, g_Bh);
    cudaGetSymbolAddress(&p_W, g_W16);
    __half* tmp16 = (__half*)p_tmp;
    __half* Ah = (__half*)p_Ah;
    __half* Bh = (__half*)p_Bh;
    __half* W16 = (__half*)p_W;

    // CSR build
    cudaMemsetAsync(p_deg, 0, N_NODES * sizeof(int));
    k_detect<<<1, 32>>>((const unsigned int*)edges);
    k_hist<<<(N_EDGES + 255) / 256, 256>>>(edges);
    k_scan<<<1, 1024>>>();
    k_scatter<<<(N_EDGES + 255) / 256, 256>>>(edges);

    // weight transpose (fp16)
    dim3 wb(32, 8);
    k_wt<<<dim3(F_IN / 32, HID / 32), wb>>>(W1l, W16 + OFF_W1L, F_IN, HID);
    k_wt<<<dim3(F_IN / 32, HID / 32), wb>>>(W1r, W16 + OFF_W1R, F_IN, HID);
    k_wt<<<dim3(HID / 32, HID / 32), wb>>>(W2l, W16 + OFF_W2L, HID, HID);
    k_wt<<<dim3(HID / 32, HID / 32), wb>>>(W2r, W16 + OFF_W2R, HID, HID);
    k_wt<<<dim3(HID / 32, F_MID / 32), wb>>>(Wf, W16 + OFF_WF, HID, F_MID);

    // ---- layer 1 (pure fp16; agg1 also emits x in fp16) ----
    k_agg1<<<N_NODES, 128>>>(x, Ah, Bh);
    cudaMemsetAsync(p_sum, 0, HID * sizeof(float));
    cudaMemsetAsync(p_sumsq, 0, HID * sizeof(float));
    {
        PassDef pl[2] = {
            {Ah, W16 + OFF_W1L, F_IN},
            {Bh, W16 + OFF_W1R, F_IN},
        };
        run_gemm(pl, 2, b1, tmp16, N_NODES, HID, 0, 1);
    }
    k_bnparams<<<HID / 256, 256>>>(g1, be1);
    {
        size_t n4 = (size_t)N_NODES * HID / 4;
        k_bnrelu<<<(unsigned)((n4 + 255) / 256), 256>>>(tmp16, Bh);
    }

    // ---- layer 2 (pure fp16) ----
    k_agg2<<<N_NODES, 128>>>(Bh, Ah);
    cudaMemsetAsync(p_sum, 0, HID * sizeof(float));
    cudaMemsetAsync(p_sumsq, 0, HID * sizeof(float));
    {
        PassDef pl[2] = {
            {Ah, W16 + OFF_W2L, HID},
            {Bh, W16 + OFF_W2R, HID},
        };
        run_gemm(pl, 2, b2, tmp16, N_NODES, HID, 0, 1);
    }
    k_bnparams<<<HID / 256, 256>>>(g2, be2);
    {
        size_t n4 = (size_t)N_NODES * HID / 4;
        k_bnrelu<<<(unsigned)((n4 + 255) / 256), 256>>>(tmp16, Bh);
    }

    // ---- fc + ReLU (pure fp16) ----
    {
        PassDef pl[1] = {
            {Bh, W16 + OFF_WF, HID},
        };
        run_gemm(pl, 1, bf, tmp16, N_NODES, F_MID, 1, 0);
    }

    // ---- head ----
    k_out<<<(N_NODES + 7) / 8, 256>>>(tmp16, Wo, bo, out);
}

// round 15
// speedup vs baseline: 3.0886x; 1.0473x over previous
#include <cuda_runtime.h>
#include <cuda_fp16.h>
#include <cstdint>

#define N_NODES 50000
#define N_EDGES 400000
#define F_IN    256
#define HID     1024
#define F_MID   512
#define N_OUT   10
#define EPS_BN  1e-5f

// ---------------- scratch (device globals) ----------------
__device__ __half g_tmp16[(size_t)N_NODES * HID];  // pre-BN / fc output (fp16)
__device__ __half g_Ah[(size_t)N_NODES * HID];     // aggregate (fp16)
__device__ __half g_Bh[(size_t)N_NODES * HID];     // x / h (fp16)
#define OFF_W1L 0
#define OFF_W1R 262144
#define OFF_W2L 524288
#define OFF_W2R 1572864
#define OFF_WF  2621440
__device__ __half g_W16[3145728];                  // fp16 weights (transposed)

__device__ int   g_deg[N_NODES];
__device__ int   g_off[N_NODES];
__device__ int   g_cur[N_NODES];
__device__ int   g_csr[N_EDGES];
__device__ int   g_blk[64];
__device__ float g_sum[HID];
__device__ float g_sumsq[HID];
__device__ float g_a[HID];
__device__ float g_c[HID];
__device__ int   g_is64;

// ---------------- dtype detection ----------------
__global__ void k_detect(const unsigned int* e) {
    if (threadIdx.x == 0) {
        int is64 = 1;
        for (int i = 0; i < 64; i++)
            if (e[2 * i + 1] != 0u) { is64 = 0; break; }
        g_is64 = is64;
    }
}
__device__ __forceinline__ int load_edge(const void* edges, int idx) {
    if (g_is64) return (int)((const long long*)edges)[idx];
    return ((const int*)edges)[idx];
}

// ---------------- CSR build ----------------
__global__ void k_hist(const void* edges) {
    int i = blockIdx.x * blockDim.x + threadIdx.x;
    if (i < N_EDGES) atomicAdd(&g_deg[load_edge(edges, N_EDGES + i)], 1);
}

// multi-block exclusive scan (3 kernels, exact)
__global__ void k_scan1() {        // 49 blocks x 1024
    __shared__ int sh[1024];
    int t = threadIdx.x;
    int i = blockIdx.x * 1024 + t;
    int v = (i < N_NODES) ? g_deg[i] : 0;
    sh[t] = v;
    __syncthreads();
    #pragma unroll
    for (int off = 1; off < 1024; off <<= 1) {
        int add = (t >= off) ? sh[t - off] : 0;
        __syncthreads();
        sh[t] += add;
        __syncthreads();
    }
    if (i < N_NODES) g_off[i] = sh[t] - v;          // block-local exclusive
    if (t == 1023) g_blk[blockIdx.x] = sh[1023];    // block total
}
__global__ void k_scan2() {        // 1 block x 64
    __shared__ int sh[64];
    int t = threadIdx.x;
    int v = (t < 49) ? g_blk[t] : 0;
    sh[t] = v;
    __syncthreads();
    #pragma unroll
    for (int off = 1; off < 64; off <<= 1) {
        int add = (t >= off) ? sh[t - off] : 0;
        __syncthreads();
        sh[t] += add;
        __syncthreads();
    }
    if (t < 49) g_blk[t] = sh[t] - v;               // exclusive block offsets
}
__global__ void k_scan3() {        // add offsets, seed cursor
    int i = blockIdx.x * 256 + threadIdx.x;
    if (i < N_NODES) {
        int o = g_off[i] + g_blk[i >> 10];
        g_off[i] = o;
        g_cur[i] = o;
    }
}

__global__ void k_scatter(const void* edges) {
    int i = blockIdx.x * blockDim.x + threadIdx.x;
    if (i < N_EDGES) {
        int src = load_edge(edges, i);
        int dst = load_edge(edges, N_EDGES + i);
        g_csr[atomicAdd(&g_cur[dst], 1)] = src;
    }
}

// ---------------- layer-1 aggregation + own-row split (pure fp16) ---------
__global__ void k_agg1(const float* __restrict__ X,
                       __half* __restrict__ OH, __half* __restrict__ XHO) {
    int node = blockIdx.x;
    int t = threadIdx.x;                 // 128, 2 floats each
    float a0 = 0.f, a1 = 0.f;
    int start = g_off[node];
    int deg = g_deg[node];
    for (int i = 0; i < deg; i++) {
        const float2 v = *(const float2*)(X + (size_t)g_csr[start + i] * F_IN + t * 2);
        a0 += v.x; a1 += v.y;
    }
    float inv = (deg > 0) ? (1.0f / (float)deg) : 0.0f;
    a0 *= inv; a1 *= inv;
    size_t o = (size_t)node * F_IN + t * 2;
    *(__half2*)(OH + o) = __halves2half2(__float2half_rn(a0), __float2half_rn(a1));
    const float2 xv = *(const float2*)(X + o);
    *(__half2*)(XHO + o) = __halves2half2(__float2half_rn(xv.x), __float2half_rn(xv.y));
}

// ---------------- layer-2 aggregation: fp16 -> fp16 ----------------
__global__ void k_agg2(const __half* __restrict__ XH, __half* __restrict__ OH) {
    int node = blockIdx.x;
    int t = threadIdx.x;                 // 128, 8 elems each
    float acc[8];
    #pragma unroll
    for (int j = 0; j < 8; j++) acc[j] = 0.f;
    int start = g_off[node];
    int deg = g_deg[node];
    for (int i = 0; i < deg; i++) {
        size_t ro = (size_t)g_csr[start + i] * HID + t * 8;
        union { uint4 u; __half b[8]; } uh;
        uh.u = *(const uint4*)(XH + ro);
        #pragma unroll
        for (int j = 0; j < 8; j++)
            acc[j] += __half2float(uh.b[j]);
    }
    float inv = (deg > 0) ? (1.0f / (float)deg) : 0.0f;
    union { uint4 u; __half b[8]; } oh;
    #pragma unroll
    for (int j = 0; j < 8; j++)
        oh.b[j] = __float2half_rn(acc[j] * inv);
    *(uint4*)(OH + (size_t)node * HID + t * 8) = oh.u;
}

// ---------------- weight transpose: W[K,N] -> T[N,K] fp16 ----------------
__global__ void k_wt(const float* __restrict__ W, __half* __restrict__ T, int K, int N) {
    __shared__ float t[32][33];
    int kb = blockIdx.x * 32, nb = blockIdx.y * 32;
    int tx = threadIdx.x, ty = threadIdx.y;  // 32 x 8
    #pragma unroll
    for (int i = 0; i < 32; i += 8)
        t[ty + i][tx] = W[(size_t)(kb + ty + i) * N + nb + tx];
    __syncthreads();
    #pragma unroll
    for (int i = 0; i < 32; i += 8)
        T[(size_t)(nb + ty + i) * K + kb + tx] = __float2half_rn(t[tx][ty + i]);
}

// ---------------- fp16 mma.sync GEMM, fp16 output ----------------
// C16[M,N] = sum_p A_p[M,Kp] @ B_p[N,Kp]^T + bias (+ReLU) (+fused column stats)
// CTA tile 128x128, warp tile 32x64 (4x2 warps), BK=64,
// 3-stage cp.async, 2 CTAs/SM — best measured config.
struct GemmParams {
    const __half* A[4];
    const __half* B[4];
    int Kw[4];
    int chEnd[4];
    int totalChunks;
    const float* bias;
    __half* C16;
    int M;
    int Ncols;
    int relu;
    int stats;
};

#define STAGES 3
#define STAGE_BYTES 32768              // 16KB A + 16KB B
#define SMEM_REQ (1024 + STAGES * STAGE_BYTES)

__device__ __forceinline__ uint32_t swz(uint32_t o) { return o ^ ((o >> 3) & 0x70); }

__device__ __forceinline__ void cp16(uint32_t dst, const void* src, bool p) {
    int sz = p ? 16 : 0;
    asm volatile("cp.async.cg.shared.global [%0], [%1], 16, %2;\n"
                 :: "r"(dst), "l"(src), "r"(sz));
}

__global__ __launch_bounds__(256, 2) void k_gemm(const __grid_constant__ GemmParams P) {
    extern __shared__ char dsm[];
    uint32_t raw;
    asm("{ .reg .u64 t; cvta.to.shared.u64 t, %1; cvt.u32.u64 %0, t; }" : "=r"(raw) : "l"(dsm));
    uint32_t tiles = (raw + 1023) & ~1023u;
    int tid = threadIdx.x;
    int wid = tid >> 5;
    int lane = tid & 31;
    int mBase = blockIdx.x * 128;
    int nBase = blockIdx.y * 128;
    int mw = wid >> 1;     // 0..3
    int nw = wid & 1;      // 0..1

    auto load_chunk = [&](int c, int s) {
        int p = 0;
        while (c >= P.chEnd[p]) p++;
        int c0 = (p ? c - P.chEnd[p - 1] : c) * 64;
        const char* Ab = (const char*)P.A[p] + (size_t)c0 * 2;
        const char* Bb = (const char*)P.B[p] + (size_t)c0 * 2;
        size_t rowB = (size_t)P.Kw[p] * 2;
        uint32_t stA = tiles + s * STAGE_BYTES;
        uint32_t stB = stA + 16384;
        #pragma unroll
        for (int i = 0; i < 4; i++) {
            int o = tid + i * 256;
            int row = o >> 3, kb = (o & 7) * 16;
            bool ok = (mBase + row) < P.M;
            cp16(stA + swz(row * 128 + kb), Ab + (size_t)(mBase + row) * rowB + kb, ok);
        }
        #pragma unroll
        for (int i = 0; i < 4; i++) {
            int o = tid + i * 256;
            int row = o >> 3, kb = (o & 7) * 16;
            cp16(stB + swz(row * 128 + kb), Bb + (size_t)(nBase + row) * rowB + kb, true);
        }
        asm volatile("cp.async.commit_group;" ::: "memory");
    };

    const int T = P.totalChunks;

    float acc[2][8][4];
    #pragma unroll
    for (int mi = 0; mi < 2; mi++)
        #pragma unroll
        for (int n8 = 0; n8 < 8; n8++)
            #pragma unroll
            for (int q = 0; q < 4; q++) acc[mi][n8][q] = 0.0f;

    int npre = (T < 2) ? T : 2;
    for (int c = 0; c < npre; c++) load_chunk(c, c);

    for (int c = 0; c < T; c++) {
        int s = c % 3;
        if (c == T - 1) asm volatile("cp.async.wait_group 0;" ::: "memory");
        else            asm volatile("cp.async.wait_group 1;" ::: "memory");
        __syncthreads();

        uint32_t stA = tiles + s * STAGE_BYTES;
        uint32_t stB = stA + 16384;
        #pragma unroll
        for (int ks = 0; ks < 4; ks++) {
            uint32_t a[2][4];
            uint32_t arow = mw * 32 + ((lane >> 3) & 1) * 8 + (lane & 7);
            uint32_t akb  = ks * 32 + (lane >> 4) * 16;
            #pragma unroll
            for (int mi = 0; mi < 2; mi++) {
                uint32_t ad = stA + swz((arow + mi * 16) * 128 + akb);
                asm volatile("ldmatrix.sync.aligned.m8n8.x4.shared.b16 {%0,%1,%2,%3}, [%4];"
                             : "=r"(a[mi][0]), "=r"(a[mi][1]), "=r"(a[mi][2]), "=r"(a[mi][3])
                             : "r"(ad));
            }
            uint32_t b[4][4];
            uint32_t brow = nw * 64 + ((lane >> 4) & 1) * 8 + (lane & 7);
            uint32_t bkb  = ks * 32 + ((lane >> 3) & 1) * 16;
            #pragma unroll
            for (int ni = 0; ni < 4; ni++) {
                uint32_t bd = stB + swz((brow + ni * 16) * 128 + bkb);
                asm volatile("ldmatrix.sync.aligned.m8n8.x4.shared.b16 {%0,%1,%2,%3}, [%4];"
                             : "=r"(b[ni][0]), "=r"(b[ni][1]), "=r"(b[ni][2]), "=r"(b[ni][3])
                             : "r"(bd));
            }
            #pragma unroll
            for (int mi = 0; mi < 2; mi++)
                #pragma unroll
                for (int n8 = 0; n8 < 8; n8++) {
                    uint32_t b0 = b[n8 >> 1][(n8 & 1) * 2 + 0];
                    uint32_t b1 = b[n8 >> 1][(n8 & 1) * 2 + 1];
                    asm volatile(
                        "mma.sync.aligned.m16n8k16.row.col.f32.f16.f16.f32 "
                        "{%0,%1,%2,%3}, {%4,%5,%6,%7}, {%8,%9}, {%0,%1,%2,%3};"
                        : "+f"(acc[mi][n8][0]), "+f"(acc[mi][n8][1]),
                          "+f"(acc[mi][n8][2]), "+f"(acc[mi][n8][3])
                        : "r"(a[mi][0]), "r"(a[mi][1]), "r"(a[mi][2]), "r"(a[mi][3]),
                          "r"(b0), "r"(b1));
                }
        }
        if (c + 2 < T) load_chunk(c + 2, (c + 2) % 3);
    }

    // epilogue: bias (+ReLU), fp16 store + fused column stats (fp32)
    {
        int g = lane >> 2, t4 = lane & 3;
        #pragma unroll
        for (int n8 = 0; n8 < 8; n8++) {
            int col = nBase + nw * 64 + n8 * 8 + t4 * 2;
            float bx = P.bias[col], by = P.bias[col + 1];
            float s0 = 0.f, s1 = 0.f, q0 = 0.f, q1 = 0.f;
            #pragma unroll
            for (int mi = 0; mi < 2; mi++) {
                int r0 = mBase + mw * 32 + mi * 16 + g;
                float vx = acc[mi][n8][0] + bx;
                float vy = acc[mi][n8][1] + by;
                if (P.relu) { vx = fmaxf(vx, 0.f); vy = fmaxf(vy, 0.f); }
                if (r0 < P.M) {
                    *(__half2*)(P.C16 + (size_t)r0 * P.Ncols + col) =
                        __halves2half2(__float2half_rn(vx), __float2half_rn(vy));
                    s0 += vx; s1 += vy; q0 += vx * vx; q1 += vy * vy;
                }
                int r1 = r0 + 8;
                float wx = acc[mi][n8][2] + bx;
                float wy = acc[mi][n8][3] + by;
                if (P.relu) { wx = fmaxf(wx, 0.f); wy = fmaxf(wy, 0.f); }
                if (r1 < P.M) {
                    *(__half2*)(P.C16 + (size_t)r1 * P.Ncols + col) =
                        __halves2half2(__float2half_rn(wx), __float2half_rn(wy));
                    s0 += wx; s1 += wy; q0 += wx * wx; q1 += wy * wy;
                }
            }
            if (P.stats) {
                #pragma unroll
                for (int o = 4; o <= 16; o <<= 1) {
                    s0 += __shfl_xor_sync(0xffffffffu, s0, o);
                    s1 += __shfl_xor_sync(0xffffffffu, s1, o);
                    q0 += __shfl_xor_sync(0xffffffffu, q0, o);
                    q1 += __shfl_xor_sync(0xffffffffu, q1, o);
                }
                if (g == 0) {
                    atomicAdd(&g_sum[col], s0);
                    atomicAdd(&g_sum[col + 1], s1);
                    atomicAdd(&g_sumsq[col], q0);
                    atomicAdd(&g_sumsq[col + 1], q1);
                }
            }
        }
    }
}

// ---------------- BN params / apply ----------------
__global__ void k_bnparams(const float* __restrict__ g, const float* __restrict__ be) {
    int c = blockIdx.x * blockDim.x + threadIdx.x;
    if (c < HID) {
        float m = g_sum[c] * (1.0f / N_NODES);
        float var = g_sumsq[c] * (1.0f / N_NODES) - m * m;
        float a = g[c] * rsqrtf(var + EPS_BN);
        g_a[c] = a;
        g_c[c] = be[c] - m * a;
    }
}
// BN+ReLU: fp16 in -> fp16 out
__global__ void k_bnrelu(const __half* __restrict__ X16, __half* __restrict__ YH) {
    size_t i = (size_t)blockIdx.x * blockDim.x + threadIdx.x;  // group of 4 halves
    const size_t total = (size_t)N_NODES * HID / 4;
    if (i < total) {
        int c = (int)((i * 4) % HID);
        union { uint2 u; __half b[4]; } in;
        in.u = ((const uint2*)X16)[i];
        float v0 = fmaxf(0.f, __half2float(in.b[0]) * g_a[c + 0] + g_c[c + 0]);
        float v1 = fmaxf(0.f, __half2float(in.b[1]) * g_a[c + 1] + g_c[c + 1]);
        float v2 = fmaxf(0.f, __half2float(in.b[2]) * g_a[c + 2] + g_c[c + 2]);
        float v3 = fmaxf(0.f, __half2float(in.b[3]) * g_a[c + 3] + g_c[c + 3]);
        union { uint2 u; __half b[4]; } o;
        o.b[0] = __float2half_rn(v0);
        o.b[1] = __float2half_rn(v1);
        o.b[2] = __float2half_rn(v2);
        o.b[3] = __float2half_rn(v3);
        ((uint2*)YH)[i] = o.u;
    }
}

// ---------------- final head (fp16 input) ----------------
__global__ void k_out(const __half* __restrict__ H, const float* __restrict__ Wo,
                      const float* __restrict__ bo, float* __restrict__ Out) {
    __shared__ float sw[F_MID * N_OUT];
    for (int i = threadIdx.x; i < F_MID * N_OUT; i += blockDim.x) sw[i] = Wo[i];
    __syncthreads();
    int warp = threadIdx.x / 32, lane = threadIdx.x % 32;
    int row = blockIdx.x * (blockDim.x / 32) + warp;
    if (row >= N_NODES) return;
    float acc[N_OUT];
    #pragma unroll
    for (int o = 0; o < N_OUT; o++) acc[o] = 0.0f;
    const __half* h = H + (size_t)row * F_MID;
    for (int k = lane; k < F_MID; k += 32) {
        float hv = __half2float(h[k]);
        #pragma unroll
        for (int o = 0; o < N_OUT; o++) acc[o] += hv * sw[k * N_OUT + o];
    }
    #pragma unroll
    for (int o = 0; o < N_OUT; o++)
        #pragma unroll
        for (int off = 16; off; off >>= 1)
            acc[o] += __shfl_down_sync(0xffffffffu, acc[o], off);
    if (lane == 0)
        #pragma unroll
        for (int o = 0; o < N_OUT; o++)
            Out[(size_t)row * N_OUT + o] = acc[o] + bo[o];
}

// ---------------- host-side GEMM launcher ----------------
struct PassDef { const __half* A; const __half* B; int Kw; };
static void run_gemm(const PassDef* passes, int np, const float* bias, __half* C16,
                     int M, int N, int relu, int stats) {
    GemmParams P = {};
    int cum = 0;
    for (int i = 0; i < np; i++) {
        P.A[i] = passes[i].A;
        P.B[i] = passes[i].B;
        P.Kw[i] = passes[i].Kw;
        cum += passes[i].Kw / 64;
        P.chEnd[i] = cum;
    }
    P.totalChunks = cum;
    P.bias = bias; P.C16 = C16; P.M = M; P.Ncols = N; P.relu = relu; P.stats = stats;
    dim3 g((M + 127) / 128, N / 128);
    k_gemm<<<g, 256, SMEM_REQ>>>(P);
}

// ---------------- launch ----------------
extern "C" void kernel_launch(void* const* d_in, const int* in_sizes, int n_in,
                              void* d_out, int out_size) {
    const float* x   = (const float*)d_in[0];
    const void*  edges = d_in[1];
    const float* W1l = (const float*)d_in[2];
    const float* b1  = (const float*)d_in[3];
    const float* W1r = (const float*)d_in[4];
    const float* g1  = (const float*)d_in[5];
    const float* be1 = (const float*)d_in[6];
    const float* W2l = (const float*)d_in[7];
    const float* b2  = (const float*)d_in[8];
    const float* W2r = (const float*)d_in[9];
    const float* g2  = (const float*)d_in[10];
    const float* be2 = (const float*)d_in[11];
    const float* Wf  = (const float*)d_in[12];
    const float* bf  = (const float*)d_in[13];
    const float* Wo  = (const float*)d_in[14];
    const float* bo  = (const float*)d_in[15];
    float* out = (float*)d_out;

    cudaFuncSetAttribute(k_gemm, cudaFuncAttributeMaxDynamicSharedMemorySize, SMEM_REQ);

    void *p_deg, *p_sum, *p_sumsq, *p_tmp, *p_Ah, *p_Bh, *p_W;
    cudaGetSymbolAddress(&p_deg, g_deg);
    cudaGetSymbolAddress(&p_sum, g_sum);
    cudaGetSymbolAddress(&p_sumsq, g_sumsq);
    cudaGetSymbolAddress(&p_tmp, g_tmp16);
    cudaGetSymbolAddress(&p_Ah, g_Ah);
    cudaGetSymbolAddress(&p_Bh, g_Bh);
    cudaGetSymbolAddress(&p_W, g_W16);
    __half* tmp16 = (__half*)p_tmp;
    __half* Ah = (__half*)p_Ah;
    __half* Bh = (__half*)p_Bh;
    __half* W16 = (__half*)p_W;

    // CSR build (multi-block scan)
    cudaMemsetAsync(p_deg, 0, N_NODES * sizeof(int));
    k_detect<<<1, 32>>>((const unsigned int*)edges);
    k_hist<<<(N_EDGES + 255) / 256, 256>>>(edges);
    k_scan1<<<(N_NODES + 1023) / 1024, 1024>>>();
    k_scan2<<<1, 64>>>();
    k_scan3<<<(N_NODES + 255) / 256, 256>>>();
    k_scatter<<<(N_EDGES + 255) / 256, 256>>>(edges);

    // weight transpose (fp16)
    dim3 wb(32, 8);
    k_wt<<<dim3(F_IN / 32, HID / 32), wb>>>(W1l, W16 + OFF_W1L, F_IN, HID);
    k_wt<<<dim3(F_IN / 32, HID / 32), wb>>>(W1r, W16 + OFF_W1R, F_IN, HID);
    k_wt<<<dim3(HID / 32, HID / 32), wb>>>(W2l, W16 + OFF_W2L, HID, HID);
    k_wt<<<dim3(HID / 32, HID / 32), wb>>>(W2r, W16 + OFF_W2R, HID, HID);
    k_wt<<<dim3(HID / 32, F_MID / 32), wb>>>(Wf, W16 + OFF_WF, HID, F_MID);

    // ---- layer 1 (pure fp16; agg1 also emits x in fp16) ----
    k_agg1<<<N_NODES, 128>>>(x, Ah, Bh);
    cudaMemsetAsync(p_sum, 0, HID * sizeof(float));
    cudaMemsetAsync(p_sumsq, 0, HID * sizeof(float));
    {
        PassDef pl[2] = {
            {Ah, W16 + OFF_W1L, F_IN},
            {Bh, W16 + OFF_W1R, F_IN},
        };
        run_gemm(pl, 2, b1, tmp16, N_NODES, HID, 0, 1);
    }
    k_bnparams<<<HID / 256, 256>>>(g1, be1);
    {
        size_t n4 = (size_t)N_NODES * HID / 4;
        k_bnrelu<<<(unsigned)((n4 + 255) / 256), 256>>>(tmp16, Bh);
    }

    // ---- layer 2 (pure fp16) ----
    k_agg2<<<N_NODES, 128>>>(Bh, Ah);
    cudaMemsetAsync(p_sum, 0, HID * sizeof(float));
    cudaMemsetAsync(p_sumsq, 0, HID * sizeof(float));
    {
        PassDef pl[2] = {
            {Ah, W16 + OFF_W2L, HID},
            {Bh, W16 + OFF_W2R, HID},
        };
        run_gemm(pl, 2, b2, tmp16, N_NODES, HID, 0, 1);
    }
    k_bnparams<<<HID / 256, 256>>>(g2, be2);
    {
        size_t n4 = (size_t)N_NODES * HID / 4;
        k_bnrelu<<<(unsigned)((n4 + 255) / 256), 256>>>(tmp16, Bh);
    }

    // ---- fc + ReLU (pure fp16) ----
    {
        PassDef pl[1] = {
            {Bh, W16 + OFF_WF, HID},
        };
        run_gemm(pl, 1, bf, tmp16, N_NODES, F_MID, 1, 0);
    }

    // ---- head ----
    k_out<<<(N_NODES + 7) / 8, 256>>>(tmp16, Wo, bo, out);
}

// round 16
// speedup vs baseline: 3.2045x; 1.0375x over previous
#include <cuda_runtime.h>
#include <cuda_fp16.h>
#include <cstdint>

#define N_NODES 50000
#define N_EDGES 400000
#define F_IN    256
#define HID     1024
#define F_MID   512
#define N_OUT   10
#define EPS_BN  1e-5f

// ---------------- scratch (device globals) ----------------
__device__ __half g_tmp16[(size_t)N_NODES * HID];  // pre-BN / fc output (fp16)
__device__ __half g_Ah[(size_t)N_NODES * HID];     // aggregate (fp16)
__device__ __half g_Bh[(size_t)N_NODES * HID];     // x / h (fp16)
#define OFF_W1L 0
#define OFF_W1R 262144
#define OFF_W2L 524288
#define OFF_W2R 1572864
#define OFF_WF  2621440
__device__ __half g_W16[3145728];                  // fp16 weights (transposed)

__device__ int   g_deg[N_NODES];
__device__ int   g_off[N_NODES];
__device__ int   g_cur[N_NODES];
__device__ int   g_csr[N_EDGES];
__device__ int   g_blk[64];
__device__ float g_sum[HID];
__device__ float g_sumsq[HID];
__device__ float g_a[HID];
__device__ float g_c[HID];
__device__ int   g_is64;

// ---------------- dtype detection ----------------
__global__ void k_detect(const unsigned int* e) {
    if (threadIdx.x == 0) {
        int is64 = 1;
        for (int i = 0; i < 64; i++)
            if (e[2 * i + 1] != 0u) { is64 = 0; break; }
        g_is64 = is64;
    }
}
__device__ __forceinline__ int load_edge(const void* edges, int idx) {
    if (g_is64) return (int)((const long long*)edges)[idx];
    return ((const int*)edges)[idx];
}

// ---------------- CSR build ----------------
__global__ void k_hist(const void* edges) {
    int i = blockIdx.x * blockDim.x + threadIdx.x;
    if (i < N_EDGES) atomicAdd(&g_deg[load_edge(edges, N_EDGES + i)], 1);
}

// multi-block exclusive scan (3 kernels, exact)
__global__ void k_scan1() {        // 49 blocks x 1024
    __shared__ int sh[1024];
    int t = threadIdx.x;
    int i = blockIdx.x * 1024 + t;
    int v = (i < N_NODES) ? g_deg[i] : 0;
    sh[t] = v;
    __syncthreads();
    #pragma unroll
    for (int off = 1; off < 1024; off <<= 1) {
        int add = (t >= off) ? sh[t - off] : 0;
        __syncthreads();
        sh[t] += add;
        __syncthreads();
    }
    if (i < N_NODES) g_off[i] = sh[t] - v;          // block-local exclusive
    if (t == 1023) g_blk[blockIdx.x] = sh[1023];    // block total
}
__global__ void k_scan2() {        // 1 block x 64
    __shared__ int sh[64];
    int t = threadIdx.x;
    int v = (t < 49) ? g_blk[t] : 0;
    sh[t] = v;
    __syncthreads();
    #pragma unroll
    for (int off = 1; off < 64; off <<= 1) {
        int add = (t >= off) ? sh[t - off] : 0;
        __syncthreads();
        sh[t] += add;
        __syncthreads();
    }
    if (t < 49) g_blk[t] = sh[t] - v;               // exclusive block offsets
}
__global__ void k_scan3() {        // add offsets, seed cursor
    int i = blockIdx.x * 256 + threadIdx.x;
    if (i < N_NODES) {
        int o = g_off[i] + g_blk[i >> 10];
        g_off[i] = o;
        g_cur[i] = o;
    }
}

__global__ void k_scatter(const void* edges) {
    int i = blockIdx.x * blockDim.x + threadIdx.x;
    if (i < N_EDGES) {
        int src = load_edge(edges, i);
        int dst = load_edge(edges, N_EDGES + i);
        g_csr[atomicAdd(&g_cur[dst], 1)] = src;
    }
}

// ---------------- layer-1 aggregation + own-row split (pure fp16) ---------
__global__ void k_agg1(const float* __restrict__ X,
                       __half* __restrict__ OH, __half* __restrict__ XHO) {
    int node = blockIdx.x;
    int t = threadIdx.x;                 // 128, 2 floats each
    float a0 = 0.f, a1 = 0.f;
    int start = g_off[node];
    int deg = g_deg[node];
    for (int i = 0; i < deg; i++) {
        const float2 v = *(const float2*)(X + (size_t)g_csr[start + i] * F_IN + t * 2);
        a0 += v.x; a1 += v.y;
    }
    float inv = (deg > 0) ? (1.0f / (float)deg) : 0.0f;
    a0 *= inv; a1 *= inv;
    size_t o = (size_t)node * F_IN + t * 2;
    *(__half2*)(OH + o) = __halves2half2(__float2half_rn(a0), __float2half_rn(a1));
    const float2 xv = *(const float2*)(X + o);
    *(__half2*)(XHO + o) = __halves2half2(__float2half_rn(xv.x), __float2half_rn(xv.y));
}

// ---------------- layer-2 aggregation: fp16 -> fp16 ----------------
__global__ void k_agg2(const __half* __restrict__ XH, __half* __restrict__ OH) {
    int node = blockIdx.x;
    int t = threadIdx.x;                 // 128, 8 elems each
    float acc[8];
    #pragma unroll
    for (int j = 0; j < 8; j++) acc[j] = 0.f;
    int start = g_off[node];
    int deg = g_deg[node];
    for (int i = 0; i < deg; i++) {
        size_t ro = (size_t)g_csr[start + i] * HID + t * 8;
        union { uint4 u; __half b[8]; } uh;
        uh.u = *(const uint4*)(XH + ro);
        #pragma unroll
        for (int j = 0; j < 8; j++)
            acc[j] += __half2float(uh.b[j]);
    }
    float inv = (deg > 0) ? (1.0f / (float)deg) : 0.0f;
    union { uint4 u; __half b[8]; } oh;
    #pragma unroll
    for (int j = 0; j < 8; j++)
        oh.b[j] = __float2half_rn(acc[j] * inv);
    *(uint4*)(OH + (size_t)node * HID + t * 8) = oh.u;
}

// ---------------- weight transpose: W[K,N] -> T[N,K] fp16 ----------------
__global__ void k_wt(const float* __restrict__ W, __half* __restrict__ T, int K, int N) {
    __shared__ float t[32][33];
    int kb = blockIdx.x * 32, nb = blockIdx.y * 32;
    int tx = threadIdx.x, ty = threadIdx.y;  // 32 x 8
    #pragma unroll
    for (int i = 0; i < 32; i += 8)
        t[ty + i][tx] = W[(size_t)(kb + ty + i) * N + nb + tx];
    __syncthreads();
    #pragma unroll
    for (int i = 0; i < 32; i += 8)
        T[(size_t)(nb + ty + i) * K + kb + tx] = __float2half_rn(t[tx][ty + i]);
}

// ---------------- fp16 mma.sync GEMM, fp16 output ----------------
// C16[M,N] = sum_p A_p[M,Kp] @ B_p[N,Kp]^T + bias (+ReLU) (+fused column stats)
// CTA tile 128x128, warp tile 32x64 (4x2 warps), BK=64,
// 3-stage cp.async, 2 CTAs/SM. Grid: x = N-tile (fast) so a wave
// shares each A row-block via L2 (A is the dominant DRAM stream).
struct GemmParams {
    const __half* A[4];
    const __half* B[4];
    int Kw[4];
    int chEnd[4];
    int totalChunks;
    const float* bias;
    __half* C16;
    int M;
    int Ncols;
    int relu;
    int stats;
};

#define STAGES 3
#define STAGE_BYTES 32768              // 16KB A + 16KB B
#define SMEM_REQ (1024 + STAGES * STAGE_BYTES)

__device__ __forceinline__ uint32_t swz(uint32_t o) { return o ^ ((o >> 3) & 0x70); }

__device__ __forceinline__ void cp16(uint32_t dst, const void* src, bool p) {
    int sz = p ? 16 : 0;
    asm volatile("cp.async.cg.shared.global [%0], [%1], 16, %2;\n"
                 :: "r"(dst), "l"(src), "r"(sz));
}

__global__ __launch_bounds__(256, 2) void k_gemm(const __grid_constant__ GemmParams P) {
    extern __shared__ char dsm[];
    uint32_t raw;
    asm("{ .reg .u64 t; cvta.to.shared.u64 t, %1; cvt.u32.u64 %0, t; }" : "=r"(raw) : "l"(dsm));
    uint32_t tiles = (raw + 1023) & ~1023u;
    int tid = threadIdx.x;
    int wid = tid >> 5;
    int lane = tid & 31;
    int mBase = blockIdx.y * 128;      // M-tile on y (slow)
    int nBase = blockIdx.x * 128;      // N-tile on x (fast) -> A reuse in-wave
    int mw = wid >> 1;     // 0..3
    int nw = wid & 1;      // 0..1

    auto load_chunk = [&](int c, int s) {
        int p = 0;
        while (c >= P.chEnd[p]) p++;
        int c0 = (p ? c - P.chEnd[p - 1] : c) * 64;
        const char* Ab = (const char*)P.A[p] + (size_t)c0 * 2;
        const char* Bb = (const char*)P.B[p] + (size_t)c0 * 2;
        size_t rowB = (size_t)P.Kw[p] * 2;
        uint32_t stA = tiles + s * STAGE_BYTES;
        uint32_t stB = stA + 16384;
        #pragma unroll
        for (int i = 0; i < 4; i++) {
            int o = tid + i * 256;
            int row = o >> 3, kb = (o & 7) * 16;
            bool ok = (mBase + row) < P.M;
            cp16(stA + swz(row * 128 + kb), Ab + (size_t)(mBase + row) * rowB + kb, ok);
        }
        #pragma unroll
        for (int i = 0; i < 4; i++) {
            int o = tid + i * 256;
            int row = o >> 3, kb = (o & 7) * 16;
            cp16(stB + swz(row * 128 + kb), Bb + (size_t)(nBase + row) * rowB + kb, true);
        }
        asm volatile("cp.async.commit_group;" ::: "memory");
    };

    const int T = P.totalChunks;

    float acc[2][8][4];
    #pragma unroll
    for (int mi = 0; mi < 2; mi++)
        #pragma unroll
        for (int n8 = 0; n8 < 8; n8++)
            #pragma unroll
            for (int q = 0; q < 4; q++) acc[mi][n8][q] = 0.0f;

    int npre = (T < 2) ? T : 2;
    for (int c = 0; c < npre; c++) load_chunk(c, c);

    for (int c = 0; c < T; c++) {
        int s = c % 3;
        if (c == T - 1) asm volatile("cp.async.wait_group 0;" ::: "memory");
        else            asm volatile("cp.async.wait_group 1;" ::: "memory");
        __syncthreads();

        uint32_t stA = tiles + s * STAGE_BYTES;
        uint32_t stB = stA + 16384;
        #pragma unroll
        for (int ks = 0; ks < 4; ks++) {
            uint32_t a[2][4];
            uint32_t arow = mw * 32 + ((lane >> 3) & 1) * 8 + (lane & 7);
            uint32_t akb  = ks * 32 + (lane >> 4) * 16;
            #pragma unroll
            for (int mi = 0; mi < 2; mi++) {
                uint32_t ad = stA + swz((arow + mi * 16) * 128 + akb);
                asm volatile("ldmatrix.sync.aligned.m8n8.x4.shared.b16 {%0,%1,%2,%3}, [%4];"
                             : "=r"(a[mi][0]), "=r"(a[mi][1]), "=r"(a[mi][2]), "=r"(a[mi][3])
                             : "r"(ad));
            }
            uint32_t b[4][4];
            uint32_t brow = nw * 64 + ((lane >> 4) & 1) * 8 + (lane & 7);
            uint32_t bkb  = ks * 32 + ((lane >> 3) & 1) * 16;
            #pragma unroll
            for (int ni = 0; ni < 4; ni++) {
                uint32_t bd = stB + swz((brow + ni * 16) * 128 + bkb);
                asm volatile("ldmatrix.sync.aligned.m8n8.x4.shared.b16 {%0,%1,%2,%3}, [%4];"
                             : "=r"(b[ni][0]), "=r"(b[ni][1]), "=r"(b[ni][2]), "=r"(b[ni][3])
                             : "r"(bd));
            }
            #pragma unroll
            for (int mi = 0; mi < 2; mi++)
                #pragma unroll
                for (int n8 = 0; n8 < 8; n8++) {
                    uint32_t b0 = b[n8 >> 1][(n8 & 1) * 2 + 0];
                    uint32_t b1 = b[n8 >> 1][(n8 & 1) * 2 + 1];
                    asm volatile(
                        "mma.sync.aligned.m16n8k16.row.col.f32.f16.f16.f32 "
                        "{%0,%1,%2,%3}, {%4,%5,%6,%7}, {%8,%9}, {%0,%1,%2,%3};"
                        : "+f"(acc[mi][n8][0]), "+f"(acc[mi][n8][1]),
                          "+f"(acc[mi][n8][2]), "+f"(acc[mi][n8][3])
                        : "r"(a[mi][0]), "r"(a[mi][1]), "r"(a[mi][2]), "r"(a[mi][3]),
                          "r"(b0), "r"(b1));
                }
        }
        if (c + 2 < T) load_chunk(c + 2, (c + 2) % 3);
    }

    // epilogue: bias (+ReLU), fp16 store + fused column stats (fp32)
    {
        int g = lane >> 2, t4 = lane & 3;
        #pragma unroll
        for (int n8 = 0; n8 < 8; n8++) {
            int col = nBase + nw * 64 + n8 * 8 + t4 * 2;
            float bx = P.bias[col], by = P.bias[col + 1];
            float s0 = 0.f, s1 = 0.f, q0 = 0.f, q1 = 0.f;
            #pragma unroll
            for (int mi = 0; mi < 2; mi++) {
                int r0 = mBase + mw * 32 + mi * 16 + g;
                float vx = acc[mi][n8][0] + bx;
                float vy = acc[mi][n8][1] + by;
                if (P.relu) { vx = fmaxf(vx, 0.f); vy = fmaxf(vy, 0.f); }
                if (r0 < P.M) {
                    *(__half2*)(P.C16 + (size_t)r0 * P.Ncols + col) =
                        __halves2half2(__float2half_rn(vx), __float2half_rn(vy));
                    s0 += vx; s1 += vy; q0 += vx * vx; q1 += vy * vy;
                }
                int r1 = r0 + 8;
                float wx = acc[mi][n8][2] + bx;
                float wy = acc[mi][n8][3] + by;
                if (P.relu) { wx = fmaxf(wx, 0.f); wy = fmaxf(wy, 0.f); }
                if (r1 < P.M) {
                    *(__half2*)(P.C16 + (size_t)r1 * P.Ncols + col) =
                        __halves2half2(__float2half_rn(wx), __float2half_rn(wy));
                    s0 += wx; s1 += wy; q0 += wx * wx; q1 += wy * wy;
                }
            }
            if (P.stats) {
                #pragma unroll
                for (int o = 4; o <= 16; o <<= 1) {
                    s0 += __shfl_xor_sync(0xffffffffu, s0, o);
                    s1 += __shfl_xor_sync(0xffffffffu, s1, o);
                    q0 += __shfl_xor_sync(0xffffffffu, q0, o);
                    q1 += __shfl_xor_sync(0xffffffffu, q1, o);
                }
                if (g == 0) {
                    atomicAdd(&g_sum[col], s0);
                    atomicAdd(&g_sum[col + 1], s1);
                    atomicAdd(&g_sumsq[col], q0);
                    atomicAdd(&g_sumsq[col + 1], q1);
                }
            }
        }
    }
}

// ---------------- BN params / apply ----------------
__global__ void k_bnparams(const float* __restrict__ g, const float* __restrict__ be) {
    int c = blockIdx.x * blockDim.x + threadIdx.x;
    if (c < HID) {
        float m = g_sum[c] * (1.0f / N_NODES);
        float var = g_sumsq[c] * (1.0f / N_NODES) - m * m;
        float a = g[c] * rsqrtf(var + EPS_BN);
        g_a[c] = a;
        g_c[c] = be[c] - m * a;
    }
}
// BN+ReLU: fp16 in -> fp16 out
__global__ void k_bnrelu(const __half* __restrict__ X16, __half* __restrict__ YH) {
    size_t i = (size_t)blockIdx.x * blockDim.x + threadIdx.x;  // group of 4 halves
    const size_t total = (size_t)N_NODES * HID / 4;
    if (i < total) {
        int c = (int)((i * 4) % HID);
        union { uint2 u; __half b[4]; } in;
        in.u = ((const uint2*)X16)[i];
        float v0 = fmaxf(0.f, __half2float(in.b[0]) * g_a[c + 0] + g_c[c + 0]);
        float v1 = fmaxf(0.f, __half2float(in.b[1]) * g_a[c + 1] + g_c[c + 1]);
        float v2 = fmaxf(0.f, __half2float(in.b[2]) * g_a[c + 2] + g_c[c + 2]);
        float v3 = fmaxf(0.f, __half2float(in.b[3]) * g_a[c + 3] + g_c[c + 3]);
        union { uint2 u; __half b[4]; } o;
        o.b[0] = __float2half_rn(v0);
        o.b[1] = __float2half_rn(v1);
        o.b[2] = __float2half_rn(v2);
        o.b[3] = __float2half_rn(v3);
        ((uint2*)YH)[i] = o.u;
    }
}

// ---------------- final head (fp16 input) ----------------
__global__ void k_out(const __half* __restrict__ H, const float* __restrict__ Wo,
                      const float* __restrict__ bo, float* __restrict__ Out) {
    __shared__ float sw[F_MID * N_OUT];
    for (int i = threadIdx.x; i < F_MID * N_OUT; i += blockDim.x) sw[i] = Wo[i];
    __syncthreads();
    int warp = threadIdx.x / 32, lane = threadIdx.x % 32;
    int row = blockIdx.x * (blockDim.x / 32) + warp;
    if (row >= N_NODES) return;
    float acc[N_OUT];
    #pragma unroll
    for (int o = 0; o < N_OUT; o++) acc[o] = 0.0f;
    const __half* h = H + (size_t)row * F_MID;
    for (int k = lane; k < F_MID; k += 32) {
        float hv = __half2float(h[k]);
        #pragma unroll
        for (int o = 0; o < N_OUT; o++) acc[o] += hv * sw[k * N_OUT + o];
    }
    #pragma unroll
    for (int o = 0; o < N_OUT; o++)
        #pragma unroll
        for (int off = 16; off; off >>= 1)
            acc[o] += __shfl_down_sync(0xffffffffu, acc[o], off);
    if (lane == 0)
        #pragma unroll
        for (int o = 0; o < N_OUT; o++)
            Out[(size_t)row * N_OUT + o] = acc[o] + bo[o];
}

// ---------------- host-side GEMM launcher ----------------
struct PassDef { const __half* A; const __half* B; int Kw; };
static void run_gemm(const PassDef* passes, int np, const float* bias, __half* C16,
                     int M, int N, int relu, int stats) {
    GemmParams P = {};
    int cum = 0;
    for (int i = 0; i < np; i++) {
        P.A[i] = passes[i].A;
        P.B[i] = passes[i].B;
        P.Kw[i] = passes[i].Kw;
        cum += passes[i].Kw / 64;
        P.chEnd[i] = cum;
    }
    P.totalChunks = cum;
    P.bias = bias; P.C16 = C16; P.M = M; P.Ncols = N; P.relu = relu; P.stats = stats;
    dim3 g(N / 128, (M + 127) / 128);   // x = N-tile (fast) for in-wave A reuse
    k_gemm<<<g, 256, SMEM_REQ>>>(P);
}

// ---------------- launch ----------------
extern "C" void kernel_launch(void* const* d_in, const int* in_sizes, int n_in,
                              void* d_out, int out_size) {
    const float* x   = (const float*)d_in[0];
    const void*  edges = d_in[1];
    const float* W1l = (const float*)d_in[2];
    const float* b1  = (const float*)d_in[3];
    const float* W1r = (const float*)d_in[4];
    const float* g1  = (const float*)d_in[5];
    const float* be1 = (const float*)d_in[6];
    const float* W2l = (const float*)d_in[7];
    const float* b2  = (const float*)d_in[8];
    const float* W2r = (const float*)d_in[9];
    const float* g2  = (const float*)d_in[10];
    const float* be2 = (const float*)d_in[11];
    const float* Wf  = (const float*)d_in[12];
    const float* bf  = (const float*)d_in[13];
    const float* Wo  = (const float*)d_in[14];
    const float* bo  = (const float*)d_in[15];
    float* out = (float*)d_out;

    cudaFuncSetAttribute(k_gemm, cudaFuncAttributeMaxDynamicSharedMemorySize, SMEM_REQ);

    void *p_deg, *p_sum, *p_sumsq, *p_tmp, *p_Ah, *p_Bh, *p_W;
    cudaGetSymbolAddress(&p_deg, g_deg);
    cudaGetSymbolAddress(&p_sum, g_sum);
    cudaGetSymbolAddress(&p_sumsq, g_sumsq);
    cudaGetSymbolAddress(&p_tmp, g_tmp16);
    cudaGetSymbolAddress(&p_Ah, g_Ah);
    cudaGetSymbolAddress(&p_Bh, g_Bh);
    cudaGetSymbolAddress(&p_W, g_W16);
    __half* tmp16 = (__half*)p_tmp;
    __half* Ah = (__half*)p_Ah;
    __half* Bh = (__half*)p_Bh;
    __half* W16 = (__half*)p_W;

    // CSR build (multi-block scan)
    cudaMemsetAsync(p_deg, 0, N_NODES * sizeof(int));
    k_detect<<<1, 32>>>((const unsigned int*)edges);
    k_hist<<<(N_EDGES + 255) / 256, 256>>>(edges);
    k_scan1<<<(N_NODES + 1023) / 1024, 1024>>>();
    k_scan2<<<1, 64>>>();
    k_scan3<<<(N_NODES + 255) / 256, 256>>>();
    k_scatter<<<(N_EDGES + 255) / 256, 256>>>(edges);

    // weight transpose (fp16)
    dim3 wb(32, 8);
    k_wt<<<dim3(F_IN / 32, HID / 32), wb>>>(W1l, W16 + OFF_W1L, F_IN, HID);
    k_wt<<<dim3(F_IN / 32, HID / 32), wb>>>(W1r, W16 + OFF_W1R, F_IN, HID);
    k_wt<<<dim3(HID / 32, HID / 32), wb>>>(W2l, W16 + OFF_W2L, HID, HID);
    k_wt<<<dim3(HID / 32, HID / 32), wb>>>(W2r, W16 + OFF_W2R, HID, HID);
    k_wt<<<dim3(HID / 32, F_MID / 32), wb>>>(Wf, W16 + OFF_WF, HID, F_MID);

    // ---- layer 1 (pure fp16; agg1 also emits x in fp16) ----
    k_agg1<<<N_NODES, 128>>>(x, Ah, Bh);
    cudaMemsetAsync(p_sum, 0, HID * sizeof(float));
    cudaMemsetAsync(p_sumsq, 0, HID * sizeof(float));
    {
        PassDef pl[2] = {
            {Ah, W16 + OFF_W1L, F_IN},
            {Bh, W16 + OFF_W1R, F_IN},
        };
        run_gemm(pl, 2, b1, tmp16, N_NODES, HID, 0, 1);
    }
    k_bnparams<<<HID / 256, 256>>>(g1, be1);
    {
        size_t n4 = (size_t)N_NODES * HID / 4;
        k_bnrelu<<<(unsigned)((n4 + 255) / 256), 256>>>(tmp16, Bh);
    }

    // ---- layer 2 (pure fp16) ----
    k_agg2<<<N_NODES, 128>>>(Bh, Ah);
    cudaMemsetAsync(p_sum, 0, HID * sizeof(float));
    cudaMemsetAsync(p_sumsq, 0, HID * sizeof(float));
    {
        PassDef pl[2] = {
            {Ah, W16 + OFF_W2L, HID},
            {Bh, W16 + OFF_W2R, HID},
        };
        run_gemm(pl, 2, b2, tmp16, N_NODES, HID, 0, 1);
    }
    k_bnparams<<<HID / 256, 256>>>(g2, be2);
    {
        size_t n4 = (size_t)N_NODES * HID / 4;
        k_bnrelu<<<(unsigned)((n4 + 255) / 256), 256>>>(tmp16, Bh);
    }

    // ---- fc + ReLU (pure fp16) ----
    {
        PassDef pl[1] = {
            {Bh, W16 + OFF_WF, HID},
        };
        run_gemm(pl, 1, bf, tmp16, N_NODES, F_MID, 1, 0);
    }

    // ---- head ----
    k_out<<<(N_NODES + 7) / 8, 256>>>(tmp16, Wo, bo, out);
}